// round 10
// baseline (speedup 1.0000x reference)
#include <cuda_runtime.h>
#include <cuda_fp16.h>
#include <math.h>
#include <stdint.h>

#define N_B   8192
#define N_K   10
#define N_D   128
#define M_HOP2 (N_B * N_K)          // 81920

// ---------------- scratch (static __device__ globals; no allocs) ------------
__device__ float  g_QW   [(size_t)M_HOP2 * 768];     // src @ Wcombq^T + ckq
__device__ __half g_buf_h[(size_t)M_HOP2 * 896];     // [ctx(768) || src(128)] hi
__device__ __half g_buf_l[(size_t)M_HOP2 * 896];     // lo
__device__ __half g_h_h  [(size_t)M_HOP2 * N_D];
__device__ __half g_h_l  [(size_t)M_HOP2 * N_D];
__device__ float  g_NL1  [(size_t)M_HOP2 * N_D];
__device__ int    g_inv  [M_HOP2];
__device__ float  g_cq   [2 * 256];
// combined weights
__device__ __half g_wcq [2*768*128];                 // Wk_h^T @ Wq1_h
__device__ float  g_ckq [2*768];                     // Wk_h^T @ cq_h
__device__ float  g_tmpvo[2*256*768];                // Wo @ Wv_blockdiag (fp32 temp)
__device__ float  g_bvo [2*256];                     // Wo bv + bo
__device__ __half g_wf  [2*128*896];                 // [W1a@Wvo || W1b] fp16
__device__ float  g_cvec[2*128];                     // W1a @ bvo
__device__ __half g_w2  [2*128*128];
__device__ float  g_wqb [2*2*128];                   // Wq1_h^T bk_h
__device__ float  g_cqb [2*2];                       // bk_h . cq_h

// ---------------- helpers ---------------------------------------------------
__device__ __forceinline__ void split2h(float v, __half& h, __half& l) {
    h = __float2half_rn(v);
    l = __float2half_rn(v - __half2float(h));
}

// ================= prep 1: const_q | comb_vo | stage-1 gather ================
__global__ __launch_bounds__(256) void prep1_kernel(
    const float* __restrict__ Wq, const float* __restrict__ bq,
    const float* __restrict__ tb,
    const float* __restrict__ Wo, const float* __restrict__ Wv,
    const float* __restrict__ bo, const float* __restrict__ bv,
    const float* __restrict__ nf, const float* __restrict__ mem,
    const int* __restrict__ idx,
    float* __restrict__ cq, float* __restrict__ tmpvo, float* __restrict__ bvo,
    __half* __restrict__ dh, __half* __restrict__ dl)
{
    int blk = blockIdx.x, tid = threadIdx.x;
    if (blk < 2) {                     // const_q: cq[j]=bq[j]+sum cos(tb)*Wq[j,128+t]
        __shared__ float ct[128];
        int p = blk, j = tid;
        if (j < 128) ct[j] = cosf(tb[j]);
        __syncthreads();
        const float* W = Wq + (size_t)p * 65536;
        float s = bq[p * 256 + j];
        #pragma unroll 4
        for (int t = 0; t < 128; t++) s = fmaf(ct[t], W[(size_t)j * 256 + 128 + t], s);
        cq[p * 256 + j] = s;
        return;
    }
    blk -= 2;
    if (blk < 1536) {                  // comb_vo: tmpvo[p][i][j], bvo
        int p = blk / 768, rr = blk % 768;
        int i = rr / 3, jc = rr % 3;
        int j = jc * 256 + tid;
        int h = j / 384, jp = j % 384;
        float acc = 0.f;
        #pragma unroll 4
        for (int d = 0; d < 128; d++)
            acc = fmaf(Wo[((size_t)p*256 + i)*256 + h*128 + d],
                       Wv[((size_t)p*256 + h*128 + d)*384 + jp], acc);
        tmpvo[((size_t)p*256 + i)*768 + j] = acc;
        if (jc == 0 && tid == 0) {
            float c = bo[p*256 + i];
            for (int e = 0; e < 256; e++)
                c = fmaf(Wo[((size_t)p*256 + i)*256 + e], bv[p*256 + e], c);
            bvo[p*256 + i] = c;
        }
        return;
    }
    blk -= 1536;                       // stage-1 gather: 2 rows/block
    int r = blk * 2 + (tid >> 7);
    int t = tid & 127;
    size_t s = (size_t)idx[r] * N_D + t;
    float v = nf[s] + mem[s];
    size_t o = (size_t)r * 896 + 768 + t;
    split2h(v, dh[o], dl[o]);
}

// ================= prep 2: comb_q | comb_qb | comb_w1 | misc =================
__global__ __launch_bounds__(256) void prep2_kernel(
    const float* __restrict__ Wk, const float* __restrict__ Wq,
    const float* __restrict__ cq, const float* __restrict__ bk,
    const float* __restrict__ W1, const float* __restrict__ W2,
    const float* __restrict__ tmpvo, const float* __restrict__ bvo,
    __half* __restrict__ wcq, float* __restrict__ ckq,
    float* __restrict__ wqb, float* __restrict__ cqb,
    __half* __restrict__ wf, float* __restrict__ cvec, __half* __restrict__ w2)
{
    int blk = blockIdx.x, tid = threadIdx.x;
    if (blk < 768) {                   // comb_q: 2 jr rows per block
        __shared__ float wk[2][128];
        int p = blk / 384;
        int half_ = tid >> 7, s = tid & 127;
        int jr = (blk % 384) * 2 + half_;
        int h = jr / 384, j = jr % 384;
        wk[half_][s] = Wk[((size_t)p*256 + h*128 + s)*384 + j];
        __syncthreads();
        float acc = 0.f;
        #pragma unroll 4
        for (int d = 0; d < 128; d++)
            acc = fmaf(wk[half_][d], Wq[((size_t)p*256 + h*128 + d)*256 + s], acc);
        wcq[((size_t)p*768 + jr)*128 + s] = __float2half_rn(acc);
        if (s == 0) {
            float c = 0.f;
            for (int d = 0; d < 128; d++) c = fmaf(wk[half_][d], cq[p*256 + h*128 + d], c);
            ckq[p*768 + jr] = c;
        }
        return;
    }
    blk -= 768;
    if (blk < 2) {                     // comb_qb
        int id = blk * 256 + tid;      // 512 total
        int p = id / 256, h = (id % 256) / 128, s = id % 128;
        float acc = 0.f;
        #pragma unroll 4
        for (int d = 0; d < 128; d++)
            acc = fmaf(Wq[((size_t)p*256 + h*128 + d)*256 + s], bk[p*256 + h*128 + d], acc);
        wqb[(p*2 + h)*128 + s] = acc;
        if (s == 0) {
            float c = 0.f;
            for (int d = 0; d < 128; d++)
                c = fmaf(bk[p*256 + h*128 + d], cq[p*256 + h*128 + d], c);
            cqb[p*2 + h] = c;
        }
        return;
    }
    blk -= 2;
    if (blk < 768) {                   // comb_w1: wf[p][n][j<768], cvec
        __shared__ float w1r[256];
        int p = blk / 384, rr = blk % 384;
        int n = rr / 3, jc = rr % 3;
        w1r[tid] = W1[((size_t)p*128 + n)*384 + tid];
        __syncthreads();
        int j = jc * 256 + tid;
        float acc = 0.f;
        #pragma unroll 4
        for (int e = 0; e < 256; e++)
            acc = fmaf(w1r[e], tmpvo[((size_t)p*256 + e)*768 + j], acc);
        wf[((size_t)p*128 + n)*896 + j] = __float2half_rn(acc);
        if (jc == 0 && tid == 0) {
            float c = 0.f;
            for (int e = 0; e < 256; e++) c = fmaf(w1r[e], bvo[p*256 + e], c);
            cvec[p*128 + n] = c;
        }
        return;
    }
    blk -= 768;
    {                                  // misc: wf W1b cols + W2 convert
        int i = blk * 256 + tid;       // 65536 total
        if (i < 32768) {
            int p = i >> 14, r = i & 16383;
            int n = r >> 7, d = r & 127;
            wf[((size_t)p*128 + n)*896 + 768 + d] =
                __float2half_rn(W1[((size_t)p*128 + n)*384 + 256 + d]);
        } else {
            i -= 32768;
            w2[i] = __float2half_rn(W2[i]);
        }
    }
}

// gather emb0 into buf at col 768 (stages 2)
__global__ void gather_emb_kernel(const float* __restrict__ nf,
                                  const float* __restrict__ mem,
                                  const int* __restrict__ idx,
                                  __half* __restrict__ dh, __half* __restrict__ dl, int n)
{
    int r = blockIdx.x;
    if (r >= n) return;
    int t = threadIdx.x;
    size_t s = (size_t)idx[r] * N_D + t;
    float v = nf[s] + mem[s];
    size_t o = (size_t)r * 896 + 768 + t;
    split2h(v, dh[o], dl[o]);
}

// ---------------- fp16 2-pass tensor-core GEMM ------------------------------
#define GF_RELU 1
#define SMS  40
#define MATB (128 * SMS * 2)
#define STGB (3 * MATB)
#define NSTG 3
#define GSMEM (NSTG * STGB)

__device__ __forceinline__ void cpa16(uint32_t s, const void* g) {
    asm volatile("cp.async.cg.shared.global [%0], [%1], 16;\n" :: "r"(s), "l"(g));
}
__device__ __forceinline__ void ldm4(uint32_t* r, uint32_t a) {
    asm volatile("ldmatrix.sync.aligned.m8n8.x4.shared.b16 {%0,%1,%2,%3},[%4];\n"
                 : "=r"(r[0]), "=r"(r[1]), "=r"(r[2]), "=r"(r[3]) : "r"(a));
}
__device__ __forceinline__ void mmaf16(float* d, const uint32_t* a, uint32_t b0, uint32_t b1) {
    asm volatile("mma.sync.aligned.m16n8k16.row.col.f32.f16.f16.f32 "
                 "{%0,%1,%2,%3},{%4,%5,%6,%7},{%8,%9},{%0,%1,%2,%3};\n"
                 : "+f"(d[0]), "+f"(d[1]), "+f"(d[2]), "+f"(d[3])
                 : "r"(a[0]), "r"(a[1]), "r"(a[2]), "r"(a[3]), "r"(b0), "r"(b1));
}

__device__ __forceinline__ void issue_chunk(uint32_t sw, uint32_t bufofs,
    const __half* Ah, const __half* Al, size_t ga,
    const __half* Wh, size_t gw)
{
    uint32_t s0 = sw + bufofs;
    cpa16(s0,          Ah + ga); cpa16(s0 + 32,          Ah + ga + 16);
    cpa16(s0 + MATB,   Al + ga); cpa16(s0 + MATB + 32,   Al + ga + 16);
    cpa16(s0 + 2*MATB, Wh + gw); cpa16(s0 + 2*MATB + 32, Wh + gw + 16);
    asm volatile("cp.async.commit_group;\n");
}

__global__ __launch_bounds__(256, 2) void mma_gemm(
    const __half* __restrict__ Ah, const __half* __restrict__ Al, int lda,
    const __half* __restrict__ Wh, int ldw,
    int Kd,
    const float* __restrict__ bias, const float* __restrict__ bias2,
    float* __restrict__ Cf, int ldcf,
    __half* __restrict__ Oh, __half* __restrict__ Ol, int ldo,
    const int* __restrict__ zmask, int flags)
{
    extern __shared__ __align__(16) char smem_raw[];
    uint32_t sb = (uint32_t)__cvta_generic_to_shared(smem_raw);
    int tid = threadIdx.x;
    int m0 = blockIdx.y * 128, n0 = blockIdx.x * 128;
    int lane = tid & 31, wid = tid >> 5;
    int wm = wid & 1, wn = wid >> 1;

    float d[4][4][4];
    #pragma unroll
    for (int i = 0; i < 4; i++)
        #pragma unroll
        for (int j = 0; j < 4; j++)
            #pragma unroll
            for (int r = 0; r < 4; r++) d[i][j][r] = 0.f;

    int row = tid >> 1;
    int ce  = (tid & 1) << 3;
    size_t ga0 = (size_t)(m0 + row) * lda + ce;
    size_t gw0 = (size_t)(n0 + row) * ldw + ce;
    uint32_t sw = sb + (uint32_t)(row * SMS + ce) * 2;

    int nch = Kd >> 5;
    issue_chunk(sw, 0, Ah, Al, ga0, Wh, gw0);
    if (nch > 1) issue_chunk(sw, STGB, Ah, Al, ga0 + 32, Wh, gw0 + 32);

    for (int c = 0; c < nch; c++) {
        if (c + 2 < nch) {
            int k0 = (c + 2) << 5;
            issue_chunk(sw, (uint32_t)((c + 2) % NSTG) * STGB, Ah, Al, ga0 + k0, Wh, gw0 + k0);
        }
        int issuedJ = (c + 2 < nch) ? c + 2 : nch - 1;
        int allow = issuedJ - c;
        if (allow >= 2)      asm volatile("cp.async.wait_group 2;\n" ::: "memory");
        else if (allow == 1) asm volatile("cp.async.wait_group 1;\n" ::: "memory");
        else                 asm volatile("cp.async.wait_group 0;\n" ::: "memory");
        __syncthreads();

        uint32_t base = sb + (uint32_t)(c % NSTG) * STGB;
        #pragma unroll
        for (int h = 0; h < 2; h++) {
            uint32_t ah[4][4], al[4][4], bh[2][4];
            int colA = (h << 4) + ((lane >> 4) << 3);
            #pragma unroll
            for (int mi = 0; mi < 4; mi++) {
                int r_ = wm * 64 + mi * 16 + (lane & 15);
                uint32_t ad = base + (uint32_t)(r_ * SMS + colA) * 2;
                ldm4(ah[mi], ad);
                ldm4(al[mi], ad + MATB);
            }
            #pragma unroll
            for (int nj2 = 0; nj2 < 2; nj2++) {
                int r_ = wn * 32 + nj2 * 16 + (lane & 7) + (((lane >> 3) & 1) << 3);
                uint32_t bd = base + 2 * MATB + (uint32_t)(r_ * SMS + colA) * 2;
                ldm4(bh[nj2], bd);
            }
            #pragma unroll
            for (int mi = 0; mi < 4; mi++)
                #pragma unroll
                for (int nj = 0; nj < 4; nj++)
                    mmaf16(d[mi][nj], ah[mi], bh[nj >> 1][nj & 1], bh[nj >> 1][(nj & 1) + 2]);
            #pragma unroll
            for (int mi = 0; mi < 4; mi++)
                #pragma unroll
                for (int nj = 0; nj < 4; nj++)
                    mmaf16(d[mi][nj], al[mi], bh[nj >> 1][nj & 1], bh[nj >> 1][(nj & 1) + 2]);
        }
        __syncthreads();
    }

    int gr = lane >> 2, tg = lane & 3;
    #pragma unroll
    for (int mi = 0; mi < 4; mi++) {
        int mb = m0 + wm * 64 + mi * 16 + gr;
        #pragma unroll
        for (int half = 0; half < 2; half++) {
            int m = mb + half * 8;
            bool zm = (zmask != nullptr) && (zmask[m] != 0);
            #pragma unroll
            for (int nj = 0; nj < 4; nj++) {
                int n = n0 + wn * 32 + nj * 8 + tg * 2;
                float v0 = d[mi][nj][half * 2 + 0];
                float v1 = d[mi][nj][half * 2 + 1];
                if (bias) { v0 += bias[n]; v1 += bias[n + 1]; }
                if (bias2) {
                    if (!zm) { v0 += bias2[n]; v1 += bias2[n + 1]; }
                } else if (zm) { v0 = 0.f; v1 = 0.f; }
                if (flags & GF_RELU) { v0 = fmaxf(v0, 0.f); v1 = fmaxf(v1, 0.f); }
                if (Cf) *(float2*)&Cf[(size_t)m * ldcf + n] = make_float2(v0, v1);
                if (Oh) {
                    __half2 hh, ll;
                    split2h(v0, hh.x, ll.x);
                    split2h(v1, hh.y, ll.y);
                    *(__half2*)&Oh[(size_t)m * ldo + n] = hh;
                    *(__half2*)&Ol[(size_t)m * ldo + n] = ll;
                }
            }
        }
    }
}

// ---------------- fused keyv-build + attention v4 ---------------------------
// One warp per row m, 4 warps/block. float4 gathers (16B/lane covers 128 cols).
// Pass A: build scores; node+mem sum and cos cached in smem.
// Pass B: node/cos from smem, edge re-gathered (L2-hot). ctx zeroed on invalid.
__global__ __launch_bounds__(128) void fused_attn(
    const int* __restrict__ neigh,
    const int* __restrict__ eidx,
    const float* __restrict__ etime,
    const float* __restrict__ ts, int ts_div,
    const float* __restrict__ nf, const float* __restrict__ mem,
    const float* __restrict__ ef,
    const float* __restrict__ dense_neigh,
    const float* __restrict__ tw, const float* __restrict__ tb,
    const float* __restrict__ QW,
    const __half* __restrict__ bufh, const __half* __restrict__ bufl,
    const float* __restrict__ wqb, const float* __restrict__ cqb,
    __half* __restrict__ ctxh, __half* __restrict__ ctxl,
    int* __restrict__ inv, int M)
{
    __shared__ float s_tw[128], s_tb[128];
    __shared__ float cosb[4][N_K * 128];
    __shared__ float nodb[4][N_K * 128];
    int tid = threadIdx.x;
    s_tw[tid] = tw[tid];
    s_tb[tid] = tb[tid];
    __syncthreads();

    int wl = tid >> 5, lane = tid & 31;
    int m = blockIdx.x * 4 + wl;
    if (m >= M) return;
    const float SC = 0.08838834764831843f;   // 1/sqrt(128)
    float* cb = cosb[wl];
    float* nb = nodb[wl];
    int l4 = lane * 4;

    // qb_h = src . wqb_h + cqb_h
    float qb0, qb1;
    {
        size_t sbse = (size_t)m * 896 + 768 + l4;
        __half2 h0 = *(const __half2*)&bufh[sbse];
        __half2 h1 = *(const __half2*)&bufh[sbse + 2];
        __half2 l0 = *(const __half2*)&bufl[sbse];
        __half2 l1 = *(const __half2*)&bufl[sbse + 2];
        float2 fh0 = __half22float2(h0), fh1 = __half22float2(h1);
        float2 fl0 = __half22float2(l0), fl1 = __half22float2(l1);
        float sx = fh0.x + fl0.x, sy = fh0.y + fl0.y;
        float sz = fh1.x + fl1.x, sw_ = fh1.y + fl1.y;
        float4 w0 = *(const float4*)&wqb[l4];
        float4 w1 = *(const float4*)&wqb[128 + l4];
        qb0 = sx*w0.x + sy*w0.y + sz*w0.z + sw_*w0.w;
        qb1 = sx*w1.x + sy*w1.y + sz*w1.z + sw_*w1.w;
        #pragma unroll
        for (int o = 16; o; o >>= 1) {
            qb0 += __shfl_xor_sync(0xffffffffu, qb0, o);
            qb1 += __shfl_xor_sync(0xffffffffu, qb1, o);
        }
        qb0 += cqb[0]; qb1 += cqb[1];
    }

    float4 qw0[3], qw1[3];
    {
        const float* qwp = QW + (size_t)m * 768;
        #pragma unroll
        for (int s = 0; s < 3; s++) {
            qw0[s] = *(const float4*)&qwp[s * 128 + l4];
            qw1[s] = *(const float4*)&qwp[384 + s * 128 + l4];
        }
    }

    float tsv = ts[m / ts_div];
    bool msk[N_K]; bool allm = true;
    int nd[N_K], ed[N_K];
    #pragma unroll
    for (int k = 0; k < N_K; k++) {
        nd[k] = neigh[m * N_K + k];
        ed[k] = eidx [m * N_K + k];
        msk[k] = (nd[k] == 0);
        allm = allm && msk[k];
    }

    // ---- pass A: scores; node & cos cached in smem
    float s0[N_K], s1[N_K];
    #pragma unroll
    for (int k = 0; k < N_K; k++) {
        float4 vn, ve, vc;
        if (dense_neigh) {
            vn = *(const float4*)&dense_neigh[(size_t)(m * N_K + k) * N_D + l4];
        } else {
            float4 a = *(const float4*)&nf [(size_t)nd[k] * N_D + l4];
            float4 b = *(const float4*)&mem[(size_t)nd[k] * N_D + l4];
            vn = make_float4(a.x + b.x, a.y + b.y, a.z + b.z, a.w + b.w);
        }
        ve = *(const float4*)&ef[(size_t)ed[k] * N_D + l4];
        float dd = tsv - etime[m * N_K + k];
        vc.x = cosf(__fadd_rn(__fmul_rn(dd, s_tw[l4 + 0]), s_tb[l4 + 0]));
        vc.y = cosf(__fadd_rn(__fmul_rn(dd, s_tw[l4 + 1]), s_tb[l4 + 1]));
        vc.z = cosf(__fadd_rn(__fmul_rn(dd, s_tw[l4 + 2]), s_tb[l4 + 2]));
        vc.w = cosf(__fadd_rn(__fmul_rn(dd, s_tw[l4 + 3]), s_tb[l4 + 3]));
        *(float4*)&nb[k * 128 + l4] = vn;
        *(float4*)&cb[k * 128 + l4] = vc;
        float p0 = qw0[0].x*vn.x + qw0[0].y*vn.y + qw0[0].z*vn.z + qw0[0].w*vn.w
                 + qw0[1].x*ve.x + qw0[1].y*ve.y + qw0[1].z*ve.z + qw0[1].w*ve.w
                 + qw0[2].x*vc.x + qw0[2].y*vc.y + qw0[2].z*vc.z + qw0[2].w*vc.w;
        float p1 = qw1[0].x*vn.x + qw1[0].y*vn.y + qw1[0].z*vn.z + qw1[0].w*vn.w
                 + qw1[1].x*ve.x + qw1[1].y*ve.y + qw1[1].z*ve.z + qw1[1].w*ve.w
                 + qw1[2].x*vc.x + qw1[2].y*vc.y + qw1[2].z*vc.z + qw1[2].w*vc.w;
        #pragma unroll
        for (int o = 16; o; o >>= 1) {
            p0 += __shfl_xor_sync(0xffffffffu, p0, o);
            p1 += __shfl_xor_sync(0xffffffffu, p1, o);
        }
        bool mk = msk[k] && !(allm && k == 0);
        s0[k] = mk ? -1e9f : (p0 + qb0) * SC;
        s1[k] = mk ? -1e9f : (p1 + qb1) * SC;
    }

    float mx0 = s0[0], mx1 = s1[0];
    #pragma unroll
    for (int k = 1; k < N_K; k++) { mx0 = fmaxf(mx0, s0[k]); mx1 = fmaxf(mx1, s1[k]); }
    float sm0 = 0.f, sm1 = 0.f;
    #pragma unroll
    for (int k = 0; k < N_K; k++) {
        s0[k] = expf(s0[k] - mx0); sm0 += s0[k];
        s1[k] = expf(s1[k] - mx1); sm1 += s1[k];
    }
    float zf = allm ? 0.f : 1.f;       // fold invalid-row zeroing into ctx
    float r0 = zf / sm0, r1 = zf / sm1;

    // ---- pass B: ctx (node/cos from smem, edge re-gather L2-hot)
    float4 a0[3], a1[3];
    #pragma unroll
    for (int s = 0; s < 3; s++) {
        a0[s] = make_float4(0.f, 0.f, 0.f, 0.f);
        a1[s] = make_float4(0.f, 0.f, 0.f, 0.f);
    }
    #pragma unroll
    for (int k = 0; k < N_K; k++) {
        float w0 = s0[k] * r0, w1 = s1[k] * r1;
        float4 vn = *(const float4*)&nb[k * 128 + l4];
        float4 ve = *(const float4*)&ef[(size_t)ed[k] * N_D + l4];
        float4 vc = *(const float4*)&cb[k * 128 + l4];
        a0[0].x = fmaf(w0, vn.x, a0[0].x); a0[0].y = fmaf(w0, vn.y, a0[0].y);
        a0[0].z = fmaf(w0, vn.z, a0[0].z); a0[0].w = fmaf(w0, vn.w, a0[0].w);
        a0[1].x = fmaf(w0, ve.x, a0[1].x); a0[1].y = fmaf(w0, ve.y, a0[1].y);
        a0[1].z = fmaf(w0, ve.z, a0[1].z); a0[1].w = fmaf(w0, ve.w, a0[1].w);
        a0[2].x = fmaf(w0, vc.x, a0[2].x); a0[2].y = fmaf(w0, vc.y, a0[2].y);
        a0[2].z = fmaf(w0, vc.z, a0[2].z); a0[2].w = fmaf(w0, vc.w, a0[2].w);
        a1[0].x = fmaf(w1, vn.x, a1[0].x); a1[0].y = fmaf(w1, vn.y, a1[0].y);
        a1[0].z = fmaf(w1, vn.z, a1[0].z); a1[0].w = fmaf(w1, vn.w, a1[0].w);
        a1[1].x = fmaf(w1, ve.x, a1[1].x); a1[1].y = fmaf(w1, ve.y, a1[1].y);
        a1[1].z = fmaf(w1, ve.z, a1[1].z); a1[1].w = fmaf(w1, ve.w, a1[1].w);
        a1[2].x = fmaf(w1, vc.x, a1[2].x); a1[2].y = fmaf(w1, vc.y, a1[2].y);
        a1[2].z = fmaf(w1, vc.z, a1[2].z); a1[2].w = fmaf(w1, vc.w, a1[2].w);
    }

    size_t ob = (size_t)m * 896;
    #pragma unroll
    for (int s = 0; s < 3; s++) {
        __half2 hh0, ll0, hh1, ll1;
        split2h(a0[s].x, hh0.x, ll0.x); split2h(a0[s].y, hh0.y, ll0.y);
        split2h(a0[s].z, hh1.x, ll1.x); split2h(a0[s].w, hh1.y, ll1.y);
        size_t o0 = ob + s * 128 + l4;
        *(__half2*)&ctxh[o0]     = hh0;  *(__half2*)&ctxl[o0]     = ll0;
        *(__half2*)&ctxh[o0 + 2] = hh1;  *(__half2*)&ctxl[o0 + 2] = ll1;
        split2h(a1[s].x, hh0.x, ll0.x); split2h(a1[s].y, hh0.y, ll0.y);
        split2h(a1[s].z, hh1.x, ll1.x); split2h(a1[s].w, hh1.y, ll1.y);
        size_t o1 = ob + 384 + s * 128 + l4;
        *(__half2*)&ctxh[o1]     = hh0;  *(__half2*)&ctxl[o1]     = ll0;
        *(__half2*)&ctxh[o1 + 2] = hh1;  *(__half2*)&ctxl[o1 + 2] = ll1;
    }
    if (lane == 0) inv[m] = allm ? 1 : 0;
}

// ---------------- one temporal attention layer ------------------------------
struct Ptrs {
    __half *bufh, *bufl, *hh, *hl;
    float *QW; int* inv;
    __half *wcq, *wf, *w2;
    float *cq, *ckq, *cvec, *wqb, *cqb;
};

static void run_layer(const Ptrs& P, int p, int M,
                      const int* neigh, const float* dense_neigh,
                      const int* eidx, const float* etime,
                      const float* ts, int ts_div,
                      const float* nf, const float* mem, const float* ef,
                      const float* tw, const float* tb,
                      const float* b1, const float* b2,
                      float* outCf, __half* outOh, __half* outOl, int out_ldo)
{
    // QW = src @ Wcombq^T + ckq
    mma_gemm<<<dim3(6, M/128), 256, GSMEM>>>(
        P.bufh + 768, P.bufl + 768, 896,
        P.wcq + (size_t)p*768*128, 128, 128,
        P.ckq + p*768, nullptr, P.QW, 768, nullptr, nullptr, 0, nullptr, 0);
    // fused keyv-build + attention -> ctx into buf cols 0..767
    fused_attn<<<(M + 3) / 4, 128>>>(neigh, eidx, etime, ts, ts_div,
                                     nf, mem, ef, dense_neigh, tw, tb,
                                     P.QW, P.bufh, P.bufl,
                                     P.wqb + p*256, P.cqb + p*2,
                                     P.bufh, P.bufl, P.inv, M);
    // h = relu(buf @ wf^T + b1 + (valid ? cvec : 0))
    mma_gemm<<<dim3(1, M/128), 256, GSMEM>>>(
        P.bufh, P.bufl, 896,
        P.wf + (size_t)p*128*896, 896, 896,
        b1 + p*128, P.cvec + p*128, nullptr, 0, P.hh, P.hl, 128, P.inv, GF_RELU);
    // out = h @ W2^T + b2
    mma_gemm<<<dim3(1, M/128), 256, GSMEM>>>(
        P.hh, P.hl, 128,
        P.w2 + (size_t)p*16384, 128, 128,
        b2 + p*128, nullptr, outCf, 128, outOh, outOl, out_ldo, nullptr, 0);
}

// ---------------- entry -----------------------------------------------------
extern "C" void kernel_launch(void* const* d_in, const int* in_sizes, int n_in,
                              void* d_out, int out_size)
{
    const float* node_feat   = (const float*)d_in[0];
    const float* memory      = (const float*)d_in[1];
    const float* edge_feat   = (const float*)d_in[2];
    const float* time_w      = (const float*)d_in[3];
    const float* time_b      = (const float*)d_in[4];
    const float* Wq          = (const float*)d_in[5];
    const float* bq          = (const float*)d_in[6];
    const float* Wk          = (const float*)d_in[7];
    const float* bk          = (const float*)d_in[8];
    const float* Wv          = (const float*)d_in[9];
    const float* bv          = (const float*)d_in[10];
    const float* Wo          = (const float*)d_in[11];
    const float* bo          = (const float*)d_in[12];
    const float* W1          = (const float*)d_in[13];
    const float* b1          = (const float*)d_in[14];
    const float* W2          = (const float*)d_in[15];
    const float* b2          = (const float*)d_in[16];
    const float* timestamps  = (const float*)d_in[17];
    const int*   src_nodes   = (const int*)d_in[18];
    const int*   neighbors1  = (const int*)d_in[19];
    const int*   edge_idx1   = (const int*)d_in[20];
    const float* edge_times1 = (const float*)d_in[21];
    const int*   neighbors2  = (const int*)d_in[22];
    const int*   edge_idx2   = (const int*)d_in[23];
    const float* edge_times2 = (const float*)d_in[24];

    cudaFuncSetAttribute(mma_gemm, cudaFuncAttributeMaxDynamicSharedMemorySize, GSMEM);

    Ptrs P; float *NL1, *tmpvo, *bvo;
    cudaGetSymbolAddress((void**)&P.QW,   g_QW);
    cudaGetSymbolAddress((void**)&P.bufh, g_buf_h);
    cudaGetSymbolAddress((void**)&P.bufl, g_buf_l);
    cudaGetSymbolAddress((void**)&P.hh,   g_h_h);
    cudaGetSymbolAddress((void**)&P.hl,   g_h_l);
    cudaGetSymbolAddress((void**)&NL1,    g_NL1);
    cudaGetSymbolAddress((void**)&P.inv,  g_inv);
    cudaGetSymbolAddress((void**)&P.cq,   g_cq);
    cudaGetSymbolAddress((void**)&P.wcq,  g_wcq);
    cudaGetSymbolAddress((void**)&P.ckq,  g_ckq);
    cudaGetSymbolAddress((void**)&tmpvo,  g_tmpvo);
    cudaGetSymbolAddress((void**)&bvo,    g_bvo);
    cudaGetSymbolAddress((void**)&P.wf,   g_wf);
    cudaGetSymbolAddress((void**)&P.cvec, g_cvec);
    cudaGetSymbolAddress((void**)&P.w2,   g_w2);
    cudaGetSymbolAddress((void**)&P.wqb,  g_wqb);
    cudaGetSymbolAddress((void**)&P.cqb,  g_cqb);

    // launch 1: const_q | comb_vo | stage-1 gather
    prep1_kernel<<<2 + 1536 + M_HOP2/2, 256>>>(
        Wq, bq, time_b, Wo, Wv, bo, bv,
        node_feat, memory, neighbors1,
        P.cq, tmpvo, bvo, P.bufh, P.bufl);
    // launch 2: comb_q | comb_qb | comb_w1 | misc
    prep2_kernel<<<768 + 2 + 768 + 256, 256>>>(
        Wk, Wq, P.cq, bk, W1, W2, tmpvo, bvo,
        P.wcq, P.ckq, P.wqb, P.cqb, P.wf, P.cvec, P.w2);

    // stage 1 (launches 3..6: QW gemm, fused_attn, wf gemm, w2 gemm)
    run_layer(P, 0, M_HOP2, neighbors2, nullptr, edge_idx2, edge_times2,
              timestamps, N_K, node_feat, memory, edge_feat, time_w, time_b,
              b1, b2, NL1, nullptr, nullptr, 0);

    // stage 2: layer-1 embedding of src nodes (p0); SL1 -> buf col 768
    gather_emb_kernel<<<N_B, 128>>>(node_feat, memory, src_nodes, P.bufh, P.bufl, N_B);
    run_layer(P, 0, N_B, neighbors1, nullptr, edge_idx1, edge_times1,
              timestamps, 1, node_feat, memory, edge_feat, time_w, time_b,
              b1, b2, nullptr, P.bufh + 768, P.bufl + 768, 896);

    // stage 3: layer-2 aggregation (p1), neighbor feats = NL1
    run_layer(P, 1, N_B, neighbors1, NL1, edge_idx1, edge_times1,
              timestamps, 1, node_feat, memory, edge_feat, time_w, time_b,
              b1, b2, (float*)d_out, nullptr, nullptr, 0);
}

// round 11
// speedup vs baseline: 1.1294x; 1.1294x over previous
#include <cuda_runtime.h>
#include <cuda_fp16.h>
#include <math.h>
#include <stdint.h>

#define N_B   8192
#define N_K   10
#define N_D   128
#define M_HOP2 (N_B * N_K)          // 81920

// ---------------- scratch (static __device__ globals; no allocs) ------------
__device__ float  g_QW   [(size_t)M_HOP2 * 768];     // src @ Wcombq^T + ckq
__device__ __half g_buf_h[(size_t)M_HOP2 * 896];     // [ctx(768) || src(128)] hi
__device__ __half g_buf_l[(size_t)M_HOP2 * 896];     // lo
__device__ __half g_h_h  [(size_t)M_HOP2 * N_D];
__device__ __half g_h_l  [(size_t)M_HOP2 * N_D];
__device__ float  g_NL1  [(size_t)M_HOP2 * N_D];
__device__ int    g_inv  [M_HOP2];
__device__ float  g_cq   [2 * 256];
// combined weights
__device__ __half g_wcq [2*768*128];                 // Wk_h^T @ Wq1_h
__device__ float  g_ckq [2*768];                     // Wk_h^T @ cq_h
__device__ float  g_tmpvo[2*256*768];                // Wo @ Wv_blockdiag (fp32 temp)
__device__ float  g_bvo [2*256];                     // Wo bv + bo
__device__ __half g_wf  [2*128*896];                 // [W1a@Wvo || W1b] fp16
__device__ float  g_cvec[2*128];                     // W1a @ bvo
__device__ __half g_w2  [2*128*128];
__device__ float  g_wqb [2*2*128];                   // Wq1_h^T bk_h
__device__ float  g_cqb [2*2];                       // bk_h . cq_h

// ---------------- helpers ---------------------------------------------------
__device__ __forceinline__ void split2h(float v, __half& h, __half& l) {
    h = __float2half_rn(v);
    l = __float2half_rn(v - __half2float(h));
}

// ================= prep 1: const_q | comb_vo | stage-1 gather ================
__global__ __launch_bounds__(256) void prep1_kernel(
    const float* __restrict__ Wq, const float* __restrict__ bq,
    const float* __restrict__ tb,
    const float* __restrict__ Wo, const float* __restrict__ Wv,
    const float* __restrict__ bo, const float* __restrict__ bv,
    const float* __restrict__ nf, const float* __restrict__ mem,
    const int* __restrict__ idx,
    float* __restrict__ cq, float* __restrict__ tmpvo, float* __restrict__ bvo,
    __half* __restrict__ dh, __half* __restrict__ dl)
{
    int blk = blockIdx.x, tid = threadIdx.x;
    if (blk < 2) {                     // const_q
        __shared__ float ct[128];
        int p = blk, j = tid;
        if (j < 128) ct[j] = cosf(tb[j]);
        __syncthreads();
        const float* W = Wq + (size_t)p * 65536;
        float s = bq[p * 256 + j];
        #pragma unroll 4
        for (int t = 0; t < 128; t++) s = fmaf(ct[t], W[(size_t)j * 256 + 128 + t], s);
        cq[p * 256 + j] = s;
        return;
    }
    blk -= 2;
    if (blk < 1536) {                  // comb_vo
        int p = blk / 768, rr = blk % 768;
        int i = rr / 3, jc = rr % 3;
        int j = jc * 256 + tid;
        int h = j / 384, jp = j % 384;
        float acc = 0.f;
        #pragma unroll 4
        for (int d = 0; d < 128; d++)
            acc = fmaf(Wo[((size_t)p*256 + i)*256 + h*128 + d],
                       Wv[((size_t)p*256 + h*128 + d)*384 + jp], acc);
        tmpvo[((size_t)p*256 + i)*768 + j] = acc;
        if (jc == 0 && tid == 0) {
            float c = bo[p*256 + i];
            for (int e = 0; e < 256; e++)
                c = fmaf(Wo[((size_t)p*256 + i)*256 + e], bv[p*256 + e], c);
            bvo[p*256 + i] = c;
        }
        return;
    }
    blk -= 1536;                       // stage-1 gather: 2 rows/block
    int r = blk * 2 + (tid >> 7);
    int t = tid & 127;
    size_t s = (size_t)idx[r] * N_D + t;
    float v = nf[s] + mem[s];
    size_t o = (size_t)r * 896 + 768 + t;
    split2h(v, dh[o], dl[o]);
}

// ================= prep 2: comb_q | comb_qb | comb_w1 | misc =================
__global__ __launch_bounds__(256) void prep2_kernel(
    const float* __restrict__ Wk, const float* __restrict__ Wq,
    const float* __restrict__ cq, const float* __restrict__ bk,
    const float* __restrict__ W1, const float* __restrict__ W2,
    const float* __restrict__ tmpvo, const float* __restrict__ bvo,
    __half* __restrict__ wcq, float* __restrict__ ckq,
    float* __restrict__ wqb, float* __restrict__ cqb,
    __half* __restrict__ wf, float* __restrict__ cvec, __half* __restrict__ w2)
{
    int blk = blockIdx.x, tid = threadIdx.x;
    if (blk < 768) {                   // comb_q: 2 jr rows per block
        __shared__ float wk[2][128];
        int p = blk / 384;
        int half_ = tid >> 7, s = tid & 127;
        int jr = (blk % 384) * 2 + half_;
        int h = jr / 384, j = jr % 384;
        wk[half_][s] = Wk[((size_t)p*256 + h*128 + s)*384 + j];
        __syncthreads();
        float acc = 0.f;
        #pragma unroll 4
        for (int d = 0; d < 128; d++)
            acc = fmaf(wk[half_][d], Wq[((size_t)p*256 + h*128 + d)*256 + s], acc);
        wcq[((size_t)p*768 + jr)*128 + s] = __float2half_rn(acc);
        if (s == 0) {
            float c = 0.f;
            for (int d = 0; d < 128; d++) c = fmaf(wk[half_][d], cq[p*256 + h*128 + d], c);
            ckq[p*768 + jr] = c;
        }
        return;
    }
    blk -= 768;
    if (blk < 2) {                     // comb_qb
        int id = blk * 256 + tid;
        int p = id / 256, h = (id % 256) / 128, s = id % 128;
        float acc = 0.f;
        #pragma unroll 4
        for (int d = 0; d < 128; d++)
            acc = fmaf(Wq[((size_t)p*256 + h*128 + d)*256 + s], bk[p*256 + h*128 + d], acc);
        wqb[(p*2 + h)*128 + s] = acc;
        if (s == 0) {
            float c = 0.f;
            for (int d = 0; d < 128; d++)
                c = fmaf(bk[p*256 + h*128 + d], cq[p*256 + h*128 + d], c);
            cqb[p*2 + h] = c;
        }
        return;
    }
    blk -= 2;
    if (blk < 768) {                   // comb_w1
        __shared__ float w1r[256];
        int p = blk / 384, rr = blk % 384;
        int n = rr / 3, jc = rr % 3;
        w1r[tid] = W1[((size_t)p*128 + n)*384 + tid];
        __syncthreads();
        int j = jc * 256 + tid;
        float acc = 0.f;
        #pragma unroll 4
        for (int e = 0; e < 256; e++)
            acc = fmaf(w1r[e], tmpvo[((size_t)p*256 + e)*768 + j], acc);
        wf[((size_t)p*128 + n)*896 + j] = __float2half_rn(acc);
        if (jc == 0 && tid == 0) {
            float c = 0.f;
            for (int e = 0; e < 256; e++) c = fmaf(w1r[e], bvo[p*256 + e], c);
            cvec[p*128 + n] = c;
        }
        return;
    }
    blk -= 768;
    {                                  // misc
        int i = blk * 256 + tid;
        if (i < 32768) {
            int p = i >> 14, r = i & 16383;
            int n = r >> 7, d = r & 127;
            wf[((size_t)p*128 + n)*896 + 768 + d] =
                __float2half_rn(W1[((size_t)p*128 + n)*384 + 256 + d]);
        } else {
            i -= 32768;
            w2[i] = __float2half_rn(W2[i]);
        }
    }
}

// gather emb0 into buf at col 768 (stage 2)
__global__ void gather_emb_kernel(const float* __restrict__ nf,
                                  const float* __restrict__ mem,
                                  const int* __restrict__ idx,
                                  __half* __restrict__ dh, __half* __restrict__ dl, int n)
{
    int r = blockIdx.x;
    if (r >= n) return;
    int t = threadIdx.x;
    size_t s = (size_t)idx[r] * N_D + t;
    float v = nf[s] + mem[s];
    size_t o = (size_t)r * 896 + 768 + t;
    split2h(v, dh[o], dl[o]);
}

// ---------------- fp16 2-pass tensor-core GEMM ------------------------------
#define GF_RELU 1
#define SMS  40
#define MATB (128 * SMS * 2)
#define STGB (3 * MATB)
#define NSTG 3
#define GSMEM (NSTG * STGB)

__device__ __forceinline__ void cpa16(uint32_t s, const void* g) {
    asm volatile("cp.async.cg.shared.global [%0], [%1], 16;\n" :: "r"(s), "l"(g));
}
__device__ __forceinline__ void ldm4(uint32_t* r, uint32_t a) {
    asm volatile("ldmatrix.sync.aligned.m8n8.x4.shared.b16 {%0,%1,%2,%3},[%4];\n"
                 : "=r"(r[0]), "=r"(r[1]), "=r"(r[2]), "=r"(r[3]) : "r"(a));
}
__device__ __forceinline__ void mmaf16(float* d, const uint32_t* a, uint32_t b0, uint32_t b1) {
    asm volatile("mma.sync.aligned.m16n8k16.row.col.f32.f16.f16.f32 "
                 "{%0,%1,%2,%3},{%4,%5,%6,%7},{%8,%9},{%0,%1,%2,%3};\n"
                 : "+f"(d[0]), "+f"(d[1]), "+f"(d[2]), "+f"(d[3])
                 : "r"(a[0]), "r"(a[1]), "r"(a[2]), "r"(a[3]), "r"(b0), "r"(b1));
}

__device__ __forceinline__ void issue_chunk(uint32_t sw, uint32_t bufofs,
    const __half* Ah, const __half* Al, size_t ga,
    const __half* Wh, size_t gw)
{
    uint32_t s0 = sw + bufofs;
    cpa16(s0,          Ah + ga); cpa16(s0 + 32,          Ah + ga + 16);
    cpa16(s0 + MATB,   Al + ga); cpa16(s0 + MATB + 32,   Al + ga + 16);
    cpa16(s0 + 2*MATB, Wh + gw); cpa16(s0 + 2*MATB + 32, Wh + gw + 16);
    asm volatile("cp.async.commit_group;\n");
}

__global__ __launch_bounds__(256, 2) void mma_gemm(
    const __half* __restrict__ Ah, const __half* __restrict__ Al, int lda,
    const __half* __restrict__ Wh, int ldw,
    int Kd,
    const float* __restrict__ bias, const float* __restrict__ bias2,
    float* __restrict__ Cf, int ldcf,
    __half* __restrict__ Oh, __half* __restrict__ Ol, int ldo,
    const int* __restrict__ zmask, int flags)
{
    extern __shared__ __align__(16) char smem_raw[];
    uint32_t sb = (uint32_t)__cvta_generic_to_shared(smem_raw);
    int tid = threadIdx.x;
    int m0 = blockIdx.y * 128, n0 = blockIdx.x * 128;
    int lane = tid & 31, wid = tid >> 5;
    int wm = wid & 1, wn = wid >> 1;

    float d[4][4][4];
    #pragma unroll
    for (int i = 0; i < 4; i++)
        #pragma unroll
        for (int j = 0; j < 4; j++)
            #pragma unroll
            for (int r = 0; r < 4; r++) d[i][j][r] = 0.f;

    int row = tid >> 1;
    int ce  = (tid & 1) << 3;
    size_t ga0 = (size_t)(m0 + row) * lda + ce;
    size_t gw0 = (size_t)(n0 + row) * ldw + ce;
    uint32_t sw = sb + (uint32_t)(row * SMS + ce) * 2;

    int nch = Kd >> 5;
    issue_chunk(sw, 0, Ah, Al, ga0, Wh, gw0);
    if (nch > 1) issue_chunk(sw, STGB, Ah, Al, ga0 + 32, Wh, gw0 + 32);

    for (int c = 0; c < nch; c++) {
        if (c + 2 < nch) {
            int k0 = (c + 2) << 5;
            issue_chunk(sw, (uint32_t)((c + 2) % NSTG) * STGB, Ah, Al, ga0 + k0, Wh, gw0 + k0);
        }
        int issuedJ = (c + 2 < nch) ? c + 2 : nch - 1;
        int allow = issuedJ - c;
        if (allow >= 2)      asm volatile("cp.async.wait_group 2;\n" ::: "memory");
        else if (allow == 1) asm volatile("cp.async.wait_group 1;\n" ::: "memory");
        else                 asm volatile("cp.async.wait_group 0;\n" ::: "memory");
        __syncthreads();

        uint32_t base = sb + (uint32_t)(c % NSTG) * STGB;
        #pragma unroll
        for (int h = 0; h < 2; h++) {
            uint32_t ah[4][4], al[4][4], bh[2][4];
            int colA = (h << 4) + ((lane >> 4) << 3);
            #pragma unroll
            for (int mi = 0; mi < 4; mi++) {
                int r_ = wm * 64 + mi * 16 + (lane & 15);
                uint32_t ad = base + (uint32_t)(r_ * SMS + colA) * 2;
                ldm4(ah[mi], ad);
                ldm4(al[mi], ad + MATB);
            }
            #pragma unroll
            for (int nj2 = 0; nj2 < 2; nj2++) {
                int r_ = wn * 32 + nj2 * 16 + (lane & 7) + (((lane >> 3) & 1) << 3);
                uint32_t bd = base + 2 * MATB + (uint32_t)(r_ * SMS + colA) * 2;
                ldm4(bh[nj2], bd);
            }
            #pragma unroll
            for (int mi = 0; mi < 4; mi++)
                #pragma unroll
                for (int nj = 0; nj < 4; nj++)
                    mmaf16(d[mi][nj], ah[mi], bh[nj >> 1][nj & 1], bh[nj >> 1][(nj & 1) + 2]);
            #pragma unroll
            for (int mi = 0; mi < 4; mi++)
                #pragma unroll
                for (int nj = 0; nj < 4; nj++)
                    mmaf16(d[mi][nj], al[mi], bh[nj >> 1][nj & 1], bh[nj >> 1][(nj & 1) + 2]);
        }
        __syncthreads();
    }

    int gr = lane >> 2, tg = lane & 3;
    #pragma unroll
    for (int mi = 0; mi < 4; mi++) {
        int mb = m0 + wm * 64 + mi * 16 + gr;
        #pragma unroll
        for (int half = 0; half < 2; half++) {
            int m = mb + half * 8;
            bool zm = (zmask != nullptr) && (zmask[m] != 0);
            #pragma unroll
            for (int nj = 0; nj < 4; nj++) {
                int n = n0 + wn * 32 + nj * 8 + tg * 2;
                float v0 = d[mi][nj][half * 2 + 0];
                float v1 = d[mi][nj][half * 2 + 1];
                if (bias) { v0 += bias[n]; v1 += bias[n + 1]; }
                if (bias2) {
                    if (!zm) { v0 += bias2[n]; v1 += bias2[n + 1]; }
                } else if (zm) { v0 = 0.f; v1 = 0.f; }
                if (flags & GF_RELU) { v0 = fmaxf(v0, 0.f); v1 = fmaxf(v1, 0.f); }
                if (Cf) *(float2*)&Cf[(size_t)m * ldcf + n] = make_float2(v0, v1);
                if (Oh) {
                    __half2 hh, ll;
                    split2h(v0, hh.x, ll.x);
                    split2h(v1, hh.y, ll.y);
                    *(__half2*)&Oh[(size_t)m * ldo + n] = hh;
                    *(__half2*)&Ol[(size_t)m * ldo + n] = ll;
                }
            }
        }
    }
}

// ---------------- fused keyv-build + attention (R9 shape, reg-trimmed) ------
// One warp per row m, 4 warps/block, cos cached in smem (20KB). Pass B
// re-gathers node/edge rows (L2-hot) and reloads indices (saves ~30 regs).
__global__ __launch_bounds__(128) void fused_attn(
    const int* __restrict__ neigh,
    const int* __restrict__ eidx,
    const float* __restrict__ etime,
    const float* __restrict__ ts, int ts_div,
    const float* __restrict__ nf, const float* __restrict__ mem,
    const float* __restrict__ ef,
    const float* __restrict__ dense_neigh,
    const float* __restrict__ tw, const float* __restrict__ tb,
    const float* __restrict__ QW,
    const __half* __restrict__ bufh, const __half* __restrict__ bufl,
    const float* __restrict__ wqb, const float* __restrict__ cqb,
    __half* __restrict__ ctxh, __half* __restrict__ ctxl,
    int* __restrict__ inv, int M)
{
    __shared__ float s_tw[128], s_tb[128];
    __shared__ float cosb[4][N_K * 128];
    int tid = threadIdx.x;
    s_tw[tid] = tw[tid];
    s_tb[tid] = tb[tid];
    __syncthreads();

    int wl = tid >> 5, lane = tid & 31;
    int m = blockIdx.x * 4 + wl;
    if (m >= M) return;
    const float SC = 0.08838834764831843f;   // 1/sqrt(128)
    float* cb = cosb[wl];
    int jj = 2 * lane;

    // qb_h = src . wqb_h + cqb_h   (src = buf hi+lo cols 768..895)
    float qb0, qb1;
    {
        size_t sbse = (size_t)m * 896 + 768 + jj;
        float2 sh0 = __half22float2(*(const __half2*)&bufh[sbse]);
        float2 sl0 = __half22float2(*(const __half2*)&bufl[sbse]);
        float2 sh1 = __half22float2(*(const __half2*)&bufh[sbse + 64]);
        float2 sl1 = __half22float2(*(const __half2*)&bufl[sbse + 64]);
        float sx0 = sh0.x + sl0.x, sy0 = sh0.y + sl0.y;
        float sx1 = sh1.x + sl1.x, sy1 = sh1.y + sl1.y;
        float2 w00 = *(const float2*)&wqb[jj],       w01 = *(const float2*)&wqb[jj + 64];
        float2 w10 = *(const float2*)&wqb[128 + jj], w11 = *(const float2*)&wqb[128 + jj + 64];
        qb0 = sx0*w00.x + sy0*w00.y + sx1*w01.x + sy1*w01.y;
        qb1 = sx0*w10.x + sy0*w10.y + sx1*w11.x + sy1*w11.y;
        #pragma unroll
        for (int o = 16; o; o >>= 1) {
            qb0 += __shfl_xor_sync(0xffffffffu, qb0, o);
            qb1 += __shfl_xor_sync(0xffffffffu, qb1, o);
        }
        qb0 += cqb[0]; qb1 += cqb[1];
    }

    float2 qw0[6], qw1[6];
    {
        const float* qwp = QW + (size_t)m * 768;
        #pragma unroll
        for (int t = 0; t < 6; t++) {
            qw0[t] = *(const float2*)&qwp[jj + 64 * t];
            qw1[t] = *(const float2*)&qwp[384 + jj + 64 * t];
        }
    }

    float tsv = ts[m / ts_div];
    bool allm = true;
    #pragma unroll
    for (int k = 0; k < N_K; k++) allm = allm && (neigh[m * N_K + k] == 0);

    // ---- pass A: scores (cos written to smem); indices loaded per k
    float s0[N_K], s1[N_K];
    #pragma unroll
    for (int k = 0; k < N_K; k++) {
        int ndk = neigh[m * N_K + k];
        int edk = eidx [m * N_K + k];
        float2 v[6];
        if (dense_neigh) {
            const float* dr = dense_neigh + (size_t)(m * N_K + k) * N_D;
            v[0] = *(const float2*)&dr[jj];
            v[1] = *(const float2*)&dr[jj + 64];
        } else {
            const float* nr = nf  + (size_t)ndk * N_D;
            const float* mr = mem + (size_t)ndk * N_D;
            float2 a0 = *(const float2*)&nr[jj],      b0 = *(const float2*)&mr[jj];
            float2 a1 = *(const float2*)&nr[jj + 64], b1 = *(const float2*)&mr[jj + 64];
            v[0] = make_float2(a0.x + b0.x, a0.y + b0.y);
            v[1] = make_float2(a1.x + b1.x, a1.y + b1.y);
        }
        {
            const float* er = ef + (size_t)edk * N_D;
            v[2] = *(const float2*)&er[jj];
            v[3] = *(const float2*)&er[jj + 64];
        }
        float dd = tsv - etime[m * N_K + k];
        v[4].x = cosf(__fadd_rn(__fmul_rn(dd, s_tw[jj]),      s_tb[jj]));
        v[4].y = cosf(__fadd_rn(__fmul_rn(dd, s_tw[jj + 1]),  s_tb[jj + 1]));
        v[5].x = cosf(__fadd_rn(__fmul_rn(dd, s_tw[jj + 64]), s_tb[jj + 64]));
        v[5].y = cosf(__fadd_rn(__fmul_rn(dd, s_tw[jj + 65]), s_tb[jj + 65]));
        *(float2*)&cb[k * 128 + jj]      = v[4];
        *(float2*)&cb[k * 128 + jj + 64] = v[5];
        float p0 = 0.f, p1 = 0.f;
        #pragma unroll
        for (int t = 0; t < 6; t++) {
            p0 += qw0[t].x * v[t].x + qw0[t].y * v[t].y;
            p1 += qw1[t].x * v[t].x + qw1[t].y * v[t].y;
        }
        #pragma unroll
        for (int o = 16; o; o >>= 1) {
            p0 += __shfl_xor_sync(0xffffffffu, p0, o);
            p1 += __shfl_xor_sync(0xffffffffu, p1, o);
        }
        bool mk = (ndk == 0) && !(allm && k == 0);
        s0[k] = mk ? -1e9f : (p0 + qb0) * SC;
        s1[k] = mk ? -1e9f : (p1 + qb1) * SC;
    }

    float mx0 = s0[0], mx1 = s1[0];
    #pragma unroll
    for (int k = 1; k < N_K; k++) { mx0 = fmaxf(mx0, s0[k]); mx1 = fmaxf(mx1, s1[k]); }
    float sm0 = 0.f, sm1 = 0.f;
    #pragma unroll
    for (int k = 0; k < N_K; k++) {
        s0[k] = expf(s0[k] - mx0); sm0 += s0[k];
        s1[k] = expf(s1[k] - mx1); sm1 += s1[k];
    }
    float zf = allm ? 0.f : 1.f;       // fold invalid-row zeroing into ctx
    float r0 = zf / sm0, r1 = zf / sm1;

    // ---- pass B: ctx (gathers L2-hot; cos from smem; indices reloaded)
    float2 a0[6], a1[6];
    #pragma unroll
    for (int t = 0; t < 6; t++) { a0[t] = make_float2(0.f, 0.f); a1[t] = make_float2(0.f, 0.f); }
    #pragma unroll
    for (int k = 0; k < N_K; k++) {
        float w0 = s0[k] * r0, w1 = s1[k] * r1;
        int ndk = neigh[m * N_K + k];
        int edk = eidx [m * N_K + k];
        float2 v[6];
        if (dense_neigh) {
            const float* dr = dense_neigh + (size_t)(m * N_K + k) * N_D;
            v[0] = *(const float2*)&dr[jj];
            v[1] = *(const float2*)&dr[jj + 64];
        } else {
            const float* nr = nf  + (size_t)ndk * N_D;
            const float* mr = mem + (size_t)ndk * N_D;
            float2 c0 = *(const float2*)&nr[jj],      d0 = *(const float2*)&mr[jj];
            float2 c1 = *(const float2*)&nr[jj + 64], d1 = *(const float2*)&mr[jj + 64];
            v[0] = make_float2(c0.x + d0.x, c0.y + d0.y);
            v[1] = make_float2(c1.x + d1.x, c1.y + d1.y);
        }
        {
            const float* er = ef + (size_t)edk * N_D;
            v[2] = *(const float2*)&er[jj];
            v[3] = *(const float2*)&er[jj + 64];
        }
        v[4] = *(const float2*)&cb[k * 128 + jj];
        v[5] = *(const float2*)&cb[k * 128 + jj + 64];
        #pragma unroll
        for (int t = 0; t < 6; t++) {
            a0[t].x = fmaf(w0, v[t].x, a0[t].x); a0[t].y = fmaf(w0, v[t].y, a0[t].y);
            a1[t].x = fmaf(w1, v[t].x, a1[t].x); a1[t].y = fmaf(w1, v[t].y, a1[t].y);
        }
    }

    size_t ob = (size_t)m * 896 + jj;
    #pragma unroll
    for (int t = 0; t < 6; t++) {
        __half2 hh, ll;
        split2h(a0[t].x, hh.x, ll.x); split2h(a0[t].y, hh.y, ll.y);
        *(__half2*)&ctxh[ob + 64 * t] = hh;
        *(__half2*)&ctxl[ob + 64 * t] = ll;
        split2h(a1[t].x, hh.x, ll.x); split2h(a1[t].y, hh.y, ll.y);
        *(__half2*)&ctxh[ob + 384 + 64 * t] = hh;
        *(__half2*)&ctxl[ob + 384 + 64 * t] = ll;
    }
    if (lane == 0) inv[m] = allm ? 1 : 0;
}

// ---------------- one temporal attention layer ------------------------------
struct Ptrs {
    __half *bufh, *bufl, *hh, *hl;
    float *QW; int* inv;
    __half *wcq, *wf, *w2;
    float *cq, *ckq, *cvec, *wqb, *cqb;
};

static void run_layer(const Ptrs& P, int p, int M,
                      const int* neigh, const float* dense_neigh,
                      const int* eidx, const float* etime,
                      const float* ts, int ts_div,
                      const float* nf, const float* mem, const float* ef,
                      const float* tw, const float* tb,
                      const float* b1, const float* b2,
                      float* outCf, __half* outOh, __half* outOl, int out_ldo)
{
    // QW = src @ Wcombq^T + ckq
    mma_gemm<<<dim3(6, M/128), 256, GSMEM>>>(
        P.bufh + 768, P.bufl + 768, 896,
        P.wcq + (size_t)p*768*128, 128, 128,
        P.ckq + p*768, nullptr, P.QW, 768, nullptr, nullptr, 0, nullptr, 0);
    // fused keyv-build + attention -> ctx into buf cols 0..767
    fused_attn<<<(M + 3) / 4, 128>>>(neigh, eidx, etime, ts, ts_div,
                                     nf, mem, ef, dense_neigh, tw, tb,
                                     P.QW, P.bufh, P.bufl,
                                     P.wqb + p*256, P.cqb + p*2,
                                     P.bufh, P.bufl, P.inv, M);
    // h = relu(buf @ wf^T + b1 + (valid ? cvec : 0))
    mma_gemm<<<dim3(1, M/128), 256, GSMEM>>>(
        P.bufh, P.bufl, 896,
        P.wf + (size_t)p*128*896, 896, 896,
        b1 + p*128, P.cvec + p*128, nullptr, 0, P.hh, P.hl, 128, P.inv, GF_RELU);
    // out = h @ W2^T + b2
    mma_gemm<<<dim3(1, M/128), 256, GSMEM>>>(
        P.hh, P.hl, 128,
        P.w2 + (size_t)p*16384, 128, 128,
        b2 + p*128, nullptr, outCf, 128, outOh, outOl, out_ldo, nullptr, 0);
}

// ---------------- entry -----------------------------------------------------
extern "C" void kernel_launch(void* const* d_in, const int* in_sizes, int n_in,
                              void* d_out, int out_size)
{
    const float* node_feat   = (const float*)d_in[0];
    const float* memory      = (const float*)d_in[1];
    const float* edge_feat   = (const float*)d_in[2];
    const float* time_w      = (const float*)d_in[3];
    const float* time_b      = (const float*)d_in[4];
    const float* Wq          = (const float*)d_in[5];
    const float* bq          = (const float*)d_in[6];
    const float* Wk          = (const float*)d_in[7];
    const float* bk          = (const float*)d_in[8];
    const float* Wv          = (const float*)d_in[9];
    const float* bv          = (const float*)d_in[10];
    const float* Wo          = (const float*)d_in[11];
    const float* bo          = (const float*)d_in[12];
    const float* W1          = (const float*)d_in[13];
    const float* b1          = (const float*)d_in[14];
    const float* W2          = (const float*)d_in[15];
    const float* b2          = (const float*)d_in[16];
    const float* timestamps  = (const float*)d_in[17];
    const int*   src_nodes   = (const int*)d_in[18];
    const int*   neighbors1  = (const int*)d_in[19];
    const int*   edge_idx1   = (const int*)d_in[20];
    const float* edge_times1 = (const float*)d_in[21];
    const int*   neighbors2  = (const int*)d_in[22];
    const int*   edge_idx2   = (const int*)d_in[23];
    const float* edge_times2 = (const float*)d_in[24];

    cudaFuncSetAttribute(mma_gemm, cudaFuncAttributeMaxDynamicSharedMemorySize, GSMEM);

    Ptrs P; float *NL1, *tmpvo, *bvo;
    cudaGetSymbolAddress((void**)&P.QW,   g_QW);
    cudaGetSymbolAddress((void**)&P.bufh, g_buf_h);
    cudaGetSymbolAddress((void**)&P.bufl, g_buf_l);
    cudaGetSymbolAddress((void**)&P.hh,   g_h_h);
    cudaGetSymbolAddress((void**)&P.hl,   g_h_l);
    cudaGetSymbolAddress((void**)&NL1,    g_NL1);
    cudaGetSymbolAddress((void**)&P.inv,  g_inv);
    cudaGetSymbolAddress((void**)&P.cq,   g_cq);
    cudaGetSymbolAddress((void**)&P.wcq,  g_wcq);
    cudaGetSymbolAddress((void**)&P.ckq,  g_ckq);
    cudaGetSymbolAddress((void**)&tmpvo,  g_tmpvo);
    cudaGetSymbolAddress((void**)&bvo,    g_bvo);
    cudaGetSymbolAddress((void**)&P.wf,   g_wf);
    cudaGetSymbolAddress((void**)&P.cvec, g_cvec);
    cudaGetSymbolAddress((void**)&P.w2,   g_w2);
    cudaGetSymbolAddress((void**)&P.wqb,  g_wqb);
    cudaGetSymbolAddress((void**)&P.cqb,  g_cqb);

    // launch 1: const_q | comb_vo | stage-1 gather
    prep1_kernel<<<2 + 1536 + M_HOP2/2, 256>>>(
        Wq, bq, time_b, Wo, Wv, bo, bv,
        node_feat, memory, neighbors1,
        P.cq, tmpvo, bvo, P.bufh, P.bufl);
    // launch 2: comb_q | comb_qb | comb_w1 | misc
    prep2_kernel<<<768 + 2 + 768 + 256, 256>>>(
        Wk, Wq, P.cq, bk, W1, W2, tmpvo, bvo,
        P.wcq, P.ckq, P.wqb, P.cqb, P.wf, P.cvec, P.w2);

    // stage 1: layer-1 embedding of flattened first-hop neighbors (p0)
    run_layer(P, 0, M_HOP2, neighbors2, nullptr, edge_idx2, edge_times2,
              timestamps, N_K, node_feat, memory, edge_feat, time_w, time_b,
              b1, b2, NL1, nullptr, nullptr, 0);

    // stage 2: layer-1 embedding of src nodes (p0); SL1 -> buf col 768
    gather_emb_kernel<<<N_B, 128>>>(node_feat, memory, src_nodes, P.bufh, P.bufl, N_B);
    run_layer(P, 0, N_B, neighbors1, nullptr, edge_idx1, edge_times1,
              timestamps, 1, node_feat, memory, edge_feat, time_w, time_b,
              b1, b2, nullptr, P.bufh + 768, P.bufl + 768, 896);

    // stage 3: layer-2 aggregation (p1), neighbor feats = NL1
    run_layer(P, 1, N_B, neighbors1, NL1, edge_idx1, edge_times1,
              timestamps, 1, node_feat, memory, edge_feat, time_w, time_b,
              b1, b2, (float*)d_out, nullptr, nullptr, 0);
}

// round 12
// speedup vs baseline: 1.2797x; 1.1330x over previous
#include <cuda_runtime.h>
#include <cuda_fp16.h>
#include <math.h>
#include <stdint.h>

#define N_B   8192
#define N_K   10
#define N_D   128
#define M_HOP2 (N_B * N_K)          // 81920

// ---------------- scratch (static __device__ globals; no allocs) ------------
__device__ float  g_QW   [(size_t)M_HOP2 * 768];     // src @ Wcombq^T + ckq
__device__ __half g_buf_h[(size_t)M_HOP2 * 896];     // [ctx(768) || src(128)] hi
__device__ __half g_buf_l[(size_t)M_HOP2 * 896];     // lo
__device__ __half g_h_h  [(size_t)M_HOP2 * N_D];
__device__ __half g_h_l  [(size_t)M_HOP2 * N_D];
__device__ float  g_NL1  [(size_t)M_HOP2 * N_D];
__device__ int    g_inv  [M_HOP2];
__device__ float  g_cq   [2 * 256];
// combined weights
__device__ __half g_wcq [2*768*128];                 // Wk_h^T @ Wq1_h
__device__ float  g_ckq [2*768];                     // Wk_h^T @ cq_h
__device__ float  g_tmpvo[2*256*768];                // Wo @ Wv_blockdiag (fp32 temp)
__device__ float  g_bvo [2*256];                     // Wo bv + bo
__device__ __half g_wf  [2*128*896];                 // [W1a@Wvo || W1b] fp16
__device__ float  g_cvec[2*128];                     // W1a @ bvo
__device__ __half g_w2  [2*128*128];
__device__ float  g_wqb [2*2*128];                   // Wq1_h^T bk_h
__device__ float  g_cqb [2*2];                       // bk_h . cq_h

// ---------------- helpers ---------------------------------------------------
__device__ __forceinline__ void split2h(float v, __half& h, __half& l) {
    h = __float2half_rn(v);
    l = __float2half_rn(v - __half2float(h));
}

// ================= prep 1: const_q | comb_vo | stage-1 gather ================
__global__ __launch_bounds__(256) void prep1_kernel(
    const float* __restrict__ Wq, const float* __restrict__ bq,
    const float* __restrict__ tb,
    const float* __restrict__ Wo, const float* __restrict__ Wv,
    const float* __restrict__ bo, const float* __restrict__ bv,
    const float* __restrict__ nf, const float* __restrict__ mem,
    const int* __restrict__ idx,
    float* __restrict__ cq, float* __restrict__ tmpvo, float* __restrict__ bvo,
    __half* __restrict__ dh, __half* __restrict__ dl)
{
    int blk = blockIdx.x, tid = threadIdx.x;
    if (blk < 2) {                     // const_q
        __shared__ float ct[128];
        int p = blk, j = tid;
        if (j < 128) ct[j] = cosf(tb[j]);
        __syncthreads();
        const float* W = Wq + (size_t)p * 65536;
        float s = bq[p * 256 + j];
        #pragma unroll 4
        for (int t = 0; t < 128; t++) s = fmaf(ct[t], W[(size_t)j * 256 + 128 + t], s);
        cq[p * 256 + j] = s;
        return;
    }
    blk -= 2;
    if (blk < 1536) {                  // comb_vo
        int p = blk / 768, rr = blk % 768;
        int i = rr / 3, jc = rr % 3;
        int j = jc * 256 + tid;
        int h = j / 384, jp = j % 384;
        float acc = 0.f;
        #pragma unroll 4
        for (int d = 0; d < 128; d++)
            acc = fmaf(Wo[((size_t)p*256 + i)*256 + h*128 + d],
                       Wv[((size_t)p*256 + h*128 + d)*384 + jp], acc);
        tmpvo[((size_t)p*256 + i)*768 + j] = acc;
        if (jc == 0 && tid == 0) {
            float c = bo[p*256 + i];
            for (int e = 0; e < 256; e++)
                c = fmaf(Wo[((size_t)p*256 + i)*256 + e], bv[p*256 + e], c);
            bvo[p*256 + i] = c;
        }
        return;
    }
    blk -= 1536;                       // stage-1 gather: 2 rows/block
    int r = blk * 2 + (tid >> 7);
    int t = tid & 127;
    size_t s = (size_t)idx[r] * N_D + t;
    float v = nf[s] + mem[s];
    size_t o = (size_t)r * 896 + 768 + t;
    split2h(v, dh[o], dl[o]);
}

// ================= prep 2: comb_q | comb_qb | comb_w1 | misc =================
__global__ __launch_bounds__(256) void prep2_kernel(
    const float* __restrict__ Wk, const float* __restrict__ Wq,
    const float* __restrict__ cq, const float* __restrict__ bk,
    const float* __restrict__ W1, const float* __restrict__ W2,
    const float* __restrict__ tmpvo, const float* __restrict__ bvo,
    __half* __restrict__ wcq, float* __restrict__ ckq,
    float* __restrict__ wqb, float* __restrict__ cqb,
    __half* __restrict__ wf, float* __restrict__ cvec, __half* __restrict__ w2)
{
    int blk = blockIdx.x, tid = threadIdx.x;
    if (blk < 768) {                   // comb_q: 2 jr rows per block
        __shared__ float wk[2][128];
        int p = blk / 384;
        int half_ = tid >> 7, s = tid & 127;
        int jr = (blk % 384) * 2 + half_;
        int h = jr / 384, j = jr % 384;
        wk[half_][s] = Wk[((size_t)p*256 + h*128 + s)*384 + j];
        __syncthreads();
        float acc = 0.f;
        #pragma unroll 4
        for (int d = 0; d < 128; d++)
            acc = fmaf(wk[half_][d], Wq[((size_t)p*256 + h*128 + d)*256 + s], acc);
        wcq[((size_t)p*768 + jr)*128 + s] = __float2half_rn(acc);
        if (s == 0) {
            float c = 0.f;
            for (int d = 0; d < 128; d++) c = fmaf(wk[half_][d], cq[p*256 + h*128 + d], c);
            ckq[p*768 + jr] = c;
        }
        return;
    }
    blk -= 768;
    if (blk < 2) {                     // comb_qb
        int id = blk * 256 + tid;
        int p = id / 256, h = (id % 256) / 128, s = id % 128;
        float acc = 0.f;
        #pragma unroll 4
        for (int d = 0; d < 128; d++)
            acc = fmaf(Wq[((size_t)p*256 + h*128 + d)*256 + s], bk[p*256 + h*128 + d], acc);
        wqb[(p*2 + h)*128 + s] = acc;
        if (s == 0) {
            float c = 0.f;
            for (int d = 0; d < 128; d++)
                c = fmaf(bk[p*256 + h*128 + d], cq[p*256 + h*128 + d], c);
            cqb[p*2 + h] = c;
        }
        return;
    }
    blk -= 2;
    if (blk < 768) {                   // comb_w1
        __shared__ float w1r[256];
        int p = blk / 384, rr = blk % 384;
        int n = rr / 3, jc = rr % 3;
        w1r[tid] = W1[((size_t)p*128 + n)*384 + tid];
        __syncthreads();
        int j = jc * 256 + tid;
        float acc = 0.f;
        #pragma unroll 4
        for (int e = 0; e < 256; e++)
            acc = fmaf(w1r[e], tmpvo[((size_t)p*256 + e)*768 + j], acc);
        wf[((size_t)p*128 + n)*896 + j] = __float2half_rn(acc);
        if (jc == 0 && tid == 0) {
            float c = 0.f;
            for (int e = 0; e < 256; e++) c = fmaf(w1r[e], bvo[p*256 + e], c);
            cvec[p*128 + n] = c;
        }
        return;
    }
    blk -= 768;
    {                                  // misc
        int i = blk * 256 + tid;
        if (i < 32768) {
            int p = i >> 14, r = i & 16383;
            int n = r >> 7, d = r & 127;
            wf[((size_t)p*128 + n)*896 + 768 + d] =
                __float2half_rn(W1[((size_t)p*128 + n)*384 + 256 + d]);
        } else {
            i -= 32768;
            w2[i] = __float2half_rn(W2[i]);
        }
    }
}

// gather emb0 into buf at col 768 (stage 2)
__global__ void gather_emb_kernel(const float* __restrict__ nf,
                                  const float* __restrict__ mem,
                                  const int* __restrict__ idx,
                                  __half* __restrict__ dh, __half* __restrict__ dl, int n)
{
    int r = blockIdx.x;
    if (r >= n) return;
    int t = threadIdx.x;
    size_t s = (size_t)idx[r] * N_D + t;
    float v = nf[s] + mem[s];
    size_t o = (size_t)r * 896 + 768 + t;
    split2h(v, dh[o], dl[o]);
}

// ---------------- fp16 2-pass tensor-core GEMM ------------------------------
#define GF_RELU 1
#define SMS  40
#define MATB (128 * SMS * 2)
#define STGB (3 * MATB)
#define NSTG 3
#define GSMEM (NSTG * STGB)

__device__ __forceinline__ void cpa16(uint32_t s, const void* g) {
    asm volatile("cp.async.cg.shared.global [%0], [%1], 16;\n" :: "r"(s), "l"(g));
}
__device__ __forceinline__ void ldm4(uint32_t* r, uint32_t a) {
    asm volatile("ldmatrix.sync.aligned.m8n8.x4.shared.b16 {%0,%1,%2,%3},[%4];\n"
                 : "=r"(r[0]), "=r"(r[1]), "=r"(r[2]), "=r"(r[3]) : "r"(a));
}
__device__ __forceinline__ void mmaf16(float* d, const uint32_t* a, uint32_t b0, uint32_t b1) {
    asm volatile("mma.sync.aligned.m16n8k16.row.col.f32.f16.f16.f32 "
                 "{%0,%1,%2,%3},{%4,%5,%6,%7},{%8,%9},{%0,%1,%2,%3};\n"
                 : "+f"(d[0]), "+f"(d[1]), "+f"(d[2]), "+f"(d[3])
                 : "r"(a[0]), "r"(a[1]), "r"(a[2]), "r"(a[3]), "r"(b0), "r"(b1));
}

__device__ __forceinline__ void issue_chunk(uint32_t sw, uint32_t bufofs,
    const __half* Ah, const __half* Al, size_t ga,
    const __half* Wh, size_t gw)
{
    uint32_t s0 = sw + bufofs;
    cpa16(s0,          Ah + ga); cpa16(s0 + 32,          Ah + ga + 16);
    cpa16(s0 + MATB,   Al + ga); cpa16(s0 + MATB + 32,   Al + ga + 16);
    cpa16(s0 + 2*MATB, Wh + gw); cpa16(s0 + 2*MATB + 32, Wh + gw + 16);
    asm volatile("cp.async.commit_group;\n");
}

__global__ __launch_bounds__(256, 2) void mma_gemm(
    const __half* __restrict__ Ah, const __half* __restrict__ Al, int lda,
    const __half* __restrict__ Wh, int ldw,
    int Kd,
    const float* __restrict__ bias, const float* __restrict__ bias2,
    float* __restrict__ Cf, int ldcf,
    __half* __restrict__ Oh, __half* __restrict__ Ol, int ldo,
    const int* __restrict__ zmask, int flags)
{
    extern __shared__ __align__(16) char smem_raw[];
    uint32_t sb = (uint32_t)__cvta_generic_to_shared(smem_raw);
    int tid = threadIdx.x;
    int m0 = blockIdx.y * 128, n0 = blockIdx.x * 128;
    int lane = tid & 31, wid = tid >> 5;
    int wm = wid & 1, wn = wid >> 1;

    float d[4][4][4];
    #pragma unroll
    for (int i = 0; i < 4; i++)
        #pragma unroll
        for (int j = 0; j < 4; j++)
            #pragma unroll
            for (int r = 0; r < 4; r++) d[i][j][r] = 0.f;

    int row = tid >> 1;
    int ce  = (tid & 1) << 3;
    size_t ga0 = (size_t)(m0 + row) * lda + ce;
    size_t gw0 = (size_t)(n0 + row) * ldw + ce;
    uint32_t sw = sb + (uint32_t)(row * SMS + ce) * 2;

    int nch = Kd >> 5;
    issue_chunk(sw, 0, Ah, Al, ga0, Wh, gw0);
    if (nch > 1) issue_chunk(sw, STGB, Ah, Al, ga0 + 32, Wh, gw0 + 32);

    for (int c = 0; c < nch; c++) {
        if (c + 2 < nch) {
            int k0 = (c + 2) << 5;
            issue_chunk(sw, (uint32_t)((c + 2) % NSTG) * STGB, Ah, Al, ga0 + k0, Wh, gw0 + k0);
        }
        int issuedJ = (c + 2 < nch) ? c + 2 : nch - 1;
        int allow = issuedJ - c;
        if (allow >= 2)      asm volatile("cp.async.wait_group 2;\n" ::: "memory");
        else if (allow == 1) asm volatile("cp.async.wait_group 1;\n" ::: "memory");
        else                 asm volatile("cp.async.wait_group 0;\n" ::: "memory");
        __syncthreads();

        uint32_t base = sb + (uint32_t)(c % NSTG) * STGB;
        #pragma unroll
        for (int h = 0; h < 2; h++) {
            uint32_t ah[4][4], al[4][4], bh[2][4];
            int colA = (h << 4) + ((lane >> 4) << 3);
            #pragma unroll
            for (int mi = 0; mi < 4; mi++) {
                int r_ = wm * 64 + mi * 16 + (lane & 15);
                uint32_t ad = base + (uint32_t)(r_ * SMS + colA) * 2;
                ldm4(ah[mi], ad);
                ldm4(al[mi], ad + MATB);
            }
            #pragma unroll
            for (int nj2 = 0; nj2 < 2; nj2++) {
                int r_ = wn * 32 + nj2 * 16 + (lane & 7) + (((lane >> 3) & 1) << 3);
                uint32_t bd = base + 2 * MATB + (uint32_t)(r_ * SMS + colA) * 2;
                ldm4(bh[nj2], bd);
            }
            #pragma unroll
            for (int mi = 0; mi < 4; mi++)
                #pragma unroll
                for (int nj = 0; nj < 4; nj++)
                    mmaf16(d[mi][nj], ah[mi], bh[nj >> 1][nj & 1], bh[nj >> 1][(nj & 1) + 2]);
            #pragma unroll
            for (int mi = 0; mi < 4; mi++)
                #pragma unroll
                for (int nj = 0; nj < 4; nj++)
                    mmaf16(d[mi][nj], al[mi], bh[nj >> 1][nj & 1], bh[nj >> 1][(nj & 1) + 2]);
        }
        __syncthreads();
    }

    int gr = lane >> 2, tg = lane & 3;
    #pragma unroll
    for (int mi = 0; mi < 4; mi++) {
        int mb = m0 + wm * 64 + mi * 16 + gr;
        #pragma unroll
        for (int half = 0; half < 2; half++) {
            int m = mb + half * 8;
            bool zm = (zmask != nullptr) && (zmask[m] != 0);
            #pragma unroll
            for (int nj = 0; nj < 4; nj++) {
                int n = n0 + wn * 32 + nj * 8 + tg * 2;
                float v0 = d[mi][nj][half * 2 + 0];
                float v1 = d[mi][nj][half * 2 + 1];
                if (bias) { v0 += bias[n]; v1 += bias[n + 1]; }
                if (bias2) {
                    if (!zm) { v0 += bias2[n]; v1 += bias2[n + 1]; }
                } else if (zm) { v0 = 0.f; v1 = 0.f; }
                if (flags & GF_RELU) { v0 = fmaxf(v0, 0.f); v1 = fmaxf(v1, 0.f); }
                if (Cf) *(float2*)&Cf[(size_t)m * ldcf + n] = make_float2(v0, v1);
                if (Oh) {
                    __half2 hh, ll;
                    split2h(v0, hh.x, ll.x);
                    split2h(v1, hh.y, ll.y);
                    *(__half2*)&Oh[(size_t)m * ldo + n] = hh;
                    *(__half2*)&Ol[(size_t)m * ldo + n] = ll;
                }
            }
        }
    }
}

// ---------------- fused keyv-build + attention: ONLINE SOFTMAX, single pass --
// One warp per row m, 4 warps/block. Running (max, sum, ctx) with rescale.
// Masked scores (-1e9) annihilated by first finite-score rescale (== 2-pass).
__global__ __launch_bounds__(128, 4) void fused_attn(
    const int* __restrict__ neigh,
    const int* __restrict__ eidx,
    const float* __restrict__ etime,
    const float* __restrict__ ts, int ts_div,
    const float* __restrict__ nf, const float* __restrict__ mem,
    const float* __restrict__ ef,
    const float* __restrict__ dense_neigh,
    const float* __restrict__ tw, const float* __restrict__ tb,
    const float* __restrict__ QW,
    const __half* __restrict__ bufh, const __half* __restrict__ bufl,
    const float* __restrict__ wqb, const float* __restrict__ cqb,
    __half* __restrict__ ctxh, __half* __restrict__ ctxl,
    int* __restrict__ inv, int M)
{
    __shared__ float s_tw[128], s_tb[128];
    int tid = threadIdx.x;
    s_tw[tid] = tw[tid];
    s_tb[tid] = tb[tid];
    __syncthreads();

    int wl = tid >> 5, lane = tid & 31;
    int m = blockIdx.x * 4 + wl;
    if (m >= M) return;
    const float SC = 0.08838834764831843f;   // 1/sqrt(128)
    int jj = 2 * lane;

    // qb_h = src . wqb_h + cqb_h   (src = buf hi+lo cols 768..895)
    float qb0, qb1;
    {
        size_t sbse = (size_t)m * 896 + 768 + jj;
        float2 sh0 = __half22float2(*(const __half2*)&bufh[sbse]);
        float2 sl0 = __half22float2(*(const __half2*)&bufl[sbse]);
        float2 sh1 = __half22float2(*(const __half2*)&bufh[sbse + 64]);
        float2 sl1 = __half22float2(*(const __half2*)&bufl[sbse + 64]);
        float sx0 = sh0.x + sl0.x, sy0 = sh0.y + sl0.y;
        float sx1 = sh1.x + sl1.x, sy1 = sh1.y + sl1.y;
        float2 w00 = *(const float2*)&wqb[jj],       w01 = *(const float2*)&wqb[jj + 64];
        float2 w10 = *(const float2*)&wqb[128 + jj], w11 = *(const float2*)&wqb[128 + jj + 64];
        qb0 = sx0*w00.x + sy0*w00.y + sx1*w01.x + sy1*w01.y;
        qb1 = sx0*w10.x + sy0*w10.y + sx1*w11.x + sy1*w11.y;
        #pragma unroll
        for (int o = 16; o; o >>= 1) {
            qb0 += __shfl_xor_sync(0xffffffffu, qb0, o);
            qb1 += __shfl_xor_sync(0xffffffffu, qb1, o);
        }
        qb0 += cqb[0]; qb1 += cqb[1];
    }

    float2 qw0[6], qw1[6];
    {
        const float* qwp = QW + (size_t)m * 768;
        #pragma unroll
        for (int t = 0; t < 6; t++) {
            qw0[t] = *(const float2*)&qwp[jj + 64 * t];
            qw1[t] = *(const float2*)&qwp[384 + jj + 64 * t];
        }
    }

    float tsv = ts[m / ts_div];
    bool allm = true;
    #pragma unroll
    for (int k = 0; k < N_K; k++) allm = allm && (neigh[m * N_K + k] == 0);

    // ---- single pass: online softmax + ctx accumulation
    float mx0 = -3.0e38f, mx1 = -3.0e38f, sm0 = 0.f, sm1 = 0.f;
    float2 a0[6], a1[6];
    #pragma unroll
    for (int t = 0; t < 6; t++) { a0[t] = make_float2(0.f, 0.f); a1[t] = make_float2(0.f, 0.f); }

    #pragma unroll
    for (int k = 0; k < N_K; k++) {
        int ndk = neigh[m * N_K + k];
        int edk = eidx [m * N_K + k];
        float2 v[6];
        if (dense_neigh) {
            const float* dr = dense_neigh + (size_t)(m * N_K + k) * N_D;
            v[0] = *(const float2*)&dr[jj];
            v[1] = *(const float2*)&dr[jj + 64];
        } else {
            const float* nr = nf  + (size_t)ndk * N_D;
            const float* mr = mem + (size_t)ndk * N_D;
            float2 a_ = *(const float2*)&nr[jj],      b_ = *(const float2*)&mr[jj];
            float2 c_ = *(const float2*)&nr[jj + 64], d_ = *(const float2*)&mr[jj + 64];
            v[0] = make_float2(a_.x + b_.x, a_.y + b_.y);
            v[1] = make_float2(c_.x + d_.x, c_.y + d_.y);
        }
        {
            const float* er = ef + (size_t)edk * N_D;
            v[2] = *(const float2*)&er[jj];
            v[3] = *(const float2*)&er[jj + 64];
        }
        float dd = tsv - etime[m * N_K + k];
        v[4].x = cosf(__fadd_rn(__fmul_rn(dd, s_tw[jj]),      s_tb[jj]));
        v[4].y = cosf(__fadd_rn(__fmul_rn(dd, s_tw[jj + 1]),  s_tb[jj + 1]));
        v[5].x = cosf(__fadd_rn(__fmul_rn(dd, s_tw[jj + 64]), s_tb[jj + 64]));
        v[5].y = cosf(__fadd_rn(__fmul_rn(dd, s_tw[jj + 65]), s_tb[jj + 65]));

        float p0 = 0.f, p1 = 0.f;
        #pragma unroll
        for (int t = 0; t < 6; t++) {
            p0 += qw0[t].x * v[t].x + qw0[t].y * v[t].y;
            p1 += qw1[t].x * v[t].x + qw1[t].y * v[t].y;
        }
        #pragma unroll
        for (int o = 16; o; o >>= 1) {
            p0 += __shfl_xor_sync(0xffffffffu, p0, o);
            p1 += __shfl_xor_sync(0xffffffffu, p1, o);
        }
        bool mk = (ndk == 0) && !(allm && k == 0);
        float sc0 = mk ? -1e9f : (p0 + qb0) * SC;
        float sc1 = mk ? -1e9f : (p1 + qb1) * SC;

        // online update head 0
        float nm0 = fmaxf(mx0, sc0);
        float rs0 = expf(mx0 - nm0);          // rescale old state
        float e0  = expf(sc0 - nm0);
        sm0 = sm0 * rs0 + e0;
        mx0 = nm0;
        // head 1
        float nm1 = fmaxf(mx1, sc1);
        float rs1 = expf(mx1 - nm1);
        float e1  = expf(sc1 - nm1);
        sm1 = sm1 * rs1 + e1;
        mx1 = nm1;
        #pragma unroll
        for (int t = 0; t < 6; t++) {
            a0[t].x = fmaf(e0, v[t].x, a0[t].x * rs0);
            a0[t].y = fmaf(e0, v[t].y, a0[t].y * rs0);
            a1[t].x = fmaf(e1, v[t].x, a1[t].x * rs1);
            a1[t].y = fmaf(e1, v[t].y, a1[t].y * rs1);
        }
    }

    float zf = allm ? 0.f : 1.f;       // fold invalid-row zeroing into ctx
    float r0 = zf / sm0, r1 = zf / sm1;

    size_t ob = (size_t)m * 896 + jj;
    #pragma unroll
    for (int t = 0; t < 6; t++) {
        __half2 hh, ll;
        split2h(a0[t].x * r0, hh.x, ll.x); split2h(a0[t].y * r0, hh.y, ll.y);
        *(__half2*)&ctxh[ob + 64 * t] = hh;
        *(__half2*)&ctxl[ob + 64 * t] = ll;
        split2h(a1[t].x * r1, hh.x, ll.x); split2h(a1[t].y * r1, hh.y, ll.y);
        *(__half2*)&ctxh[ob + 384 + 64 * t] = hh;
        *(__half2*)&ctxl[ob + 384 + 64 * t] = ll;
    }
    if (lane == 0) inv[m] = allm ? 1 : 0;
}

// ---------------- one temporal attention layer ------------------------------
struct Ptrs {
    __half *bufh, *bufl, *hh, *hl;
    float *QW; int* inv;
    __half *wcq, *wf, *w2;
    float *cq, *ckq, *cvec, *wqb, *cqb;
};

static void run_layer(const Ptrs& P, int p, int M,
                      const int* neigh, const float* dense_neigh,
                      const int* eidx, const float* etime,
                      const float* ts, int ts_div,
                      const float* nf, const float* mem, const float* ef,
                      const float* tw, const float* tb,
                      const float* b1, const float* b2,
                      float* outCf, __half* outOh, __half* outOl, int out_ldo)
{
    // QW = src @ Wcombq^T + ckq
    mma_gemm<<<dim3(6, M/128), 256, GSMEM>>>(
        P.bufh + 768, P.bufl + 768, 896,
        P.wcq + (size_t)p*768*128, 128, 128,
        P.ckq + p*768, nullptr, P.QW, 768, nullptr, nullptr, 0, nullptr, 0);
    // fused keyv-build + attention -> ctx into buf cols 0..767
    fused_attn<<<(M + 3) / 4, 128>>>(neigh, eidx, etime, ts, ts_div,
                                     nf, mem, ef, dense_neigh, tw, tb,
                                     P.QW, P.bufh, P.bufl,
                                     P.wqb + p*256, P.cqb + p*2,
                                     P.bufh, P.bufl, P.inv, M);
    // h = relu(buf @ wf^T + b1 + (valid ? cvec : 0))
    mma_gemm<<<dim3(1, M/128), 256, GSMEM>>>(
        P.bufh, P.bufl, 896,
        P.wf + (size_t)p*128*896, 896, 896,
        b1 + p*128, P.cvec + p*128, nullptr, 0, P.hh, P.hl, 128, P.inv, GF_RELU);
    // out = h @ W2^T + b2
    mma_gemm<<<dim3(1, M/128), 256, GSMEM>>>(
        P.hh, P.hl, 128,
        P.w2 + (size_t)p*16384, 128, 128,
        b2 + p*128, nullptr, outCf, 128, outOh, outOl, out_ldo, nullptr, 0);
}

// ---------------- entry -----------------------------------------------------
extern "C" void kernel_launch(void* const* d_in, const int* in_sizes, int n_in,
                              void* d_out, int out_size)
{
    const float* node_feat   = (const float*)d_in[0];
    const float* memory      = (const float*)d_in[1];
    const float* edge_feat   = (const float*)d_in[2];
    const float* time_w      = (const float*)d_in[3];
    const float* time_b      = (const float*)d_in[4];
    const float* Wq          = (const float*)d_in[5];
    const float* bq          = (const float*)d_in[6];
    const float* Wk          = (const float*)d_in[7];
    const float* bk          = (const float*)d_in[8];
    const float* Wv          = (const float*)d_in[9];
    const float* bv          = (const float*)d_in[10];
    const float* Wo          = (const float*)d_in[11];
    const float* bo          = (const float*)d_in[12];
    const float* W1          = (const float*)d_in[13];
    const float* b1          = (const float*)d_in[14];
    const float* W2          = (const float*)d_in[15];
    const float* b2          = (const float*)d_in[16];
    const float* timestamps  = (const float*)d_in[17];
    const int*   src_nodes   = (const int*)d_in[18];
    const int*   neighbors1  = (const int*)d_in[19];
    const int*   edge_idx1   = (const int*)d_in[20];
    const float* edge_times1 = (const float*)d_in[21];
    const int*   neighbors2  = (const int*)d_in[22];
    const int*   edge_idx2   = (const int*)d_in[23];
    const float* edge_times2 = (const float*)d_in[24];

    cudaFuncSetAttribute(mma_gemm, cudaFuncAttributeMaxDynamicSharedMemorySize, GSMEM);

    Ptrs P; float *NL1, *tmpvo, *bvo;
    cudaGetSymbolAddress((void**)&P.QW,   g_QW);
    cudaGetSymbolAddress((void**)&P.bufh, g_buf_h);
    cudaGetSymbolAddress((void**)&P.bufl, g_buf_l);
    cudaGetSymbolAddress((void**)&P.hh,   g_h_h);
    cudaGetSymbolAddress((void**)&P.hl,   g_h_l);
    cudaGetSymbolAddress((void**)&NL1,    g_NL1);
    cudaGetSymbolAddress((void**)&P.inv,  g_inv);
    cudaGetSymbolAddress((void**)&P.cq,   g_cq);
    cudaGetSymbolAddress((void**)&P.wcq,  g_wcq);
    cudaGetSymbolAddress((void**)&P.ckq,  g_ckq);
    cudaGetSymbolAddress((void**)&tmpvo,  g_tmpvo);
    cudaGetSymbolAddress((void**)&bvo,    g_bvo);
    cudaGetSymbolAddress((void**)&P.wf,   g_wf);
    cudaGetSymbolAddress((void**)&P.cvec, g_cvec);
    cudaGetSymbolAddress((void**)&P.w2,   g_w2);
    cudaGetSymbolAddress((void**)&P.wqb,  g_wqb);
    cudaGetSymbolAddress((void**)&P.cqb,  g_cqb);

    // launch 1: const_q | comb_vo | stage-1 gather
    prep1_kernel<<<2 + 1536 + M_HOP2/2, 256>>>(
        Wq, bq, time_b, Wo, Wv, bo, bv,
        node_feat, memory, neighbors1,
        P.cq, tmpvo, bvo, P.bufh, P.bufl);
    // launch 2: comb_q | comb_qb | comb_w1 | misc
    prep2_kernel<<<768 + 2 + 768 + 256, 256>>>(
        Wk, Wq, P.cq, bk, W1, W2, tmpvo, bvo,
        P.wcq, P.ckq, P.wqb, P.cqb, P.wf, P.cvec, P.w2);

    // stage 1: layer-1 embedding of flattened first-hop neighbors (p0)
    run_layer(P, 0, M_HOP2, neighbors2, nullptr, edge_idx2, edge_times2,
              timestamps, N_K, node_feat, memory, edge_feat, time_w, time_b,
              b1, b2, NL1, nullptr, nullptr, 0);

    // stage 2: layer-1 embedding of src nodes (p0); SL1 -> buf col 768
    gather_emb_kernel<<<N_B, 128>>>(node_feat, memory, src_nodes, P.bufh, P.bufl, N_B);
    run_layer(P, 0, N_B, neighbors1, nullptr, edge_idx1, edge_times1,
              timestamps, 1, node_feat, memory, edge_feat, time_w, time_b,
              b1, b2, nullptr, P.bufh + 768, P.bufl + 768, 896);

    // stage 3: layer-2 aggregation (p1), neighbor feats = NL1
    run_layer(P, 1, N_B, neighbors1, NL1, edge_idx1, edge_times1,
              timestamps, 1, node_feat, memory, edge_feat, time_w, time_b,
              b1, b2, (float*)d_out, nullptr, nullptr, 0);
}

// round 14
// speedup vs baseline: 1.3014x; 1.0170x over previous
#include <cuda_runtime.h>
#include <cuda_fp16.h>
#include <math.h>
#include <stdint.h>

#define N_B   8192
#define N_K   10
#define N_D   128
#define M_HOP2 (N_B * N_K)          // 81920

// ---------------- scratch (static __device__ globals; no allocs) ------------
__device__ float  g_QW   [(size_t)M_HOP2 * 768];     // src @ Wcombq^T + ckq
__device__ __half g_buf_h[(size_t)M_HOP2 * 896];     // [ctx(768) || src(128)] hi
__device__ __half g_buf_l[(size_t)M_HOP2 * 896];     // lo
__device__ __half g_h_h  [(size_t)M_HOP2 * N_D];
__device__ __half g_h_l  [(size_t)M_HOP2 * N_D];
__device__ float  g_NL1  [(size_t)M_HOP2 * N_D];
__device__ int    g_inv  [M_HOP2];
__device__ float  g_cq   [2 * 256];
// combined weights
__device__ __half g_wcq [2*768*128];                 // Wk_h^T @ Wq1_h
__device__ float  g_ckq [2*768];                     // Wk_h^T @ cq_h
__device__ float  g_tmpvo[2*256*768];                // Wo @ Wv_blockdiag (fp32 temp)
__device__ float  g_bvo [2*256];                     // Wo bv + bo
__device__ __half g_wf  [2*128*896];                 // [W1a@Wvo || W1b] fp16
__device__ float  g_cvec[2*128];                     // W1a @ bvo
__device__ __half g_w2  [2*128*128];
__device__ float  g_wqb [2*2*128];                   // Wq1_h^T bk_h
__device__ float  g_cqb [2*2];                       // bk_h . cq_h

// ---------------- helpers ---------------------------------------------------
__device__ __forceinline__ void split2h(float v, __half& h, __half& l) {
    h = __float2half_rn(v);
    l = __float2half_rn(v - __half2float(h));
}

// ================= prep 1: const_q | comb_vo | stage-1 gather ================
__global__ __launch_bounds__(256) void prep1_kernel(
    const float* __restrict__ Wq, const float* __restrict__ bq,
    const float* __restrict__ tb,
    const float* __restrict__ Wo, const float* __restrict__ Wv,
    const float* __restrict__ bo, const float* __restrict__ bv,
    const float* __restrict__ nf, const float* __restrict__ mem,
    const int* __restrict__ idx,
    float* __restrict__ cq, float* __restrict__ tmpvo, float* __restrict__ bvo,
    __half* __restrict__ dh, __half* __restrict__ dl)
{
    int blk = blockIdx.x, tid = threadIdx.x;
    if (blk < 2) {                     // const_q
        __shared__ float ct[128];
        int p = blk, j = tid;
        if (j < 128) ct[j] = cosf(tb[j]);
        __syncthreads();
        const float* W = Wq + (size_t)p * 65536;
        float s = bq[p * 256 + j];
        #pragma unroll 4
        for (int t = 0; t < 128; t++) s = fmaf(ct[t], W[(size_t)j * 256 + 128 + t], s);
        cq[p * 256 + j] = s;
        return;
    }
    blk -= 2;
    if (blk < 1536) {                  // comb_vo
        int p = blk / 768, rr = blk % 768;
        int i = rr / 3, jc = rr % 3;
        int j = jc * 256 + tid;
        int h = j / 384, jp = j % 384;
        float acc = 0.f;
        #pragma unroll 4
        for (int d = 0; d < 128; d++)
            acc = fmaf(Wo[((size_t)p*256 + i)*256 + h*128 + d],
                       Wv[((size_t)p*256 + h*128 + d)*384 + jp], acc);
        tmpvo[((size_t)p*256 + i)*768 + j] = acc;
        if (jc == 0 && tid == 0) {
            float c = bo[p*256 + i];
            for (int e = 0; e < 256; e++)
                c = fmaf(Wo[((size_t)p*256 + i)*256 + e], bv[p*256 + e], c);
            bvo[p*256 + i] = c;
        }
        return;
    }
    blk -= 1536;                       // stage-1 gather: 2 rows/block
    int r = blk * 2 + (tid >> 7);
    int t = tid & 127;
    size_t s = (size_t)idx[r] * N_D + t;
    float v = nf[s] + mem[s];
    size_t o = (size_t)r * 896 + 768 + t;
    split2h(v, dh[o], dl[o]);
}

// ================= prep 2: comb_q | comb_qb | comb_w1 | misc =================
__global__ __launch_bounds__(256) void prep2_kernel(
    const float* __restrict__ Wk, const float* __restrict__ Wq,
    const float* __restrict__ cq, const float* __restrict__ bk,
    const float* __restrict__ W1, const float* __restrict__ W2,
    const float* __restrict__ tmpvo, const float* __restrict__ bvo,
    __half* __restrict__ wcq, float* __restrict__ ckq,
    float* __restrict__ wqb, float* __restrict__ cqb,
    __half* __restrict__ wf, float* __restrict__ cvec, __half* __restrict__ w2)
{
    int blk = blockIdx.x, tid = threadIdx.x;
    if (blk < 768) {                   // comb_q: 2 jr rows per block
        __shared__ float wk[2][128];
        int p = blk / 384;
        int half_ = tid >> 7, s = tid & 127;
        int jr = (blk % 384) * 2 + half_;
        int h = jr / 384, j = jr % 384;
        wk[half_][s] = Wk[((size_t)p*256 + h*128 + s)*384 + j];
        __syncthreads();
        float acc = 0.f;
        #pragma unroll 4
        for (int d = 0; d < 128; d++)
            acc = fmaf(wk[half_][d], Wq[((size_t)p*256 + h*128 + d)*256 + s], acc);
        wcq[((size_t)p*768 + jr)*128 + s] = __float2half_rn(acc);
        if (s == 0) {
            float c = 0.f;
            for (int d = 0; d < 128; d++) c = fmaf(wk[half_][d], cq[p*256 + h*128 + d], c);
            ckq[p*768 + jr] = c;
        }
        return;
    }
    blk -= 768;
    if (blk < 2) {                     // comb_qb
        int id = blk * 256 + tid;
        int p = id / 256, h = (id % 256) / 128, s = id % 128;
        float acc = 0.f;
        #pragma unroll 4
        for (int d = 0; d < 128; d++)
            acc = fmaf(Wq[((size_t)p*256 + h*128 + d)*256 + s], bk[p*256 + h*128 + d], acc);
        wqb[(p*2 + h)*128 + s] = acc;
        if (s == 0) {
            float c = 0.f;
            for (int d = 0; d < 128; d++)
                c = fmaf(bk[p*256 + h*128 + d], cq[p*256 + h*128 + d], c);
            cqb[p*2 + h] = c;
        }
        return;
    }
    blk -= 2;
    if (blk < 768) {                   // comb_w1
        __shared__ float w1r[256];
        int p = blk / 384, rr = blk % 384;
        int n = rr / 3, jc = rr % 3;
        w1r[tid] = W1[((size_t)p*128 + n)*384 + tid];
        __syncthreads();
        int j = jc * 256 + tid;
        float acc = 0.f;
        #pragma unroll 4
        for (int e = 0; e < 256; e++)
            acc = fmaf(w1r[e], tmpvo[((size_t)p*256 + e)*768 + j], acc);
        wf[((size_t)p*128 + n)*896 + j] = __float2half_rn(acc);
        if (jc == 0 && tid == 0) {
            float c = 0.f;
            for (int e = 0; e < 256; e++) c = fmaf(w1r[e], bvo[p*256 + e], c);
            cvec[p*128 + n] = c;
        }
        return;
    }
    blk -= 768;
    {                                  // misc
        int i = blk * 256 + tid;
        if (i < 32768) {
            int p = i >> 14, r = i & 16383;
            int n = r >> 7, d = r & 127;
            wf[((size_t)p*128 + n)*896 + 768 + d] =
                __float2half_rn(W1[((size_t)p*128 + n)*384 + 256 + d]);
        } else {
            i -= 32768;
            w2[i] = __float2half_rn(W2[i]);
        }
    }
}

// gather emb0 into buf at col 768 (stage 2)
__global__ void gather_emb_kernel(const float* __restrict__ nf,
                                  const float* __restrict__ mem,
                                  const int* __restrict__ idx,
                                  __half* __restrict__ dh, __half* __restrict__ dl, int n)
{
    int r = blockIdx.x;
    if (r >= n) return;
    int t = threadIdx.x;
    size_t s = (size_t)idx[r] * N_D + t;
    float v = nf[s] + mem[s];
    size_t o = (size_t)r * 896 + 768 + t;
    split2h(v, dh[o], dl[o]);
}

// ---------------- fp16 2-pass tensor-core GEMM ------------------------------
#define GF_RELU 1
#define SMS  40
#define MATB (128 * SMS * 2)
#define STGB (3 * MATB)
#define NSTG 3
#define GSMEM (NSTG * STGB)

__device__ __forceinline__ void cpa16(uint32_t s, const void* g) {
    asm volatile("cp.async.cg.shared.global [%0], [%1], 16;\n" :: "r"(s), "l"(g));
}
__device__ __forceinline__ void ldm4(uint32_t* r, uint32_t a) {
    asm volatile("ldmatrix.sync.aligned.m8n8.x4.shared.b16 {%0,%1,%2,%3},[%4];\n"
                 : "=r"(r[0]), "=r"(r[1]), "=r"(r[2]), "=r"(r[3]) : "r"(a));
}
__device__ __forceinline__ void mmaf16(float* d, const uint32_t* a, uint32_t b0, uint32_t b1) {
    asm volatile("mma.sync.aligned.m16n8k16.row.col.f32.f16.f16.f32 "
                 "{%0,%1,%2,%3},{%4,%5,%6,%7},{%8,%9},{%0,%1,%2,%3};\n"
                 : "+f"(d[0]), "+f"(d[1]), "+f"(d[2]), "+f"(d[3])
                 : "r"(a[0]), "r"(a[1]), "r"(a[2]), "r"(a[3]), "r"(b0), "r"(b1));
}

__device__ __forceinline__ void issue_chunk(uint32_t sw, uint32_t bufofs,
    const __half* Ah, const __half* Al, size_t ga,
    const __half* Wh, size_t gw)
{
    uint32_t s0 = sw + bufofs;
    cpa16(s0,          Ah + ga); cpa16(s0 + 32,          Ah + ga + 16);
    cpa16(s0 + MATB,   Al + ga); cpa16(s0 + MATB + 32,   Al + ga + 16);
    cpa16(s0 + 2*MATB, Wh + gw); cpa16(s0 + 2*MATB + 32, Wh + gw + 16);
    asm volatile("cp.async.commit_group;\n");
}

__global__ __launch_bounds__(256, 2) void mma_gemm(
    const __half* __restrict__ Ah, const __half* __restrict__ Al, int lda,
    const __half* __restrict__ Wh, int ldw,
    int Kd,
    const float* __restrict__ bias, const float* __restrict__ bias2,
    float* __restrict__ Cf, int ldcf,
    __half* __restrict__ Oh, __half* __restrict__ Ol, int ldo,
    const int* __restrict__ zmask, int flags)
{
    extern __shared__ __align__(16) char smem_raw[];
    uint32_t sb = (uint32_t)__cvta_generic_to_shared(smem_raw);
    int tid = threadIdx.x;
    int m0 = blockIdx.y * 128, n0 = blockIdx.x * 128;
    int lane = tid & 31, wid = tid >> 5;
    int wm = wid & 1, wn = wid >> 1;

    float d[4][4][4];
    #pragma unroll
    for (int i = 0; i < 4; i++)
        #pragma unroll
        for (int j = 0; j < 4; j++)
            #pragma unroll
            for (int r = 0; r < 4; r++) d[i][j][r] = 0.f;

    int row = tid >> 1;
    int ce  = (tid & 1) << 3;
    size_t ga0 = (size_t)(m0 + row) * lda + ce;
    size_t gw0 = (size_t)(n0 + row) * ldw + ce;
    uint32_t sw = sb + (uint32_t)(row * SMS + ce) * 2;

    int nch = Kd >> 5;
    issue_chunk(sw, 0, Ah, Al, ga0, Wh, gw0);
    if (nch > 1) issue_chunk(sw, STGB, Ah, Al, ga0 + 32, Wh, gw0 + 32);

    for (int c = 0; c < nch; c++) {
        if (c + 2 < nch) {
            int k0 = (c + 2) << 5;
            issue_chunk(sw, (uint32_t)((c + 2) % NSTG) * STGB, Ah, Al, ga0 + k0, Wh, gw0 + k0);
        }
        int issuedJ = (c + 2 < nch) ? c + 2 : nch - 1;
        int allow = issuedJ - c;
        if (allow >= 2)      asm volatile("cp.async.wait_group 2;\n" ::: "memory");
        else if (allow == 1) asm volatile("cp.async.wait_group 1;\n" ::: "memory");
        else                 asm volatile("cp.async.wait_group 0;\n" ::: "memory");
        __syncthreads();

        uint32_t base = sb + (uint32_t)(c % NSTG) * STGB;
        #pragma unroll
        for (int h = 0; h < 2; h++) {
            uint32_t ah[4][4], al[4][4], bh[2][4];
            int colA = (h << 4) + ((lane >> 4) << 3);
            #pragma unroll
            for (int mi = 0; mi < 4; mi++) {
                int r_ = wm * 64 + mi * 16 + (lane & 15);
                uint32_t ad = base + (uint32_t)(r_ * SMS + colA) * 2;
                ldm4(ah[mi], ad);
                ldm4(al[mi], ad + MATB);
            }
            #pragma unroll
            for (int nj2 = 0; nj2 < 2; nj2++) {
                int r_ = wn * 32 + nj2 * 16 + (lane & 7) + (((lane >> 3) & 1) << 3);
                uint32_t bd = base + 2 * MATB + (uint32_t)(r_ * SMS + colA) * 2;
                ldm4(bh[nj2], bd);
            }
            #pragma unroll
            for (int mi = 0; mi < 4; mi++)
                #pragma unroll
                for (int nj = 0; nj < 4; nj++)
                    mmaf16(d[mi][nj], ah[mi], bh[nj >> 1][nj & 1], bh[nj >> 1][(nj & 1) + 2]);
            #pragma unroll
            for (int mi = 0; mi < 4; mi++)
                #pragma unroll
                for (int nj = 0; nj < 4; nj++)
                    mmaf16(d[mi][nj], al[mi], bh[nj >> 1][nj & 1], bh[nj >> 1][(nj & 1) + 2]);
        }
        __syncthreads();
    }

    int gr = lane >> 2, tg = lane & 3;
    #pragma unroll
    for (int mi = 0; mi < 4; mi++) {
        int mb = m0 + wm * 64 + mi * 16 + gr;
        #pragma unroll
        for (int half = 0; half < 2; half++) {
            int m = mb + half * 8;
            bool zm = (zmask != nullptr) && (zmask[m] != 0);
            #pragma unroll
            for (int nj = 0; nj < 4; nj++) {
                int n = n0 + wn * 32 + nj * 8 + tg * 2;
                float v0 = d[mi][nj][half * 2 + 0];
                float v1 = d[mi][nj][half * 2 + 1];
                if (bias) { v0 += bias[n]; v1 += bias[n + 1]; }
                if (bias2) {
                    if (!zm) { v0 += bias2[n]; v1 += bias2[n + 1]; }
                } else if (zm) { v0 = 0.f; v1 = 0.f; }
                if (flags & GF_RELU) { v0 = fmaxf(v0, 0.f); v1 = fmaxf(v1, 0.f); }
                if (Cf) *(float2*)&Cf[(size_t)m * ldcf + n] = make_float2(v0, v1);
                if (Oh) {
                    __half2 hh, ll;
                    split2h(v0, hh.x, ll.x);
                    split2h(v1, hh.y, ll.y);
                    *(__half2*)&Oh[(size_t)m * ldo + n] = hh;
                    *(__half2*)&Ol[(size_t)m * ldo + n] = ll;
                }
            }
        }
    }
}

// ------- fused keyv-build + attention: online softmax, float4 gathers -------
// One warp per row m, 4 warps/block. l4 = lane*4 covers all 128 cols per load.
__global__ __launch_bounds__(128, 4) void fused_attn(
    const int* __restrict__ neigh,
    const int* __restrict__ eidx,
    const float* __restrict__ etime,
    const float* __restrict__ ts, int ts_div,
    const float* __restrict__ nf, const float* __restrict__ mem,
    const float* __restrict__ ef,
    const float* __restrict__ dense_neigh,
    const float* __restrict__ tw, const float* __restrict__ tb,
    const float* __restrict__ QW,
    const __half* __restrict__ bufh, const __half* __restrict__ bufl,
    const float* __restrict__ wqb, const float* __restrict__ cqb,
    __half* __restrict__ ctxh, __half* __restrict__ ctxl,
    int* __restrict__ inv, int M)
{
    __shared__ float s_tw[128], s_tb[128];
    int tid = threadIdx.x;
    s_tw[tid] = tw[tid];
    s_tb[tid] = tb[tid];
    __syncthreads();

    int wl = tid >> 5, lane = tid & 31;
    int m = blockIdx.x * 4 + wl;
    if (m >= M) return;
    const float SC = 0.08838834764831843f;   // 1/sqrt(128)
    int l4 = lane * 4;

    // qb_h = src . wqb_h + cqb_h   (src = buf hi+lo cols 768..895)
    float qb0, qb1;
    {
        size_t sbse = (size_t)m * 896 + 768 + l4;
        float2 fh0 = __half22float2(*(const __half2*)&bufh[sbse]);
        float2 fh1 = __half22float2(*(const __half2*)&bufh[sbse + 2]);
        float2 fl0 = __half22float2(*(const __half2*)&bufl[sbse]);
        float2 fl1 = __half22float2(*(const __half2*)&bufl[sbse + 2]);
        float sx = fh0.x + fl0.x, sy = fh0.y + fl0.y;
        float sz = fh1.x + fl1.x, sw_ = fh1.y + fl1.y;
        float4 w0 = *(const float4*)&wqb[l4];
        float4 w1 = *(const float4*)&wqb[128 + l4];
        qb0 = sx*w0.x + sy*w0.y + sz*w0.z + sw_*w0.w;
        qb1 = sx*w1.x + sy*w1.y + sz*w1.z + sw_*w1.w;
        #pragma unroll
        for (int o = 16; o; o >>= 1) {
            qb0 += __shfl_xor_sync(0xffffffffu, qb0, o);
            qb1 += __shfl_xor_sync(0xffffffffu, qb1, o);
        }
        qb0 += cqb[0]; qb1 += cqb[1];
    }

    float4 qw0[3], qw1[3];
    {
        const float* qwp = QW + (size_t)m * 768;
        #pragma unroll
        for (int s = 0; s < 3; s++) {
            qw0[s] = *(const float4*)&qwp[s * 128 + l4];
            qw1[s] = *(const float4*)&qwp[384 + s * 128 + l4];
        }
    }

    float tsv = ts[m / ts_div];
    bool allm = true;
    #pragma unroll
    for (int k = 0; k < N_K; k++) allm = allm && (neigh[m * N_K + k] == 0);

    // ---- single pass: online softmax + ctx accumulation
    float mx0 = -3.0e38f, mx1 = -3.0e38f, sm0 = 0.f, sm1 = 0.f;
    float4 a0[3], a1[3];
    #pragma unroll
    for (int s = 0; s < 3; s++) {
        a0[s] = make_float4(0.f, 0.f, 0.f, 0.f);
        a1[s] = make_float4(0.f, 0.f, 0.f, 0.f);
    }

    #pragma unroll
    for (int k = 0; k < N_K; k++) {
        int ndk = neigh[m * N_K + k];
        int edk = eidx [m * N_K + k];
        float4 vn, ve, vc;
        if (dense_neigh) {
            vn = *(const float4*)&dense_neigh[(size_t)(m * N_K + k) * N_D + l4];
        } else {
            float4 a = *(const float4*)&nf [(size_t)ndk * N_D + l4];
            float4 b = *(const float4*)&mem[(size_t)ndk * N_D + l4];
            vn = make_float4(a.x + b.x, a.y + b.y, a.z + b.z, a.w + b.w);
        }
        ve = *(const float4*)&ef[(size_t)edk * N_D + l4];
        float dd = tsv - etime[m * N_K + k];
        vc.x = cosf(__fadd_rn(__fmul_rn(dd, s_tw[l4 + 0]), s_tb[l4 + 0]));
        vc.y = cosf(__fadd_rn(__fmul_rn(dd, s_tw[l4 + 1]), s_tb[l4 + 1]));
        vc.z = cosf(__fadd_rn(__fmul_rn(dd, s_tw[l4 + 2]), s_tb[l4 + 2]));
        vc.w = cosf(__fadd_rn(__fmul_rn(dd, s_tw[l4 + 3]), s_tb[l4 + 3]));

        float p0 = qw0[0].x*vn.x + qw0[0].y*vn.y + qw0[0].z*vn.z + qw0[0].w*vn.w
                 + qw0[1].x*ve.x + qw0[1].y*ve.y + qw0[1].z*ve.z + qw0[1].w*ve.w
                 + qw0[2].x*vc.x + qw0[2].y*vc.y + qw0[2].z*vc.z + qw0[2].w*vc.w;
        float p1 = qw1[0].x*vn.x + qw1[0].y*vn.y + qw1[0].z*vn.z + qw1[0].w*vn.w
                 + qw1[1].x*ve.x + qw1[1].y*ve.y + qw1[1].z*ve.z + qw1[1].w*ve.w
                 + qw1[2].x*vc.x + qw1[2].y*vc.y + qw1[2].z*vc.z + qw1[2].w*vc.w;
        #pragma unroll
        for (int o = 16; o; o >>= 1) {
            p0 += __shfl_xor_sync(0xffffffffu, p0, o);
            p1 += __shfl_xor_sync(0xffffffffu, p1, o);
        }
        bool mk = (ndk == 0) && !(allm && k == 0);
        float sc0 = mk ? -1e9f : (p0 + qb0) * SC;
        float sc1 = mk ? -1e9f : (p1 + qb1) * SC;

        // online update
        float nm0 = fmaxf(mx0, sc0);
        float rs0 = expf(mx0 - nm0);
        float e0  = expf(sc0 - nm0);
        sm0 = sm0 * rs0 + e0;
        mx0 = nm0;
        float nm1 = fmaxf(mx1, sc1);
        float rs1 = expf(mx1 - nm1);
        float e1  = expf(sc1 - nm1);
        sm1 = sm1 * rs1 + e1;
        mx1 = nm1;
        a0[0].x = fmaf(e0, vn.x, a0[0].x * rs0); a0[0].y = fmaf(e0, vn.y, a0[0].y * rs0);
        a0[0].z = fmaf(e0, vn.z, a0[0].z * rs0); a0[0].w = fmaf(e0, vn.w, a0[0].w * rs0);
        a0[1].x = fmaf(e0, ve.x, a0[1].x * rs0); a0[1].y = fmaf(e0, ve.y, a0[1].y * rs0);
        a0[1].z = fmaf(e0, ve.z, a0[1].z * rs0); a0[1].w = fmaf(e0, ve.w, a0[1].w * rs0);
        a0[2].x = fmaf(e0, vc.x, a0[2].x * rs0); a0[2].y = fmaf(e0, vc.y, a0[2].y * rs0);
        a0[2].z = fmaf(e0, vc.z, a0[2].z * rs0); a0[2].w = fmaf(e0, vc.w, a0[2].w * rs0);
        a1[0].x = fmaf(e1, vn.x, a1[0].x * rs1); a1[0].y = fmaf(e1, vn.y, a1[0].y * rs1);
        a1[0].z = fmaf(e1, vn.z, a1[0].z * rs1); a1[0].w = fmaf(e1, vn.w, a1[0].w * rs1);
        a1[1].x = fmaf(e1, ve.x, a1[1].x * rs1); a1[1].y = fmaf(e1, ve.y, a1[1].y * rs1);
        a1[1].z = fmaf(e1, ve.z, a1[1].z * rs1); a1[1].w = fmaf(e1, ve.w, a1[1].w * rs1);
        a1[2].x = fmaf(e1, vc.x, a1[2].x * rs1); a1[2].y = fmaf(e1, vc.y, a1[2].y * rs1);
        a1[2].z = fmaf(e1, vc.z, a1[2].z * rs1); a1[2].w = fmaf(e1, vc.w, a1[2].w * rs1);
    }

    float zf = allm ? 0.f : 1.f;       // fold invalid-row zeroing into ctx
    float r0 = zf / sm0, r1 = zf / sm1;

    size_t ob = (size_t)m * 896;
    #pragma unroll
    for (int s = 0; s < 3; s++) {
        __half2 hh0, ll0, hh1, ll1;
        split2h(a0[s].x * r0, hh0.x, ll0.x); split2h(a0[s].y * r0, hh0.y, ll0.y);
        split2h(a0[s].z * r0, hh1.x, ll1.x); split2h(a0[s].w * r0, hh1.y, ll1.y);
        size_t o0 = ob + s * 128 + l4;
        *(__half2*)&ctxh[o0]     = hh0;  *(__half2*)&ctxl[o0]     = ll0;
        *(__half2*)&ctxh[o0 + 2] = hh1;  *(__half2*)&ctxl[o0 + 2] = ll1;
        split2h(a1[s].x * r1, hh0.x, ll0.x); split2h(a1[s].y * r1, hh0.y, ll0.y);
        split2h(a1[s].z * r1, hh1.x, ll1.x); split2h(a1[s].w * r1, hh1.y, ll1.y);
        size_t o1 = ob + 384 + s * 128 + l4;
        *(__half2*)&ctxh[o1]     = hh0;  *(__half2*)&ctxl[o1]     = ll0;
        *(__half2*)&ctxh[o1 + 2] = hh1;  *(__half2*)&ctxl[o1 + 2] = ll1;
    }
    if (lane == 0) inv[m] = allm ? 1 : 0;
}

// ---------------- one temporal attention layer ------------------------------
struct Ptrs {
    __half *bufh, *bufl, *hh, *hl;
    float *QW; int* inv;
    __half *wcq, *wf, *w2;
    float *cq, *ckq, *cvec, *wqb, *cqb;
};

static void run_layer(const Ptrs& P, int p, int M,
                      const int* neigh, const float* dense_neigh,
                      const int* eidx, const float* etime,
                      const float* ts, int ts_div,
                      const float* nf, const float* mem, const float* ef,
                      const float* tw, const float* tb,
                      const float* b1, const float* b2,
                      float* outCf, __half* outOh, __half* outOl, int out_ldo)
{
    // QW = src @ Wcombq^T + ckq
    mma_gemm<<<dim3(6, M/128), 256, GSMEM>>>(
        P.bufh + 768, P.bufl + 768, 896,
        P.wcq + (size_t)p*768*128, 128, 128,
        P.ckq + p*768, nullptr, P.QW, 768, nullptr, nullptr, 0, nullptr, 0);
    // fused keyv-build + attention -> ctx into buf cols 0..767
    fused_attn<<<(M + 3) / 4, 128>>>(neigh, eidx, etime, ts, ts_div,
                                     nf, mem, ef, dense_neigh, tw, tb,
                                     P.QW, P.bufh, P.bufl,
                                     P.wqb + p*256, P.cqb + p*2,
                                     P.bufh, P.bufl, P.inv, M);
    // h = relu(buf @ wf^T + b1 + (valid ? cvec : 0))
    mma_gemm<<<dim3(1, M/128), 256, GSMEM>>>(
        P.bufh, P.bufl, 896,
        P.wf + (size_t)p*128*896, 896, 896,
        b1 + p*128, P.cvec + p*128, nullptr, 0, P.hh, P.hl, 128, P.inv, GF_RELU);
    // out = h @ W2^T + b2
    mma_gemm<<<dim3(1, M/128), 256, GSMEM>>>(
        P.hh, P.hl, 128,
        P.w2 + (size_t)p*16384, 128, 128,
        b2 + p*128, nullptr, outCf, 128, outOh, outOl, out_ldo, nullptr, 0);
}

// ---------------- entry -----------------------------------------------------
extern "C" void kernel_launch(void* const* d_in, const int* in_sizes, int n_in,
                              void* d_out, int out_size)
{
    const float* node_feat   = (const float*)d_in[0];
    const float* memory      = (const float*)d_in[1];
    const float* edge_feat   = (const float*)d_in[2];
    const float* time_w      = (const float*)d_in[3];
    const float* time_b      = (const float*)d_in[4];
    const float* Wq          = (const float*)d_in[5];
    const float* bq          = (const float*)d_in[6];
    const float* Wk          = (const float*)d_in[7];
    const float* bk          = (const float*)d_in[8];
    const float* Wv          = (const float*)d_in[9];
    const float* bv          = (const float*)d_in[10];
    const float* Wo          = (const float*)d_in[11];
    const float* bo          = (const float*)d_in[12];
    const float* W1          = (const float*)d_in[13];
    const float* b1          = (const float*)d_in[14];
    const float* W2          = (const float*)d_in[15];
    const float* b2          = (const float*)d_in[16];
    const float* timestamps  = (const float*)d_in[17];
    const int*   src_nodes   = (const int*)d_in[18];
    const int*   neighbors1  = (const int*)d_in[19];
    const int*   edge_idx1   = (const int*)d_in[20];
    const float* edge_times1 = (const float*)d_in[21];
    const int*   neighbors2  = (const int*)d_in[22];
    const int*   edge_idx2   = (const int*)d_in[23];
    const float* edge_times2 = (const float*)d_in[24];

    cudaFuncSetAttribute(mma_gemm, cudaFuncAttributeMaxDynamicSharedMemorySize, GSMEM);

    Ptrs P; float *NL1, *tmpvo, *bvo;
    cudaGetSymbolAddress((void**)&P.QW,   g_QW);
    cudaGetSymbolAddress((void**)&P.bufh, g_buf_h);
    cudaGetSymbolAddress((void**)&P.bufl, g_buf_l);
    cudaGetSymbolAddress((void**)&P.hh,   g_h_h);
    cudaGetSymbolAddress((void**)&P.hl,   g_h_l);
    cudaGetSymbolAddress((void**)&NL1,    g_NL1);
    cudaGetSymbolAddress((void**)&P.inv,  g_inv);
    cudaGetSymbolAddress((void**)&P.cq,   g_cq);
    cudaGetSymbolAddress((void**)&P.wcq,  g_wcq);
    cudaGetSymbolAddress((void**)&P.ckq,  g_ckq);
    cudaGetSymbolAddress((void**)&tmpvo,  g_tmpvo);
    cudaGetSymbolAddress((void**)&bvo,    g_bvo);
    cudaGetSymbolAddress((void**)&P.wf,   g_wf);
    cudaGetSymbolAddress((void**)&P.cvec, g_cvec);
    cudaGetSymbolAddress((void**)&P.w2,   g_w2);
    cudaGetSymbolAddress((void**)&P.wqb,  g_wqb);
    cudaGetSymbolAddress((void**)&P.cqb,  g_cqb);

    // launch 1: const_q | comb_vo | stage-1 gather
    prep1_kernel<<<2 + 1536 + M_HOP2/2, 256>>>(
        Wq, bq, time_b, Wo, Wv, bo, bv,
        node_feat, memory, neighbors1,
        P.cq, tmpvo, bvo, P.bufh, P.bufl);
    // launch 2: comb_q | comb_qb | comb_w1 | misc
    prep2_kernel<<<768 + 2 + 768 + 256, 256>>>(
        Wk, Wq, P.cq, bk, W1, W2, tmpvo, bvo,
        P.wcq, P.ckq, P.wqb, P.cqb, P.wf, P.cvec, P.w2);

    // stage 1: layer-1 embedding of flattened first-hop neighbors (p0)
    run_layer(P, 0, M_HOP2, neighbors2, nullptr, edge_idx2, edge_times2,
              timestamps, N_K, node_feat, memory, edge_feat, time_w, time_b,
              b1, b2, NL1, nullptr, nullptr, 0);

    // stage 2: layer-1 embedding of src nodes (p0); SL1 -> buf col 768
    gather_emb_kernel<<<N_B, 128>>>(node_feat, memory, src_nodes, P.bufh, P.bufl, N_B);
    run_layer(P, 0, N_B, neighbors1, nullptr, edge_idx1, edge_times1,
              timestamps, 1, node_feat, memory, edge_feat, time_w, time_b,
              b1, b2, nullptr, P.bufh + 768, P.bufl + 768, 896);

    // stage 3: layer-2 aggregation (p1), neighbor feats = NL1
    run_layer(P, 1, N_B, neighbors1, NL1, edge_idx1, edge_times1,
              timestamps, 1, node_feat, memory, edge_feat, time_w, time_b,
              b1, b2, (float*)d_out, nullptr, nullptr, 0);
}

// round 15
// speedup vs baseline: 1.3380x; 1.0281x over previous
#include <cuda_runtime.h>
#include <cuda_fp16.h>
#include <math.h>
#include <stdint.h>

#define N_B   8192
#define N_K   10
#define N_D   128
#define M_HOP2 (N_B * N_K)          // 81920

// ---------------- scratch (static __device__ globals; no allocs) ------------
__device__ __half g_QW   [(size_t)M_HOP2 * 768];     // fp16: src @ Wcombq^T + ckq
__device__ __half g_buf_h[(size_t)M_HOP2 * 896];     // [ctx(768) || src(128)] hi
__device__ __half g_buf_l[(size_t)M_HOP2 * 896];     // lo
__device__ __half g_h_h  [(size_t)M_HOP2 * N_D];
__device__ __half g_h_l  [(size_t)M_HOP2 * N_D];
__device__ float  g_NL1  [(size_t)M_HOP2 * N_D];
__device__ int    g_inv  [M_HOP2];
__device__ float  g_cq   [2 * 256];
// combined weights
__device__ __half g_wcq [2*768*128];                 // Wk_h^T @ Wq1_h
__device__ float  g_ckq [2*768];                     // Wk_h^T @ cq_h
__device__ float  g_tmpvo[2*256*768];                // Wo @ Wv_blockdiag (fp32 temp)
__device__ float  g_bvo [2*256];                     // Wo bv + bo
__device__ __half g_wf  [2*128*896];                 // [W1a@Wvo || W1b] fp16
__device__ float  g_cvec[2*128];                     // W1a @ bvo
__device__ __half g_w2  [2*128*128];
__device__ float  g_wqb [2*2*128];                   // Wq1_h^T bk_h
__device__ float  g_cqb [2*2];                       // bk_h . cq_h

// ---------------- helpers ---------------------------------------------------
__device__ __forceinline__ void split2h(float v, __half& h, __half& l) {
    h = __float2half_rn(v);
    l = __float2half_rn(v - __half2float(h));
}

// ================= prep 1: const_q | comb_vo | stage-1 gather ================
__global__ __launch_bounds__(256) void prep1_kernel(
    const float* __restrict__ Wq, const float* __restrict__ bq,
    const float* __restrict__ tb,
    const float* __restrict__ Wo, const float* __restrict__ Wv,
    const float* __restrict__ bo, const float* __restrict__ bv,
    const float* __restrict__ nf, const float* __restrict__ mem,
    const int* __restrict__ idx,
    float* __restrict__ cq, float* __restrict__ tmpvo, float* __restrict__ bvo,
    __half* __restrict__ dh, __half* __restrict__ dl)
{
    int blk = blockIdx.x, tid = threadIdx.x;
    if (blk < 2) {                     // const_q
        __shared__ float ct[128];
        int p = blk, j = tid;
        if (j < 128) ct[j] = cosf(tb[j]);
        __syncthreads();
        const float* W = Wq + (size_t)p * 65536;
        float s = bq[p * 256 + j];
        #pragma unroll 4
        for (int t = 0; t < 128; t++) s = fmaf(ct[t], W[(size_t)j * 256 + 128 + t], s);
        cq[p * 256 + j] = s;
        return;
    }
    blk -= 2;
    if (blk < 1536) {                  // comb_vo
        int p = blk / 768, rr = blk % 768;
        int i = rr / 3, jc = rr % 3;
        int j = jc * 256 + tid;
        int h = j / 384, jp = j % 384;
        float acc = 0.f;
        #pragma unroll 4
        for (int d = 0; d < 128; d++)
            acc = fmaf(Wo[((size_t)p*256 + i)*256 + h*128 + d],
                       Wv[((size_t)p*256 + h*128 + d)*384 + jp], acc);
        tmpvo[((size_t)p*256 + i)*768 + j] = acc;
        if (jc == 0 && tid == 0) {
            float c = bo[p*256 + i];
            for (int e = 0; e < 256; e++)
                c = fmaf(Wo[((size_t)p*256 + i)*256 + e], bv[p*256 + e], c);
            bvo[p*256 + i] = c;
        }
        return;
    }
    blk -= 1536;                       // stage-1 gather: 2 rows/block
    int r = blk * 2 + (tid >> 7);
    int t = tid & 127;
    size_t s = (size_t)idx[r] * N_D + t;
    float v = nf[s] + mem[s];
    size_t o = (size_t)r * 896 + 768 + t;
    split2h(v, dh[o], dl[o]);
}

// ================= prep 2: comb_q | comb_qb | comb_w1 | misc =================
__global__ __launch_bounds__(256) void prep2_kernel(
    const float* __restrict__ Wk, const float* __restrict__ Wq,
    const float* __restrict__ cq, const float* __restrict__ bk,
    const float* __restrict__ W1, const float* __restrict__ W2,
    const float* __restrict__ tmpvo, const float* __restrict__ bvo,
    __half* __restrict__ wcq, float* __restrict__ ckq,
    float* __restrict__ wqb, float* __restrict__ cqb,
    __half* __restrict__ wf, float* __restrict__ cvec, __half* __restrict__ w2)
{
    int blk = blockIdx.x, tid = threadIdx.x;
    if (blk < 768) {                   // comb_q: 2 jr rows per block
        __shared__ float wk[2][128];
        int p = blk / 384;
        int half_ = tid >> 7, s = tid & 127;
        int jr = (blk % 384) * 2 + half_;
        int h = jr / 384, j = jr % 384;
        wk[half_][s] = Wk[((size_t)p*256 + h*128 + s)*384 + j];
        __syncthreads();
        float acc = 0.f;
        #pragma unroll 4
        for (int d = 0; d < 128; d++)
            acc = fmaf(wk[half_][d], Wq[((size_t)p*256 + h*128 + d)*256 + s], acc);
        wcq[((size_t)p*768 + jr)*128 + s] = __float2half_rn(acc);
        if (s == 0) {
            float c = 0.f;
            for (int d = 0; d < 128; d++) c = fmaf(wk[half_][d], cq[p*256 + h*128 + d], c);
            ckq[p*768 + jr] = c;
        }
        return;
    }
    blk -= 768;
    if (blk < 2) {                     // comb_qb
        int id = blk * 256 + tid;
        int p = id / 256, h = (id % 256) / 128, s = id % 128;
        float acc = 0.f;
        #pragma unroll 4
        for (int d = 0; d < 128; d++)
            acc = fmaf(Wq[((size_t)p*256 + h*128 + d)*256 + s], bk[p*256 + h*128 + d], acc);
        wqb[(p*2 + h)*128 + s] = acc;
        if (s == 0) {
            float c = 0.f;
            for (int d = 0; d < 128; d++)
                c = fmaf(bk[p*256 + h*128 + d], cq[p*256 + h*128 + d], c);
            cqb[p*2 + h] = c;
        }
        return;
    }
    blk -= 2;
    if (blk < 768) {                   // comb_w1
        __shared__ float w1r[256];
        int p = blk / 384, rr = blk % 384;
        int n = rr / 3, jc = rr % 3;
        w1r[tid] = W1[((size_t)p*128 + n)*384 + tid];
        __syncthreads();
        int j = jc * 256 + tid;
        float acc = 0.f;
        #pragma unroll 4
        for (int e = 0; e < 256; e++)
            acc = fmaf(w1r[e], tmpvo[((size_t)p*256 + e)*768 + j], acc);
        wf[((size_t)p*128 + n)*896 + j] = __float2half_rn(acc);
        if (jc == 0 && tid == 0) {
            float c = 0.f;
            for (int e = 0; e < 256; e++) c = fmaf(w1r[e], bvo[p*256 + e], c);
            cvec[p*128 + n] = c;
        }
        return;
    }
    blk -= 768;
    {                                  // misc
        int i = blk * 256 + tid;
        if (i < 32768) {
            int p = i >> 14, r = i & 16383;
            int n = r >> 7, d = r & 127;
            wf[((size_t)p*128 + n)*896 + 768 + d] =
                __float2half_rn(W1[((size_t)p*128 + n)*384 + 256 + d]);
        } else {
            i -= 32768;
            w2[i] = __float2half_rn(W2[i]);
        }
    }
}

// gather emb0 into buf at col 768 (stage 2)
__global__ void gather_emb_kernel(const float* __restrict__ nf,
                                  const float* __restrict__ mem,
                                  const int* __restrict__ idx,
                                  __half* __restrict__ dh, __half* __restrict__ dl, int n)
{
    int r = blockIdx.x;
    if (r >= n) return;
    int t = threadIdx.x;
    size_t s = (size_t)idx[r] * N_D + t;
    float v = nf[s] + mem[s];
    size_t o = (size_t)r * 896 + 768 + t;
    split2h(v, dh[o], dl[o]);
}

// ---------------- fp16 tensor-core GEMM (2-pass, or 1-pass if Al==null) -----
#define GF_RELU 1
#define SMS  40
#define MATB (128 * SMS * 2)
#define STGB (3 * MATB)
#define NSTG 3
#define GSMEM (NSTG * STGB)

__device__ __forceinline__ void cpa16(uint32_t s, const void* g) {
    asm volatile("cp.async.cg.shared.global [%0], [%1], 16;\n" :: "r"(s), "l"(g));
}
__device__ __forceinline__ void ldm4(uint32_t* r, uint32_t a) {
    asm volatile("ldmatrix.sync.aligned.m8n8.x4.shared.b16 {%0,%1,%2,%3},[%4];\n"
                 : "=r"(r[0]), "=r"(r[1]), "=r"(r[2]), "=r"(r[3]) : "r"(a));
}
__device__ __forceinline__ void mmaf16(float* d, const uint32_t* a, uint32_t b0, uint32_t b1) {
    asm volatile("mma.sync.aligned.m16n8k16.row.col.f32.f16.f16.f32 "
                 "{%0,%1,%2,%3},{%4,%5,%6,%7},{%8,%9},{%0,%1,%2,%3};\n"
                 : "+f"(d[0]), "+f"(d[1]), "+f"(d[2]), "+f"(d[3])
                 : "r"(a[0]), "r"(a[1]), "r"(a[2]), "r"(a[3]), "r"(b0), "r"(b1));
}

__device__ __forceinline__ void issue_chunk(uint32_t sw, uint32_t bufofs,
    const __half* Ah, const __half* Al, size_t ga,
    const __half* Wh, size_t gw)
{
    uint32_t s0 = sw + bufofs;
    cpa16(s0,          Ah + ga); cpa16(s0 + 32,          Ah + ga + 16);
    if (Al) { cpa16(s0 + MATB, Al + ga); cpa16(s0 + MATB + 32, Al + ga + 16); }
    cpa16(s0 + 2*MATB, Wh + gw); cpa16(s0 + 2*MATB + 32, Wh + gw + 16);
    asm volatile("cp.async.commit_group;\n");
}

// epilogue: Oh && Ol -> hi/lo split; Oh only -> plain fp16; Cf -> fp32
__global__ __launch_bounds__(256, 2) void mma_gemm(
    const __half* __restrict__ Ah, const __half* __restrict__ Al, int lda,
    const __half* __restrict__ Wh, int ldw,
    int Kd,
    const float* __restrict__ bias, const float* __restrict__ bias2,
    float* __restrict__ Cf, int ldcf,
    __half* __restrict__ Oh, __half* __restrict__ Ol, int ldo,
    const int* __restrict__ zmask, int flags)
{
    extern __shared__ __align__(16) char smem_raw[];
    uint32_t sb = (uint32_t)__cvta_generic_to_shared(smem_raw);
    int tid = threadIdx.x;
    int m0 = blockIdx.y * 128, n0 = blockIdx.x * 128;
    int lane = tid & 31, wid = tid >> 5;
    int wm = wid & 1, wn = wid >> 1;

    float d[4][4][4];
    #pragma unroll
    for (int i = 0; i < 4; i++)
        #pragma unroll
        for (int j = 0; j < 4; j++)
            #pragma unroll
            for (int r = 0; r < 4; r++) d[i][j][r] = 0.f;

    int row = tid >> 1;
    int ce  = (tid & 1) << 3;
    size_t ga0 = (size_t)(m0 + row) * lda + ce;
    size_t gw0 = (size_t)(n0 + row) * ldw + ce;
    uint32_t sw = sb + (uint32_t)(row * SMS + ce) * 2;

    int nch = Kd >> 5;
    issue_chunk(sw, 0, Ah, Al, ga0, Wh, gw0);
    if (nch > 1) issue_chunk(sw, STGB, Ah, Al, ga0 + 32, Wh, gw0 + 32);

    for (int c = 0; c < nch; c++) {
        if (c + 2 < nch) {
            int k0 = (c + 2) << 5;
            issue_chunk(sw, (uint32_t)((c + 2) % NSTG) * STGB, Ah, Al, ga0 + k0, Wh, gw0 + k0);
        }
        int issuedJ = (c + 2 < nch) ? c + 2 : nch - 1;
        int allow = issuedJ - c;
        if (allow >= 2)      asm volatile("cp.async.wait_group 2;\n" ::: "memory");
        else if (allow == 1) asm volatile("cp.async.wait_group 1;\n" ::: "memory");
        else                 asm volatile("cp.async.wait_group 0;\n" ::: "memory");
        __syncthreads();

        uint32_t base = sb + (uint32_t)(c % NSTG) * STGB;
        #pragma unroll
        for (int h = 0; h < 2; h++) {
            uint32_t ah[4][4], bh[2][4];
            int colA = (h << 4) + ((lane >> 4) << 3);
            #pragma unroll
            for (int mi = 0; mi < 4; mi++) {
                int r_ = wm * 64 + mi * 16 + (lane & 15);
                ldm4(ah[mi], base + (uint32_t)(r_ * SMS + colA) * 2);
            }
            #pragma unroll
            for (int nj2 = 0; nj2 < 2; nj2++) {
                int r_ = wn * 32 + nj2 * 16 + (lane & 7) + (((lane >> 3) & 1) << 3);
                ldm4(bh[nj2], base + 2 * MATB + (uint32_t)(r_ * SMS + colA) * 2);
            }
            #pragma unroll
            for (int mi = 0; mi < 4; mi++)
                #pragma unroll
                for (int nj = 0; nj < 4; nj++)
                    mmaf16(d[mi][nj], ah[mi], bh[nj >> 1][nj & 1], bh[nj >> 1][(nj & 1) + 2]);
            if (Al) {
                uint32_t al[4][4];
                #pragma unroll
                for (int mi = 0; mi < 4; mi++) {
                    int r_ = wm * 64 + mi * 16 + (lane & 15);
                    ldm4(al[mi], base + MATB + (uint32_t)(r_ * SMS + colA) * 2);
                }
                #pragma unroll
                for (int mi = 0; mi < 4; mi++)
                    #pragma unroll
                    for (int nj = 0; nj < 4; nj++)
                        mmaf16(d[mi][nj], al[mi], bh[nj >> 1][nj & 1], bh[nj >> 1][(nj & 1) + 2]);
            }
        }
        __syncthreads();
    }

    int gr = lane >> 2, tg = lane & 3;
    #pragma unroll
    for (int mi = 0; mi < 4; mi++) {
        int mb = m0 + wm * 64 + mi * 16 + gr;
        #pragma unroll
        for (int half = 0; half < 2; half++) {
            int m = mb + half * 8;
            bool zm = (zmask != nullptr) && (zmask[m] != 0);
            #pragma unroll
            for (int nj = 0; nj < 4; nj++) {
                int n = n0 + wn * 32 + nj * 8 + tg * 2;
                float v0 = d[mi][nj][half * 2 + 0];
                float v1 = d[mi][nj][half * 2 + 1];
                if (bias) { v0 += bias[n]; v1 += bias[n + 1]; }
                if (bias2) {
                    if (!zm) { v0 += bias2[n]; v1 += bias2[n + 1]; }
                } else if (zm) { v0 = 0.f; v1 = 0.f; }
                if (flags & GF_RELU) { v0 = fmaxf(v0, 0.f); v1 = fmaxf(v1, 0.f); }
                if (Cf) *(float2*)&Cf[(size_t)m * ldcf + n] = make_float2(v0, v1);
                if (Oh) {
                    if (Ol) {
                        __half2 hh, ll;
                        split2h(v0, hh.x, ll.x);
                        split2h(v1, hh.y, ll.y);
                        *(__half2*)&Oh[(size_t)m * ldo + n] = hh;
                        *(__half2*)&Ol[(size_t)m * ldo + n] = ll;
                    } else {
                        *(__half2*)&Oh[(size_t)m * ldo + n] =
                            __floats2half2_rn(v0, v1);
                    }
                }
            }
        }
    }
}

// ------- fused keyv-build + attention: online softmax, float4 gathers -------
// One warp per row m, 4 warps/block. qw read as fp16 (score path; attenuated).
__global__ __launch_bounds__(128, 4) void fused_attn(
    const int* __restrict__ neigh,
    const int* __restrict__ eidx,
    const float* __restrict__ etime,
    const float* __restrict__ ts, int ts_div,
    const float* __restrict__ nf, const float* __restrict__ mem,
    const float* __restrict__ ef,
    const float* __restrict__ dense_neigh,
    const float* __restrict__ tw, const float* __restrict__ tb,
    const __half* __restrict__ QW,
    const __half* __restrict__ bufh, const __half* __restrict__ bufl,
    const float* __restrict__ wqb, const float* __restrict__ cqb,
    __half* __restrict__ ctxh, __half* __restrict__ ctxl,
    int* __restrict__ inv, int M)
{
    __shared__ float s_tw[128], s_tb[128];
    int tid = threadIdx.x;
    s_tw[tid] = tw[tid];
    s_tb[tid] = tb[tid];
    __syncthreads();

    int wl = tid >> 5, lane = tid & 31;
    int m = blockIdx.x * 4 + wl;
    if (m >= M) return;
    const float SC = 0.08838834764831843f;   // 1/sqrt(128)
    int l4 = lane * 4;

    // qb_h = src . wqb_h + cqb_h
    float qb0, qb1;
    {
        size_t sbse = (size_t)m * 896 + 768 + l4;
        float2 fh0 = __half22float2(*(const __half2*)&bufh[sbse]);
        float2 fh1 = __half22float2(*(const __half2*)&bufh[sbse + 2]);
        float2 fl0 = __half22float2(*(const __half2*)&bufl[sbse]);
        float2 fl1 = __half22float2(*(const __half2*)&bufl[sbse + 2]);
        float sx = fh0.x + fl0.x, sy = fh0.y + fl0.y;
        float sz = fh1.x + fl1.x, sw_ = fh1.y + fl1.y;
        float4 w0 = *(const float4*)&wqb[l4];
        float4 w1 = *(const float4*)&wqb[128 + l4];
        qb0 = sx*w0.x + sy*w0.y + sz*w0.z + sw_*w0.w;
        qb1 = sx*w1.x + sy*w1.y + sz*w1.z + sw_*w1.w;
        #pragma unroll
        for (int o = 16; o; o >>= 1) {
            qb0 += __shfl_xor_sync(0xffffffffu, qb0, o);
            qb1 += __shfl_xor_sync(0xffffffffu, qb1, o);
        }
        qb0 += cqb[0]; qb1 += cqb[1];
    }

    float4 qw0[3], qw1[3];
    {
        const __half* qwp = QW + (size_t)m * 768;
        #pragma unroll
        for (int s = 0; s < 3; s++) {
            float2 c0 = __half22float2(*(const __half2*)&qwp[s * 128 + l4]);
            float2 c1 = __half22float2(*(const __half2*)&qwp[s * 128 + l4 + 2]);
            qw0[s] = make_float4(c0.x, c0.y, c1.x, c1.y);
            c0 = __half22float2(*(const __half2*)&qwp[384 + s * 128 + l4]);
            c1 = __half22float2(*(const __half2*)&qwp[384 + s * 128 + l4 + 2]);
            qw1[s] = make_float4(c0.x, c0.y, c1.x, c1.y);
        }
    }

    float tsv = ts[m / ts_div];
    bool allm = true;
    #pragma unroll
    for (int k = 0; k < N_K; k++) allm = allm && (neigh[m * N_K + k] == 0);

    // ---- single pass: online softmax + ctx accumulation
    float mx0 = -3.0e38f, mx1 = -3.0e38f, sm0 = 0.f, sm1 = 0.f;
    float4 a0[3], a1[3];
    #pragma unroll
    for (int s = 0; s < 3; s++) {
        a0[s] = make_float4(0.f, 0.f, 0.f, 0.f);
        a1[s] = make_float4(0.f, 0.f, 0.f, 0.f);
    }

    #pragma unroll
    for (int k = 0; k < N_K; k++) {
        int ndk = neigh[m * N_K + k];
        int edk = eidx [m * N_K + k];
        float4 vn, ve, vc;
        if (dense_neigh) {
            vn = *(const float4*)&dense_neigh[(size_t)(m * N_K + k) * N_D + l4];
        } else {
            float4 a = *(const float4*)&nf [(size_t)ndk * N_D + l4];
            float4 b = *(const float4*)&mem[(size_t)ndk * N_D + l4];
            vn = make_float4(a.x + b.x, a.y + b.y, a.z + b.z, a.w + b.w);
        }
        ve = *(const float4*)&ef[(size_t)edk * N_D + l4];
        float dd = tsv - etime[m * N_K + k];
        vc.x = cosf(__fadd_rn(__fmul_rn(dd, s_tw[l4 + 0]), s_tb[l4 + 0]));
        vc.y = cosf(__fadd_rn(__fmul_rn(dd, s_tw[l4 + 1]), s_tb[l4 + 1]));
        vc.z = cosf(__fadd_rn(__fmul_rn(dd, s_tw[l4 + 2]), s_tb[l4 + 2]));
        vc.w = cosf(__fadd_rn(__fmul_rn(dd, s_tw[l4 + 3]), s_tb[l4 + 3]));

        float p0 = qw0[0].x*vn.x + qw0[0].y*vn.y + qw0[0].z*vn.z + qw0[0].w*vn.w
                 + qw0[1].x*ve.x + qw0[1].y*ve.y + qw0[1].z*ve.z + qw0[1].w*ve.w
                 + qw0[2].x*vc.x + qw0[2].y*vc.y + qw0[2].z*vc.z + qw0[2].w*vc.w;
        float p1 = qw1[0].x*vn.x + qw1[0].y*vn.y + qw1[0].z*vn.z + qw1[0].w*vn.w
                 + qw1[1].x*ve.x + qw1[1].y*ve.y + qw1[1].z*ve.z + qw1[1].w*ve.w
                 + qw1[2].x*vc.x + qw1[2].y*vc.y + qw1[2].z*vc.z + qw1[2].w*vc.w;
        #pragma unroll
        for (int o = 16; o; o >>= 1) {
            p0 += __shfl_xor_sync(0xffffffffu, p0, o);
            p1 += __shfl_xor_sync(0xffffffffu, p1, o);
        }
        bool mk = (ndk == 0) && !(allm && k == 0);
        float sc0 = mk ? -1e9f : (p0 + qb0) * SC;
        float sc1 = mk ? -1e9f : (p1 + qb1) * SC;

        // online update
        float nm0 = fmaxf(mx0, sc0);
        float rs0 = expf(mx0 - nm0);
        float e0  = expf(sc0 - nm0);
        sm0 = sm0 * rs0 + e0;
        mx0 = nm0;
        float nm1 = fmaxf(mx1, sc1);
        float rs1 = expf(mx1 - nm1);
        float e1  = expf(sc1 - nm1);
        sm1 = sm1 * rs1 + e1;
        mx1 = nm1;
        a0[0].x = fmaf(e0, vn.x, a0[0].x * rs0); a0[0].y = fmaf(e0, vn.y, a0[0].y * rs0);
        a0[0].z = fmaf(e0, vn.z, a0[0].z * rs0); a0[0].w = fmaf(e0, vn.w, a0[0].w * rs0);
        a0[1].x = fmaf(e0, ve.x, a0[1].x * rs0); a0[1].y = fmaf(e0, ve.y, a0[1].y * rs0);
        a0[1].z = fmaf(e0, ve.z, a0[1].z * rs0); a0[1].w = fmaf(e0, ve.w, a0[1].w * rs0);
        a0[2].x = fmaf(e0, vc.x, a0[2].x * rs0); a0[2].y = fmaf(e0, vc.y, a0[2].y * rs0);
        a0[2].z = fmaf(e0, vc.z, a0[2].z * rs0); a0[2].w = fmaf(e0, vc.w, a0[2].w * rs0);
        a1[0].x = fmaf(e1, vn.x, a1[0].x * rs1); a1[0].y = fmaf(e1, vn.y, a1[0].y * rs1);
        a1[0].z = fmaf(e1, vn.z, a1[0].z * rs1); a1[0].w = fmaf(e1, vn.w, a1[0].w * rs1);
        a1[1].x = fmaf(e1, ve.x, a1[1].x * rs1); a1[1].y = fmaf(e1, ve.y, a1[1].y * rs1);
        a1[1].z = fmaf(e1, ve.z, a1[1].z * rs1); a1[1].w = fmaf(e1, ve.w, a1[1].w * rs1);
        a1[2].x = fmaf(e1, vc.x, a1[2].x * rs1); a1[2].y = fmaf(e1, vc.y, a1[2].y * rs1);
        a1[2].z = fmaf(e1, vc.z, a1[2].z * rs1); a1[2].w = fmaf(e1, vc.w, a1[2].w * rs1);
    }

    float zf = allm ? 0.f : 1.f;       // fold invalid-row zeroing into ctx
    float r0 = zf / sm0, r1 = zf / sm1;

    size_t ob = (size_t)m * 896;
    #pragma unroll
    for (int s = 0; s < 3; s++) {
        __half2 hh0, ll0, hh1, ll1;
        split2h(a0[s].x * r0, hh0.x, ll0.x); split2h(a0[s].y * r0, hh0.y, ll0.y);
        split2h(a0[s].z * r0, hh1.x, ll1.x); split2h(a0[s].w * r0, hh1.y, ll1.y);
        size_t o0 = ob + s * 128 + l4;
        *(__half2*)&ctxh[o0]     = hh0;  *(__half2*)&ctxl[o0]     = ll0;
        *(__half2*)&ctxh[o0 + 2] = hh1;  *(__half2*)&ctxl[o0 + 2] = ll1;
        split2h(a1[s].x * r1, hh0.x, ll0.x); split2h(a1[s].y * r1, hh0.y, ll0.y);
        split2h(a1[s].z * r1, hh1.x, ll1.x); split2h(a1[s].w * r1, hh1.y, ll1.y);
        size_t o1 = ob + 384 + s * 128 + l4;
        *(__half2*)&ctxh[o1]     = hh0;  *(__half2*)&ctxl[o1]     = ll0;
        *(__half2*)&ctxh[o1 + 2] = hh1;  *(__half2*)&ctxl[o1 + 2] = ll1;
    }
    if (lane == 0) inv[m] = allm ? 1 : 0;
}

// ---------------- one temporal attention layer ------------------------------
struct Ptrs {
    __half *bufh, *bufl, *hh, *hl, *QW;
    int* inv;
    __half *wcq, *wf, *w2;
    float *cq, *ckq, *cvec, *wqb, *cqb;
};

static void run_layer(const Ptrs& P, int p, int M,
                      const int* neigh, const float* dense_neigh,
                      const int* eidx, const float* etime,
                      const float* ts, int ts_div,
                      const float* nf, const float* mem, const float* ef,
                      const float* tw, const float* tb,
                      const float* b1, const float* b2,
                      float* outCf, __half* outOh, __half* outOl, int out_ldo)
{
    // QW = src(hi) @ Wcombq^T + ckq  -> fp16 (score path; 1-pass A)
    mma_gemm<<<dim3(6, M/128), 256, GSMEM>>>(
        P.bufh + 768, nullptr, 896,
        P.wcq + (size_t)p*768*128, 128, 128,
        P.ckq + p*768, nullptr, nullptr, 0, P.QW, nullptr, 768, nullptr, 0);
    // fused keyv-build + attention -> ctx into buf cols 0..767
    fused_attn<<<(M + 3) / 4, 128>>>(neigh, eidx, etime, ts, ts_div,
                                     nf, mem, ef, dense_neigh, tw, tb,
                                     P.QW, P.bufh, P.bufl,
                                     P.wqb + p*256, P.cqb + p*2,
                                     P.bufh, P.bufl, P.inv, M);
    // h = relu(buf @ wf^T + b1 + (valid ? cvec : 0))
    mma_gemm<<<dim3(1, M/128), 256, GSMEM>>>(
        P.bufh, P.bufl, 896,
        P.wf + (size_t)p*128*896, 896, 896,
        b1 + p*128, P.cvec + p*128, nullptr, 0, P.hh, P.hl, 128, P.inv, GF_RELU);
    // out = h @ W2^T + b2
    mma_gemm<<<dim3(1, M/128), 256, GSMEM>>>(
        P.hh, P.hl, 128,
        P.w2 + (size_t)p*16384, 128, 128,
        b2 + p*128, nullptr, outCf, 128, outOh, outOl, out_ldo, nullptr, 0);
}

// ---------------- entry -----------------------------------------------------
extern "C" void kernel_launch(void* const* d_in, const int* in_sizes, int n_in,
                              void* d_out, int out_size)
{
    const float* node_feat   = (const float*)d_in[0];
    const float* memory      = (const float*)d_in[1];
    const float* edge_feat   = (const float*)d_in[2];
    const float* time_w      = (const float*)d_in[3];
    const float* time_b      = (const float*)d_in[4];
    const float* Wq          = (const float*)d_in[5];
    const float* bq          = (const float*)d_in[6];
    const float* Wk          = (const float*)d_in[7];
    const float* bk          = (const float*)d_in[8];
    const float* Wv          = (const float*)d_in[9];
    const float* bv          = (const float*)d_in[10];
    const float* Wo          = (const float*)d_in[11];
    const float* bo          = (const float*)d_in[12];
    const float* W1          = (const float*)d_in[13];
    const float* b1          = (const float*)d_in[14];
    const float* W2          = (const float*)d_in[15];
    const float* b2          = (const float*)d_in[16];
    const float* timestamps  = (const float*)d_in[17];
    const int*   src_nodes   = (const int*)d_in[18];
    const int*   neighbors1  = (const int*)d_in[19];
    const int*   edge_idx1   = (const int*)d_in[20];
    const float* edge_times1 = (const float*)d_in[21];
    const int*   neighbors2  = (const int*)d_in[22];
    const int*   edge_idx2   = (const int*)d_in[23];
    const float* edge_times2 = (const float*)d_in[24];

    cudaFuncSetAttribute(mma_gemm, cudaFuncAttributeMaxDynamicSharedMemorySize, GSMEM);

    Ptrs P; float *NL1, *tmpvo, *bvo;
    cudaGetSymbolAddress((void**)&P.QW,   g_QW);
    cudaGetSymbolAddress((void**)&P.bufh, g_buf_h);
    cudaGetSymbolAddress((void**)&P.bufl, g_buf_l);
    cudaGetSymbolAddress((void**)&P.hh,   g_h_h);
    cudaGetSymbolAddress((void**)&P.hl,   g_h_l);
    cudaGetSymbolAddress((void**)&NL1,    g_NL1);
    cudaGetSymbolAddress((void**)&P.inv,  g_inv);
    cudaGetSymbolAddress((void**)&P.cq,   g_cq);
    cudaGetSymbolAddress((void**)&P.wcq,  g_wcq);
    cudaGetSymbolAddress((void**)&P.ckq,  g_ckq);
    cudaGetSymbolAddress((void**)&tmpvo,  g_tmpvo);
    cudaGetSymbolAddress((void**)&bvo,    g_bvo);
    cudaGetSymbolAddress((void**)&P.wf,   g_wf);
    cudaGetSymbolAddress((void**)&P.cvec, g_cvec);
    cudaGetSymbolAddress((void**)&P.w2,   g_w2);
    cudaGetSymbolAddress((void**)&P.wqb,  g_wqb);
    cudaGetSymbolAddress((void**)&P.cqb,  g_cqb);

    // launch 1: const_q | comb_vo | stage-1 gather
    prep1_kernel<<<2 + 1536 + M_HOP2/2, 256>>>(
        Wq, bq, time_b, Wo, Wv, bo, bv,
        node_feat, memory, neighbors1,
        P.cq, tmpvo, bvo, P.bufh, P.bufl);
    // launch 2: comb_q | comb_qb | comb_w1 | misc
    prep2_kernel<<<768 + 2 + 768 + 256, 256>>>(
        Wk, Wq, P.cq, bk, W1, W2, tmpvo, bvo,
        P.wcq, P.ckq, P.wqb, P.cqb, P.wf, P.cvec, P.w2);

    // stage 1: layer-1 embedding of flattened first-hop neighbors (p0)
    run_layer(P, 0, M_HOP2, neighbors2, nullptr, edge_idx2, edge_times2,
              timestamps, N_K, node_feat, memory, edge_feat, time_w, time_b,
              b1, b2, NL1, nullptr, nullptr, 0);

    // stage 2: layer-1 embedding of src nodes (p0); SL1 -> buf col 768
    gather_emb_kernel<<<N_B, 128>>>(node_feat, memory, src_nodes, P.bufh, P.bufl, N_B);
    run_layer(P, 0, N_B, neighbors1, nullptr, edge_idx1, edge_times1,
              timestamps, 1, node_feat, memory, edge_feat, time_w, time_b,
              b1, b2, nullptr, P.bufh + 768, P.bufl + 768, 896);

    // stage 3: layer-2 aggregation (p1), neighbor feats = NL1
    run_layer(P, 1, N_B, neighbors1, NL1, edge_idx1, edge_times1,
              timestamps, 1, node_feat, memory, edge_feat, time_w, time_b,
              b1, b2, (float*)d_out, nullptr, nullptr, 0);
}

// round 16
// speedup vs baseline: 1.4973x; 1.1190x over previous
#include <cuda_runtime.h>
#include <cuda_fp16.h>
#include <math.h>
#include <stdint.h>

#define N_B   8192
#define N_K   10
#define N_D   128
#define M_HOP2 (N_B * N_K)          // 81920

// ---------------- scratch (static __device__ globals; no allocs) ------------
__device__ __half g_QW   [(size_t)M_HOP2 * 768];     // fp16: src @ Wcombq^T + ckq
__device__ __half g_buf_h[(size_t)M_HOP2 * 896];     // [ctx(768) || src(128)] hi
__device__ __half g_buf_l[(size_t)M_HOP2 * 896];     // lo
__device__ __half g_h_h  [(size_t)M_HOP2 * N_D];
__device__ __half g_h_l  [(size_t)M_HOP2 * N_D];
__device__ float  g_NL1  [(size_t)M_HOP2 * N_D];
__device__ int    g_inv  [M_HOP2];
__device__ float  g_cq   [2 * 256];
// combined weights
__device__ __half g_wcq [2*768*128];                 // Wk_h^T @ Wq1_h
__device__ float  g_ckq [2*768];                     // Wk_h^T @ cq_h
__device__ float  g_tmpvo[2*256*768];                // Wo @ Wv_blockdiag (fp32 temp)
__device__ float  g_bvo [2*256];                     // Wo bv + bo
__device__ __half g_wf  [2*128*896];                 // [W1a@Wvo || W1b] fp16
__device__ float  g_cvec[2*128];                     // W1a @ bvo
__device__ __half g_w2  [2*128*128];
__device__ float  g_wqb [2*2*128];                   // Wq1_h^T bk_h
__device__ float  g_cqb [2*2];                       // bk_h . cq_h

// ---------------- helpers ---------------------------------------------------
__device__ __forceinline__ void split2h(float v, __half& h, __half& l) {
    h = __float2half_rn(v);
    l = __float2half_rn(v - __half2float(h));
}

// ================= prep 1: const_q | comb_vo | stage-1 gather ================
__global__ __launch_bounds__(256) void prep1_kernel(
    const float* __restrict__ Wq, const float* __restrict__ bq,
    const float* __restrict__ tb,
    const float* __restrict__ Wo, const float* __restrict__ Wv,
    const float* __restrict__ bo, const float* __restrict__ bv,
    const float* __restrict__ nf, const float* __restrict__ mem,
    const int* __restrict__ idx,
    float* __restrict__ cq, float* __restrict__ tmpvo, float* __restrict__ bvo,
    __half* __restrict__ dh, __half* __restrict__ dl)
{
    int blk = blockIdx.x, tid = threadIdx.x;
    if (blk < 2) {                     // const_q
        __shared__ float ct[128];
        int p = blk, j = tid;
        if (j < 128) ct[j] = cosf(tb[j]);
        __syncthreads();
        const float* W = Wq + (size_t)p * 65536;
        float s = bq[p * 256 + j];
        #pragma unroll 4
        for (int t = 0; t < 128; t++) s = fmaf(ct[t], W[(size_t)j * 256 + 128 + t], s);
        cq[p * 256 + j] = s;
        return;
    }
    blk -= 2;
    if (blk < 1536) {                  // comb_vo
        int p = blk / 768, rr = blk % 768;
        int i = rr / 3, jc = rr % 3;
        int j = jc * 256 + tid;
        int h = j / 384, jp = j % 384;
        float acc = 0.f;
        #pragma unroll 4
        for (int d = 0; d < 128; d++)
            acc = fmaf(Wo[((size_t)p*256 + i)*256 + h*128 + d],
                       Wv[((size_t)p*256 + h*128 + d)*384 + jp], acc);
        tmpvo[((size_t)p*256 + i)*768 + j] = acc;
        if (jc == 0 && tid == 0) {
            float c = bo[p*256 + i];
            for (int e = 0; e < 256; e++)
                c = fmaf(Wo[((size_t)p*256 + i)*256 + e], bv[p*256 + e], c);
            bvo[p*256 + i] = c;
        }
        return;
    }
    blk -= 1536;                       // stage-1 gather: 2 rows/block
    int r = blk * 2 + (tid >> 7);
    int t = tid & 127;
    size_t s = (size_t)idx[r] * N_D + t;
    float v = nf[s] + mem[s];
    size_t o = (size_t)r * 896 + 768 + t;
    split2h(v, dh[o], dl[o]);
}

// ================= prep 2: comb_q | comb_qb | comb_w1 | misc =================
__global__ __launch_bounds__(256) void prep2_kernel(
    const float* __restrict__ Wk, const float* __restrict__ Wq,
    const float* __restrict__ cq, const float* __restrict__ bk,
    const float* __restrict__ W1, const float* __restrict__ W2,
    const float* __restrict__ tmpvo, const float* __restrict__ bvo,
    __half* __restrict__ wcq, float* __restrict__ ckq,
    float* __restrict__ wqb, float* __restrict__ cqb,
    __half* __restrict__ wf, float* __restrict__ cvec, __half* __restrict__ w2)
{
    int blk = blockIdx.x, tid = threadIdx.x;
    if (blk < 768) {                   // comb_q: 2 jr rows per block
        __shared__ float wk[2][128];
        int p = blk / 384;
        int half_ = tid >> 7, s = tid & 127;
        int jr = (blk % 384) * 2 + half_;
        int h = jr / 384, j = jr % 384;
        wk[half_][s] = Wk[((size_t)p*256 + h*128 + s)*384 + j];
        __syncthreads();
        float acc = 0.f;
        #pragma unroll 4
        for (int d = 0; d < 128; d++)
            acc = fmaf(wk[half_][d], Wq[((size_t)p*256 + h*128 + d)*256 + s], acc);
        wcq[((size_t)p*768 + jr)*128 + s] = __float2half_rn(acc);
        if (s == 0) {
            float c = 0.f;
            for (int d = 0; d < 128; d++) c = fmaf(wk[half_][d], cq[p*256 + h*128 + d], c);
            ckq[p*768 + jr] = c;
        }
        return;
    }
    blk -= 768;
    if (blk < 2) {                     // comb_qb
        int id = blk * 256 + tid;
        int p = id / 256, h = (id % 256) / 128, s = id % 128;
        float acc = 0.f;
        #pragma unroll 4
        for (int d = 0; d < 128; d++)
            acc = fmaf(Wq[((size_t)p*256 + h*128 + d)*256 + s], bk[p*256 + h*128 + d], acc);
        wqb[(p*2 + h)*128 + s] = acc;
        if (s == 0) {
            float c = 0.f;
            for (int d = 0; d < 128; d++)
                c = fmaf(bk[p*256 + h*128 + d], cq[p*256 + h*128 + d], c);
            cqb[p*2 + h] = c;
        }
        return;
    }
    blk -= 2;
    if (blk < 768) {                   // comb_w1
        __shared__ float w1r[256];
        int p = blk / 384, rr = blk % 384;
        int n = rr / 3, jc = rr % 3;
        w1r[tid] = W1[((size_t)p*128 + n)*384 + tid];
        __syncthreads();
        int j = jc * 256 + tid;
        float acc = 0.f;
        #pragma unroll 4
        for (int e = 0; e < 256; e++)
            acc = fmaf(w1r[e], tmpvo[((size_t)p*256 + e)*768 + j], acc);
        wf[((size_t)p*128 + n)*896 + j] = __float2half_rn(acc);
        if (jc == 0 && tid == 0) {
            float c = 0.f;
            for (int e = 0; e < 256; e++) c = fmaf(w1r[e], bvo[p*256 + e], c);
            cvec[p*128 + n] = c;
        }
        return;
    }
    blk -= 768;
    {                                  // misc
        int i = blk * 256 + tid;
        if (i < 32768) {
            int p = i >> 14, r = i & 16383;
            int n = r >> 7, d = r & 127;
            wf[((size_t)p*128 + n)*896 + 768 + d] =
                __float2half_rn(W1[((size_t)p*128 + n)*384 + 256 + d]);
        } else {
            i -= 32768;
            w2[i] = __float2half_rn(W2[i]);
        }
    }
}

// gather emb0 into buf at col 768 (stage 2)
__global__ void gather_emb_kernel(const float* __restrict__ nf,
                                  const float* __restrict__ mem,
                                  const int* __restrict__ idx,
                                  __half* __restrict__ dh, __half* __restrict__ dl, int n)
{
    int r = blockIdx.x;
    if (r >= n) return;
    int t = threadIdx.x;
    size_t s = (size_t)idx[r] * N_D + t;
    float v = nf[s] + mem[s];
    size_t o = (size_t)r * 896 + 768 + t;
    split2h(v, dh[o], dl[o]);
}

// ---------------- fp16 tensor-core GEMM (2-pass, or 1-pass if Al==null) -----
#define GF_RELU 1
#define SMS  40
#define MATB (128 * SMS * 2)
#define STGB (3 * MATB)
#define NSTG 3
#define GSMEM (NSTG * STGB)

__device__ __forceinline__ void cpa16(uint32_t s, const void* g) {
    asm volatile("cp.async.cg.shared.global [%0], [%1], 16;\n" :: "r"(s), "l"(g));
}
__device__ __forceinline__ void ldm4(uint32_t* r, uint32_t a) {
    asm volatile("ldmatrix.sync.aligned.m8n8.x4.shared.b16 {%0,%1,%2,%3},[%4];\n"
                 : "=r"(r[0]), "=r"(r[1]), "=r"(r[2]), "=r"(r[3]) : "r"(a));
}
__device__ __forceinline__ void mmaf16(float* d, const uint32_t* a, uint32_t b0, uint32_t b1) {
    asm volatile("mma.sync.aligned.m16n8k16.row.col.f32.f16.f16.f32 "
                 "{%0,%1,%2,%3},{%4,%5,%6,%7},{%8,%9},{%0,%1,%2,%3};\n"
                 : "+f"(d[0]), "+f"(d[1]), "+f"(d[2]), "+f"(d[3])
                 : "r"(a[0]), "r"(a[1]), "r"(a[2]), "r"(a[3]), "r"(b0), "r"(b1));
}

__device__ __forceinline__ void issue_chunk(uint32_t sw, uint32_t bufofs,
    const __half* Ah, const __half* Al, size_t ga,
    const __half* Wh, size_t gw)
{
    uint32_t s0 = sw + bufofs;
    cpa16(s0,          Ah + ga); cpa16(s0 + 32,          Ah + ga + 16);
    if (Al) { cpa16(s0 + MATB, Al + ga); cpa16(s0 + MATB + 32, Al + ga + 16); }
    cpa16(s0 + 2*MATB, Wh + gw); cpa16(s0 + 2*MATB + 32, Wh + gw + 16);
    asm volatile("cp.async.commit_group;\n");
}

// epilogue: Oh && Ol -> hi/lo split; Oh only -> plain fp16; Cf -> fp32
__global__ __launch_bounds__(256, 2) void mma_gemm(
    const __half* __restrict__ Ah, const __half* __restrict__ Al, int lda,
    const __half* __restrict__ Wh, int ldw,
    int Kd,
    const float* __restrict__ bias, const float* __restrict__ bias2,
    float* __restrict__ Cf, int ldcf,
    __half* __restrict__ Oh, __half* __restrict__ Ol, int ldo,
    const int* __restrict__ zmask, int flags)
{
    extern __shared__ __align__(16) char smem_raw[];
    uint32_t sb = (uint32_t)__cvta_generic_to_shared(smem_raw);
    int tid = threadIdx.x;
    int m0 = blockIdx.y * 128, n0 = blockIdx.x * 128;
    int lane = tid & 31, wid = tid >> 5;
    int wm = wid & 1, wn = wid >> 1;

    float d[4][4][4];
    #pragma unroll
    for (int i = 0; i < 4; i++)
        #pragma unroll
        for (int j = 0; j < 4; j++)
            #pragma unroll
            for (int r = 0; r < 4; r++) d[i][j][r] = 0.f;

    int row = tid >> 1;
    int ce  = (tid & 1) << 3;
    size_t ga0 = (size_t)(m0 + row) * lda + ce;
    size_t gw0 = (size_t)(n0 + row) * ldw + ce;
    uint32_t sw = sb + (uint32_t)(row * SMS + ce) * 2;

    int nch = Kd >> 5;
    issue_chunk(sw, 0, Ah, Al, ga0, Wh, gw0);
    if (nch > 1) issue_chunk(sw, STGB, Ah, Al, ga0 + 32, Wh, gw0 + 32);

    for (int c = 0; c < nch; c++) {
        if (c + 2 < nch) {
            int k0 = (c + 2) << 5;
            issue_chunk(sw, (uint32_t)((c + 2) % NSTG) * STGB, Ah, Al, ga0 + k0, Wh, gw0 + k0);
        }
        int issuedJ = (c + 2 < nch) ? c + 2 : nch - 1;
        int allow = issuedJ - c;
        if (allow >= 2)      asm volatile("cp.async.wait_group 2;\n" ::: "memory");
        else if (allow == 1) asm volatile("cp.async.wait_group 1;\n" ::: "memory");
        else                 asm volatile("cp.async.wait_group 0;\n" ::: "memory");
        __syncthreads();

        uint32_t base = sb + (uint32_t)(c % NSTG) * STGB;
        #pragma unroll
        for (int h = 0; h < 2; h++) {
            uint32_t ah[4][4], bh[2][4];
            int colA = (h << 4) + ((lane >> 4) << 3);
            #pragma unroll
            for (int mi = 0; mi < 4; mi++) {
                int r_ = wm * 64 + mi * 16 + (lane & 15);
                ldm4(ah[mi], base + (uint32_t)(r_ * SMS + colA) * 2);
            }
            #pragma unroll
            for (int nj2 = 0; nj2 < 2; nj2++) {
                int r_ = wn * 32 + nj2 * 16 + (lane & 7) + (((lane >> 3) & 1) << 3);
                ldm4(bh[nj2], base + 2 * MATB + (uint32_t)(r_ * SMS + colA) * 2);
            }
            #pragma unroll
            for (int mi = 0; mi < 4; mi++)
                #pragma unroll
                for (int nj = 0; nj < 4; nj++)
                    mmaf16(d[mi][nj], ah[mi], bh[nj >> 1][nj & 1], bh[nj >> 1][(nj & 1) + 2]);
            if (Al) {
                uint32_t al[4][4];
                #pragma unroll
                for (int mi = 0; mi < 4; mi++) {
                    int r_ = wm * 64 + mi * 16 + (lane & 15);
                    ldm4(al[mi], base + MATB + (uint32_t)(r_ * SMS + colA) * 2);
                }
                #pragma unroll
                for (int mi = 0; mi < 4; mi++)
                    #pragma unroll
                    for (int nj = 0; nj < 4; nj++)
                        mmaf16(d[mi][nj], al[mi], bh[nj >> 1][nj & 1], bh[nj >> 1][(nj & 1) + 2]);
            }
        }
        __syncthreads();
    }

    int gr = lane >> 2, tg = lane & 3;
    #pragma unroll
    for (int mi = 0; mi < 4; mi++) {
        int mb = m0 + wm * 64 + mi * 16 + gr;
        #pragma unroll
        for (int half = 0; half < 2; half++) {
            int m = mb + half * 8;
            bool zm = (zmask != nullptr) && (zmask[m] != 0);
            #pragma unroll
            for (int nj = 0; nj < 4; nj++) {
                int n = n0 + wn * 32 + nj * 8 + tg * 2;
                float v0 = d[mi][nj][half * 2 + 0];
                float v1 = d[mi][nj][half * 2 + 1];
                if (bias) { v0 += bias[n]; v1 += bias[n + 1]; }
                if (bias2) {
                    if (!zm) { v0 += bias2[n]; v1 += bias2[n + 1]; }
                } else if (zm) { v0 = 0.f; v1 = 0.f; }
                if (flags & GF_RELU) { v0 = fmaxf(v0, 0.f); v1 = fmaxf(v1, 0.f); }
                if (Cf) *(float2*)&Cf[(size_t)m * ldcf + n] = make_float2(v0, v1);
                if (Oh) {
                    if (Ol) {
                        __half2 hh, ll;
                        split2h(v0, hh.x, ll.x);
                        split2h(v1, hh.y, ll.y);
                        *(__half2*)&Oh[(size_t)m * ldo + n] = hh;
                        *(__half2*)&Ol[(size_t)m * ldo + n] = ll;
                    } else {
                        *(__half2*)&Oh[(size_t)m * ldo + n] =
                            __floats2half2_rn(v0, v1);
                    }
                }
            }
        }
    }
}

// ------- fused keyv-build + attention: online softmax, float4 gathers -------
// One warp per row m, 4 warps/block. qw fp16; __expf in online update.
__global__ __launch_bounds__(128, 4) void fused_attn(
    const int* __restrict__ neigh,
    const int* __restrict__ eidx,
    const float* __restrict__ etime,
    const float* __restrict__ ts, int ts_div,
    const float* __restrict__ nf, const float* __restrict__ mem,
    const float* __restrict__ ef,
    const float* __restrict__ dense_neigh,
    const float* __restrict__ tw, const float* __restrict__ tb,
    const __half* __restrict__ QW,
    const __half* __restrict__ bufh, const __half* __restrict__ bufl,
    const float* __restrict__ wqb, const float* __restrict__ cqb,
    __half* __restrict__ ctxh, __half* __restrict__ ctxl,
    int* __restrict__ inv, int M)
{
    __shared__ float s_tw[128], s_tb[128];
    int tid = threadIdx.x;
    s_tw[tid] = tw[tid];
    s_tb[tid] = tb[tid];
    __syncthreads();

    int wl = tid >> 5, lane = tid & 31;
    int m = blockIdx.x * 4 + wl;
    if (m >= M) return;
    const float SC = 0.08838834764831843f;   // 1/sqrt(128)
    int l4 = lane * 4;

    // qb_h = src . wqb_h + cqb_h
    float qb0, qb1;
    {
        size_t sbse = (size_t)m * 896 + 768 + l4;
        float2 fh0 = __half22float2(*(const __half2*)&bufh[sbse]);
        float2 fh1 = __half22float2(*(const __half2*)&bufh[sbse + 2]);
        float2 fl0 = __half22float2(*(const __half2*)&bufl[sbse]);
        float2 fl1 = __half22float2(*(const __half2*)&bufl[sbse + 2]);
        float sx = fh0.x + fl0.x, sy = fh0.y + fl0.y;
        float sz = fh1.x + fl1.x, sw_ = fh1.y + fl1.y;
        float4 w0 = *(const float4*)&wqb[l4];
        float4 w1 = *(const float4*)&wqb[128 + l4];
        qb0 = sx*w0.x + sy*w0.y + sz*w0.z + sw_*w0.w;
        qb1 = sx*w1.x + sy*w1.y + sz*w1.z + sw_*w1.w;
        #pragma unroll
        for (int o = 16; o; o >>= 1) {
            qb0 += __shfl_xor_sync(0xffffffffu, qb0, o);
            qb1 += __shfl_xor_sync(0xffffffffu, qb1, o);
        }
        qb0 += cqb[0]; qb1 += cqb[1];
    }

    float4 qw0[3], qw1[3];
    {
        const __half* qwp = QW + (size_t)m * 768;
        #pragma unroll
        for (int s = 0; s < 3; s++) {
            float2 c0 = __half22float2(*(const __half2*)&qwp[s * 128 + l4]);
            float2 c1 = __half22float2(*(const __half2*)&qwp[s * 128 + l4 + 2]);
            qw0[s] = make_float4(c0.x, c0.y, c1.x, c1.y);
            c0 = __half22float2(*(const __half2*)&qwp[384 + s * 128 + l4]);
            c1 = __half22float2(*(const __half2*)&qwp[384 + s * 128 + l4 + 2]);
            qw1[s] = make_float4(c0.x, c0.y, c1.x, c1.y);
        }
    }

    float tsv = ts[m / ts_div];
    bool allm = true;
    #pragma unroll
    for (int k = 0; k < N_K; k++) allm = allm && (neigh[m * N_K + k] == 0);

    // ---- single pass: online softmax + ctx accumulation
    float mx0 = -3.0e38f, mx1 = -3.0e38f, sm0 = 0.f, sm1 = 0.f;
    float4 a0[3], a1[3];
    #pragma unroll
    for (int s = 0; s < 3; s++) {
        a0[s] = make_float4(0.f, 0.f, 0.f, 0.f);
        a1[s] = make_float4(0.f, 0.f, 0.f, 0.f);
    }

    #pragma unroll
    for (int k = 0; k < N_K; k++) {
        int ndk = neigh[m * N_K + k];
        int edk = eidx [m * N_K + k];
        float4 vn, ve, vc;
        if (dense_neigh) {
            vn = *(const float4*)&dense_neigh[(size_t)(m * N_K + k) * N_D + l4];
        } else {
            float4 a = *(const float4*)&nf [(size_t)ndk * N_D + l4];
            float4 b = *(const float4*)&mem[(size_t)ndk * N_D + l4];
            vn = make_float4(a.x + b.x, a.y + b.y, a.z + b.z, a.w + b.w);
        }
        ve = *(const float4*)&ef[(size_t)edk * N_D + l4];
        float dd = tsv - etime[m * N_K + k];
        vc.x = cosf(__fadd_rn(__fmul_rn(dd, s_tw[l4 + 0]), s_tb[l4 + 0]));
        vc.y = cosf(__fadd_rn(__fmul_rn(dd, s_tw[l4 + 1]), s_tb[l4 + 1]));
        vc.z = cosf(__fadd_rn(__fmul_rn(dd, s_tw[l4 + 2]), s_tb[l4 + 2]));
        vc.w = cosf(__fadd_rn(__fmul_rn(dd, s_tw[l4 + 3]), s_tb[l4 + 3]));

        float p0 = qw0[0].x*vn.x + qw0[0].y*vn.y + qw0[0].z*vn.z + qw0[0].w*vn.w
                 + qw0[1].x*ve.x + qw0[1].y*ve.y + qw0[1].z*ve.z + qw0[1].w*ve.w
                 + qw0[2].x*vc.x + qw0[2].y*vc.y + qw0[2].z*vc.z + qw0[2].w*vc.w;
        float p1 = qw1[0].x*vn.x + qw1[0].y*vn.y + qw1[0].z*vn.z + qw1[0].w*vn.w
                 + qw1[1].x*ve.x + qw1[1].y*ve.y + qw1[1].z*ve.z + qw1[1].w*ve.w
                 + qw1[2].x*vc.x + qw1[2].y*vc.y + qw1[2].z*vc.z + qw1[2].w*vc.w;
        #pragma unroll
        for (int o = 16; o; o >>= 1) {
            p0 += __shfl_xor_sync(0xffffffffu, p0, o);
            p1 += __shfl_xor_sync(0xffffffffu, p1, o);
        }
        bool mk = (ndk == 0) && !(allm && k == 0);
        float sc0 = mk ? -1e9f : (p0 + qb0) * SC;
        float sc1 = mk ? -1e9f : (p1 + qb1) * SC;

        // online update (fast exp: score-path only, softmax-attenuated)
        float nm0 = fmaxf(mx0, sc0);
        float rs0 = __expf(mx0 - nm0);
        float e0  = __expf(sc0 - nm0);
        sm0 = sm0 * rs0 + e0;
        mx0 = nm0;
        float nm1 = fmaxf(mx1, sc1);
        float rs1 = __expf(mx1 - nm1);
        float e1  = __expf(sc1 - nm1);
        sm1 = sm1 * rs1 + e1;
        mx1 = nm1;
        a0[0].x = fmaf(e0, vn.x, a0[0].x * rs0); a0[0].y = fmaf(e0, vn.y, a0[0].y * rs0);
        a0[0].z = fmaf(e0, vn.z, a0[0].z * rs0); a0[0].w = fmaf(e0, vn.w, a0[0].w * rs0);
        a0[1].x = fmaf(e0, ve.x, a0[1].x * rs0); a0[1].y = fmaf(e0, ve.y, a0[1].y * rs0);
        a0[1].z = fmaf(e0, ve.z, a0[1].z * rs0); a0[1].w = fmaf(e0, ve.w, a0[1].w * rs0);
        a0[2].x = fmaf(e0, vc.x, a0[2].x * rs0); a0[2].y = fmaf(e0, vc.y, a0[2].y * rs0);
        a0[2].z = fmaf(e0, vc.z, a0[2].z * rs0); a0[2].w = fmaf(e0, vc.w, a0[2].w * rs0);
        a1[0].x = fmaf(e1, vn.x, a1[0].x * rs1); a1[0].y = fmaf(e1, vn.y, a1[0].y * rs1);
        a1[0].z = fmaf(e1, vn.z, a1[0].z * rs1); a1[0].w = fmaf(e1, vn.w, a1[0].w * rs1);
        a1[1].x = fmaf(e1, ve.x, a1[1].x * rs1); a1[1].y = fmaf(e1, ve.y, a1[1].y * rs1);
        a1[1].z = fmaf(e1, ve.z, a1[1].z * rs1); a1[1].w = fmaf(e1, ve.w, a1[1].w * rs1);
        a1[2].x = fmaf(e1, vc.x, a1[2].x * rs1); a1[2].y = fmaf(e1, vc.y, a1[2].y * rs1);
        a1[2].z = fmaf(e1, vc.z, a1[2].z * rs1); a1[2].w = fmaf(e1, vc.w, a1[2].w * rs1);
    }

    float zf = allm ? 0.f : 1.f;       // fold invalid-row zeroing into ctx
    float r0 = zf / sm0, r1 = zf / sm1;

    size_t ob = (size_t)m * 896;
    #pragma unroll
    for (int s = 0; s < 3; s++) {
        __half2 hh0, ll0, hh1, ll1;
        split2h(a0[s].x * r0, hh0.x, ll0.x); split2h(a0[s].y * r0, hh0.y, ll0.y);
        split2h(a0[s].z * r0, hh1.x, ll1.x); split2h(a0[s].w * r0, hh1.y, ll1.y);
        size_t o0 = ob + s * 128 + l4;
        *(__half2*)&ctxh[o0]     = hh0;  *(__half2*)&ctxl[o0]     = ll0;
        *(__half2*)&ctxh[o0 + 2] = hh1;  *(__half2*)&ctxl[o0 + 2] = ll1;
        split2h(a1[s].x * r1, hh0.x, ll0.x); split2h(a1[s].y * r1, hh0.y, ll0.y);
        split2h(a1[s].z * r1, hh1.x, ll1.x); split2h(a1[s].w * r1, hh1.y, ll1.y);
        size_t o1 = ob + 384 + s * 128 + l4;
        *(__half2*)&ctxh[o1]     = hh0;  *(__half2*)&ctxl[o1]     = ll0;
        *(__half2*)&ctxh[o1 + 2] = hh1;  *(__half2*)&ctxl[o1 + 2] = ll1;
    }
    if (lane == 0) inv[m] = allm ? 1 : 0;
}

// ---------------- one temporal attention layer ------------------------------
struct Ptrs {
    __half *bufh, *bufl, *hh, *hl, *QW;
    int* inv;
    __half *wcq, *wf, *w2;
    float *cq, *ckq, *cvec, *wqb, *cqb;
};

static void run_layer(const Ptrs& P, int p, int M,
                      const int* neigh, const float* dense_neigh,
                      const int* eidx, const float* etime,
                      const float* ts, int ts_div,
                      const float* nf, const float* mem, const float* ef,
                      const float* tw, const float* tb,
                      const float* b1, const float* b2,
                      float* outCf, __half* outOh, __half* outOl, int out_ldo)
{
    // QW = src(hi) @ Wcombq^T + ckq  -> fp16 (score path; 1-pass A)
    mma_gemm<<<dim3(6, M/128), 256, GSMEM>>>(
        P.bufh + 768, nullptr, 896,
        P.wcq + (size_t)p*768*128, 128, 128,
        P.ckq + p*768, nullptr, nullptr, 0, P.QW, nullptr, 768, nullptr, 0);
    // fused keyv-build + attention -> ctx into buf cols 0..767
    fused_attn<<<(M + 3) / 4, 128>>>(neigh, eidx, etime, ts, ts_div,
                                     nf, mem, ef, dense_neigh, tw, tb,
                                     P.QW, P.bufh, P.bufl,
                                     P.wqb + p*256, P.cqb + p*2,
                                     P.bufh, P.bufl, P.inv, M);
    // h = relu(buf(hi) @ wf^T + b1 + (valid ? cvec : 0))  (1-pass A, value path)
    mma_gemm<<<dim3(1, M/128), 256, GSMEM>>>(
        P.bufh, nullptr, 896,
        P.wf + (size_t)p*128*896, 896, 896,
        b1 + p*128, P.cvec + p*128, nullptr, 0, P.hh, P.hl, 128, P.inv, GF_RELU);
    // out = h @ W2^T + b2  (2-pass, exact in h)
    mma_gemm<<<dim3(1, M/128), 256, GSMEM>>>(
        P.hh, P.hl, 128,
        P.w2 + (size_t)p*16384, 128, 128,
        b2 + p*128, nullptr, outCf, 128, outOh, outOl, out_ldo, nullptr, 0);
}

// ---------------- entry -----------------------------------------------------
extern "C" void kernel_launch(void* const* d_in, const int* in_sizes, int n_in,
                              void* d_out, int out_size)
{
    const float* node_feat   = (const float*)d_in[0];
    const float* memory      = (const float*)d_in[1];
    const float* edge_feat   = (const float*)d_in[2];
    const float* time_w      = (const float*)d_in[3];
    const float* time_b      = (const float*)d_in[4];
    const float* Wq          = (const float*)d_in[5];
    const float* bq          = (const float*)d_in[6];
    const float* Wk          = (const float*)d_in[7];
    const float* bk          = (const float*)d_in[8];
    const float* Wv          = (const float*)d_in[9];
    const float* bv          = (const float*)d_in[10];
    const float* Wo          = (const float*)d_in[11];
    const float* bo          = (const float*)d_in[12];
    const float* W1          = (const float*)d_in[13];
    const float* b1          = (const float*)d_in[14];
    const float* W2          = (const float*)d_in[15];
    const float* b2          = (const float*)d_in[16];
    const float* timestamps  = (const float*)d_in[17];
    const int*   src_nodes   = (const int*)d_in[18];
    const int*   neighbors1  = (const int*)d_in[19];
    const int*   edge_idx1   = (const int*)d_in[20];
    const float* edge_times1 = (const float*)d_in[21];
    const int*   neighbors2  = (const int*)d_in[22];
    const int*   edge_idx2   = (const int*)d_in[23];
    const float* edge_times2 = (const float*)d_in[24];

    cudaFuncSetAttribute(mma_gemm, cudaFuncAttributeMaxDynamicSharedMemorySize, GSMEM);

    Ptrs P; float *NL1, *tmpvo, *bvo;
    cudaGetSymbolAddress((void**)&P.QW,   g_QW);
    cudaGetSymbolAddress((void**)&P.bufh, g_buf_h);
    cudaGetSymbolAddress((void**)&P.bufl, g_buf_l);
    cudaGetSymbolAddress((void**)&P.hh,   g_h_h);
    cudaGetSymbolAddress((void**)&P.hl,   g_h_l);
    cudaGetSymbolAddress((void**)&NL1,    g_NL1);
    cudaGetSymbolAddress((void**)&P.inv,  g_inv);
    cudaGetSymbolAddress((void**)&P.cq,   g_cq);
    cudaGetSymbolAddress((void**)&P.wcq,  g_wcq);
    cudaGetSymbolAddress((void**)&P.ckq,  g_ckq);
    cudaGetSymbolAddress((void**)&tmpvo,  g_tmpvo);
    cudaGetSymbolAddress((void**)&bvo,    g_bvo);
    cudaGetSymbolAddress((void**)&P.wf,   g_wf);
    cudaGetSymbolAddress((void**)&P.cvec, g_cvec);
    cudaGetSymbolAddress((void**)&P.w2,   g_w2);
    cudaGetSymbolAddress((void**)&P.wqb,  g_wqb);
    cudaGetSymbolAddress((void**)&P.cqb,  g_cqb);

    // launch 1: const_q | comb_vo | stage-1 gather
    prep1_kernel<<<2 + 1536 + M_HOP2/2, 256>>>(
        Wq, bq, time_b, Wo, Wv, bo, bv,
        node_feat, memory, neighbors1,
        P.cq, tmpvo, bvo, P.bufh, P.bufl);
    // launch 2: comb_q | comb_qb | comb_w1 | misc
    prep2_kernel<<<768 + 2 + 768 + 256, 256>>>(
        Wk, Wq, P.cq, bk, W1, W2, tmpvo, bvo,
        P.wcq, P.ckq, P.wqb, P.cqb, P.wf, P.cvec, P.w2);

    // stage 1: layer-1 embedding of flattened first-hop neighbors (p0)
    run_layer(P, 0, M_HOP2, neighbors2, nullptr, edge_idx2, edge_times2,
              timestamps, N_K, node_feat, memory, edge_feat, time_w, time_b,
              b1, b2, NL1, nullptr, nullptr, 0);

    // stage 2: layer-1 embedding of src nodes (p0); SL1 -> buf col 768
    gather_emb_kernel<<<N_B, 128>>>(node_feat, memory, src_nodes, P.bufh, P.bufl, N_B);
    run_layer(P, 0, N_B, neighbors1, nullptr, edge_idx1, edge_times1,
              timestamps, 1, node_feat, memory, edge_feat, time_w, time_b,
              b1, b2, nullptr, P.bufh + 768, P.bufl + 768, 896);

    // stage 3: layer-2 aggregation (p1), neighbor feats = NL1
    run_layer(P, 1, N_B, neighbors1, NL1, edge_idx1, edge_times1,
              timestamps, 1, node_feat, memory, edge_feat, time_w, time_b,
              b1, b2, (float*)d_out, nullptr, nullptr, 0);
}

// round 17
// speedup vs baseline: 1.5848x; 1.0584x over previous
#include <cuda_runtime.h>
#include <cuda_fp16.h>
#include <math.h>
#include <stdint.h>

#define N_B   8192
#define N_K   10
#define N_D   128
#define M_HOP2 (N_B * N_K)          // 81920

// ---------------- scratch (static __device__ globals; no allocs) ------------
__device__ __half g_QW   [(size_t)M_HOP2 * 768];     // fp16: src @ Wcombq^T + ckq
__device__ __half g_buf_h[(size_t)M_HOP2 * 896];     // [ctx(768) || src(128)] hi
__device__ __half g_buf_l[(size_t)M_HOP2 * 896];     // lo (src cols only used)
__device__ __half g_h_h  [(size_t)M_HOP2 * N_D];
__device__ float  g_NL1  [(size_t)M_HOP2 * N_D];
__device__ int    g_inv  [M_HOP2];
__device__ float  g_cq   [2 * 256];
// combined weights
__device__ __half g_wcq [2*768*128];                 // Wk_h^T @ Wq1_h
__device__ float  g_ckq [2*768];                     // Wk_h^T @ cq_h
__device__ float  g_tmpvo[2*256*768];                // Wo @ Wv_blockdiag (fp32 temp)
__device__ float  g_bvo [2*256];                     // Wo bv + bo
__device__ __half g_wf  [2*128*896];                 // [W1a@Wvo || W1b] fp16
__device__ float  g_cvec[2*128];                     // W1a @ bvo
__device__ __half g_w2  [2*128*128];
__device__ float  g_wqb [2*2*128];                   // Wq1_h^T bk_h
__device__ float  g_cqb [2*2];                       // bk_h . cq_h

// ---------------- helpers ---------------------------------------------------
__device__ __forceinline__ void split2h(float v, __half& h, __half& l) {
    h = __float2half_rn(v);
    l = __float2half_rn(v - __half2float(h));
}

// ================= prep 1: const_q | comb_vo | stage-1 gather ================
__global__ __launch_bounds__(256) void prep1_kernel(
    const float* __restrict__ Wq, const float* __restrict__ bq,
    const float* __restrict__ tb,
    const float* __restrict__ Wo, const float* __restrict__ Wv,
    const float* __restrict__ bo, const float* __restrict__ bv,
    const float* __restrict__ nf, const float* __restrict__ mem,
    const int* __restrict__ idx,
    float* __restrict__ cq, float* __restrict__ tmpvo, float* __restrict__ bvo,
    __half* __restrict__ dh, __half* __restrict__ dl)
{
    int blk = blockIdx.x, tid = threadIdx.x;
    if (blk < 2) {                     // const_q
        __shared__ float ct[128];
        int p = blk, j = tid;
        if (j < 128) ct[j] = cosf(tb[j]);
        __syncthreads();
        const float* W = Wq + (size_t)p * 65536;
        float s = bq[p * 256 + j];
        #pragma unroll 4
        for (int t = 0; t < 128; t++) s = fmaf(ct[t], W[(size_t)j * 256 + 128 + t], s);
        cq[p * 256 + j] = s;
        return;
    }
    blk -= 2;
    if (blk < 1536) {                  // comb_vo
        int p = blk / 768, rr = blk % 768;
        int i = rr / 3, jc = rr % 3;
        int j = jc * 256 + tid;
        int h = j / 384, jp = j % 384;
        float acc = 0.f;
        #pragma unroll 4
        for (int d = 0; d < 128; d++)
            acc = fmaf(Wo[((size_t)p*256 + i)*256 + h*128 + d],
                       Wv[((size_t)p*256 + h*128 + d)*384 + jp], acc);
        tmpvo[((size_t)p*256 + i)*768 + j] = acc;
        if (jc == 0 && tid == 0) {
            float c = bo[p*256 + i];
            for (int e = 0; e < 256; e++)
                c = fmaf(Wo[((size_t)p*256 + i)*256 + e], bv[p*256 + e], c);
            bvo[p*256 + i] = c;
        }
        return;
    }
    blk -= 1536;                       // stage-1 gather: 2 rows/block
    int r = blk * 2 + (tid >> 7);
    int t = tid & 127;
    size_t s = (size_t)idx[r] * N_D + t;
    float v = nf[s] + mem[s];
    size_t o = (size_t)r * 896 + 768 + t;
    split2h(v, dh[o], dl[o]);
}

// ================= prep 2: comb_q | comb_qb | comb_w1 | misc =================
__global__ __launch_bounds__(256) void prep2_kernel(
    const float* __restrict__ Wk, const float* __restrict__ Wq,
    const float* __restrict__ cq, const float* __restrict__ bk,
    const float* __restrict__ W1, const float* __restrict__ W2,
    const float* __restrict__ tmpvo, const float* __restrict__ bvo,
    __half* __restrict__ wcq, float* __restrict__ ckq,
    float* __restrict__ wqb, float* __restrict__ cqb,
    __half* __restrict__ wf, float* __restrict__ cvec, __half* __restrict__ w2)
{
    int blk = blockIdx.x, tid = threadIdx.x;
    if (blk < 768) {                   // comb_q: 2 jr rows per block
        __shared__ float wk[2][128];
        int p = blk / 384;
        int half_ = tid >> 7, s = tid & 127;
        int jr = (blk % 384) * 2 + half_;
        int h = jr / 384, j = jr % 384;
        wk[half_][s] = Wk[((size_t)p*256 + h*128 + s)*384 + j];
        __syncthreads();
        float acc = 0.f;
        #pragma unroll 4
        for (int d = 0; d < 128; d++)
            acc = fmaf(wk[half_][d], Wq[((size_t)p*256 + h*128 + d)*256 + s], acc);
        wcq[((size_t)p*768 + jr)*128 + s] = __float2half_rn(acc);
        if (s == 0) {
            float c = 0.f;
            for (int d = 0; d < 128; d++) c = fmaf(wk[half_][d], cq[p*256 + h*128 + d], c);
            ckq[p*768 + jr] = c;
        }
        return;
    }
    blk -= 768;
    if (blk < 2) {                     // comb_qb
        int id = blk * 256 + tid;
        int p = id / 256, h = (id % 256) / 128, s = id % 128;
        float acc = 0.f;
        #pragma unroll 4
        for (int d = 0; d < 128; d++)
            acc = fmaf(Wq[((size_t)p*256 + h*128 + d)*256 + s], bk[p*256 + h*128 + d], acc);
        wqb[(p*2 + h)*128 + s] = acc;
        if (s == 0) {
            float c = 0.f;
            for (int d = 0; d < 128; d++)
                c = fmaf(bk[p*256 + h*128 + d], cq[p*256 + h*128 + d], c);
            cqb[p*2 + h] = c;
        }
        return;
    }
    blk -= 2;
    if (blk < 768) {                   // comb_w1
        __shared__ float w1r[256];
        int p = blk / 384, rr = blk % 384;
        int n = rr / 3, jc = rr % 3;
        w1r[tid] = W1[((size_t)p*128 + n)*384 + tid];
        __syncthreads();
        int j = jc * 256 + tid;
        float acc = 0.f;
        #pragma unroll 4
        for (int e = 0; e < 256; e++)
            acc = fmaf(w1r[e], tmpvo[((size_t)p*256 + e)*768 + j], acc);
        wf[((size_t)p*128 + n)*896 + j] = __float2half_rn(acc);
        if (jc == 0 && tid == 0) {
            float c = 0.f;
            for (int e = 0; e < 256; e++) c = fmaf(w1r[e], bvo[p*256 + e], c);
            cvec[p*128 + n] = c;
        }
        return;
    }
    blk -= 768;
    {                                  // misc
        int i = blk * 256 + tid;
        if (i < 32768) {
            int p = i >> 14, r = i & 16383;
            int n = r >> 7, d = r & 127;
            wf[((size_t)p*128 + n)*896 + 768 + d] =
                __float2half_rn(W1[((size_t)p*128 + n)*384 + 256 + d]);
        } else {
            i -= 32768;
            w2[i] = __float2half_rn(W2[i]);
        }
    }
}

// gather emb0 into buf at col 768 (stage 2)
__global__ void gather_emb_kernel(const float* __restrict__ nf,
                                  const float* __restrict__ mem,
                                  const int* __restrict__ idx,
                                  __half* __restrict__ dh, __half* __restrict__ dl, int n)
{
    int r = blockIdx.x;
    if (r >= n) return;
    int t = threadIdx.x;
    size_t s = (size_t)idx[r] * N_D + t;
    float v = nf[s] + mem[s];
    size_t o = (size_t)r * 896 + 768 + t;
    split2h(v, dh[o], dl[o]);
}

// ---------------- fp16 tensor-core GEMM (2-pass, or 1-pass if Al==null) -----
#define GF_RELU 1
#define SMS  40
#define MATB (128 * SMS * 2)
#define STGB (3 * MATB)
#define NSTG 3
#define GSMEM (NSTG * STGB)

__device__ __forceinline__ void cpa16(uint32_t s, const void* g) {
    asm volatile("cp.async.cg.shared.global [%0], [%1], 16;\n" :: "r"(s), "l"(g));
}
__device__ __forceinline__ void ldm4(uint32_t* r, uint32_t a) {
    asm volatile("ldmatrix.sync.aligned.m8n8.x4.shared.b16 {%0,%1,%2,%3},[%4];\n"
                 : "=r"(r[0]), "=r"(r[1]), "=r"(r[2]), "=r"(r[3]) : "r"(a));
}
__device__ __forceinline__ void mmaf16(float* d, const uint32_t* a, uint32_t b0, uint32_t b1) {
    asm volatile("mma.sync.aligned.m16n8k16.row.col.f32.f16.f16.f32 "
                 "{%0,%1,%2,%3},{%4,%5,%6,%7},{%8,%9},{%0,%1,%2,%3};\n"
                 : "+f"(d[0]), "+f"(d[1]), "+f"(d[2]), "+f"(d[3])
                 : "r"(a[0]), "r"(a[1]), "r"(a[2]), "r"(a[3]), "r"(b0), "r"(b1));
}

__device__ __forceinline__ void issue_chunk(uint32_t sw, uint32_t bufofs,
    const __half* Ah, const __half* Al, size_t ga,
    const __half* Wh, size_t gw)
{
    uint32_t s0 = sw + bufofs;
    cpa16(s0,          Ah + ga); cpa16(s0 + 32,          Ah + ga + 16);
    if (Al) { cpa16(s0 + MATB, Al + ga); cpa16(s0 + MATB + 32, Al + ga + 16); }
    cpa16(s0 + 2*MATB, Wh + gw); cpa16(s0 + 2*MATB + 32, Wh + gw + 16);
    asm volatile("cp.async.commit_group;\n");
}

// epilogue: Oh && Ol -> hi/lo split; Oh only -> plain fp16; Cf -> fp32
__global__ __launch_bounds__(256, 2) void mma_gemm(
    const __half* __restrict__ Ah, const __half* __restrict__ Al, int lda,
    const __half* __restrict__ Wh, int ldw,
    int Kd,
    const float* __restrict__ bias, const float* __restrict__ bias2,
    float* __restrict__ Cf, int ldcf,
    __half* __restrict__ Oh, __half* __restrict__ Ol, int ldo,
    const int* __restrict__ zmask, int flags)
{
    extern __shared__ __align__(16) char smem_raw[];
    uint32_t sb = (uint32_t)__cvta_generic_to_shared(smem_raw);
    int tid = threadIdx.x;
    int m0 = blockIdx.y * 128, n0 = blockIdx.x * 128;
    int lane = tid & 31, wid = tid >> 5;
    int wm = wid & 1, wn = wid >> 1;

    float d[4][4][4];
    #pragma unroll
    for (int i = 0; i < 4; i++)
        #pragma unroll
        for (int j = 0; j < 4; j++)
            #pragma unroll
            for (int r = 0; r < 4; r++) d[i][j][r] = 0.f;

    int row = tid >> 1;
    int ce  = (tid & 1) << 3;
    size_t ga0 = (size_t)(m0 + row) * lda + ce;
    size_t gw0 = (size_t)(n0 + row) * ldw + ce;
    uint32_t sw = sb + (uint32_t)(row * SMS + ce) * 2;

    int nch = Kd >> 5;
    issue_chunk(sw, 0, Ah, Al, ga0, Wh, gw0);
    if (nch > 1) issue_chunk(sw, STGB, Ah, Al, ga0 + 32, Wh, gw0 + 32);

    for (int c = 0; c < nch; c++) {
        if (c + 2 < nch) {
            int k0 = (c + 2) << 5;
            issue_chunk(sw, (uint32_t)((c + 2) % NSTG) * STGB, Ah, Al, ga0 + k0, Wh, gw0 + k0);
        }
        int issuedJ = (c + 2 < nch) ? c + 2 : nch - 1;
        int allow = issuedJ - c;
        if (allow >= 2)      asm volatile("cp.async.wait_group 2;\n" ::: "memory");
        else if (allow == 1) asm volatile("cp.async.wait_group 1;\n" ::: "memory");
        else                 asm volatile("cp.async.wait_group 0;\n" ::: "memory");
        __syncthreads();

        uint32_t base = sb + (uint32_t)(c % NSTG) * STGB;
        #pragma unroll
        for (int h = 0; h < 2; h++) {
            uint32_t ah[4][4], bh[2][4];
            int colA = (h << 4) + ((lane >> 4) << 3);
            #pragma unroll
            for (int mi = 0; mi < 4; mi++) {
                int r_ = wm * 64 + mi * 16 + (lane & 15);
                ldm4(ah[mi], base + (uint32_t)(r_ * SMS + colA) * 2);
            }
            #pragma unroll
            for (int nj2 = 0; nj2 < 2; nj2++) {
                int r_ = wn * 32 + nj2 * 16 + (lane & 7) + (((lane >> 3) & 1) << 3);
                ldm4(bh[nj2], base + 2 * MATB + (uint32_t)(r_ * SMS + colA) * 2);
            }
            #pragma unroll
            for (int mi = 0; mi < 4; mi++)
                #pragma unroll
                for (int nj = 0; nj < 4; nj++)
                    mmaf16(d[mi][nj], ah[mi], bh[nj >> 1][nj & 1], bh[nj >> 1][(nj & 1) + 2]);
            if (Al) {
                uint32_t al[4][4];
                #pragma unroll
                for (int mi = 0; mi < 4; mi++) {
                    int r_ = wm * 64 + mi * 16 + (lane & 15);
                    ldm4(al[mi], base + MATB + (uint32_t)(r_ * SMS + colA) * 2);
                }
                #pragma unroll
                for (int mi = 0; mi < 4; mi++)
                    #pragma unroll
                    for (int nj = 0; nj < 4; nj++)
                        mmaf16(d[mi][nj], al[mi], bh[nj >> 1][nj & 1], bh[nj >> 1][(nj & 1) + 2]);
            }
        }
        __syncthreads();
    }

    int gr = lane >> 2, tg = lane & 3;
    #pragma unroll
    for (int mi = 0; mi < 4; mi++) {
        int mb = m0 + wm * 64 + mi * 16 + gr;
        #pragma unroll
        for (int half = 0; half < 2; half++) {
            int m = mb + half * 8;
            bool zm = (zmask != nullptr) && (zmask[m] != 0);
            #pragma unroll
            for (int nj = 0; nj < 4; nj++) {
                int n = n0 + wn * 32 + nj * 8 + tg * 2;
                float v0 = d[mi][nj][half * 2 + 0];
                float v1 = d[mi][nj][half * 2 + 1];
                if (bias) { v0 += bias[n]; v1 += bias[n + 1]; }
                if (bias2) {
                    if (!zm) { v0 += bias2[n]; v1 += bias2[n + 1]; }
                } else if (zm) { v0 = 0.f; v1 = 0.f; }
                if (flags & GF_RELU) { v0 = fmaxf(v0, 0.f); v1 = fmaxf(v1, 0.f); }
                if (Cf) *(float2*)&Cf[(size_t)m * ldcf + n] = make_float2(v0, v1);
                if (Oh) {
                    if (Ol) {
                        __half2 hh, ll;
                        split2h(v0, hh.x, ll.x);
                        split2h(v1, hh.y, ll.y);
                        *(__half2*)&Oh[(size_t)m * ldo + n] = hh;
                        *(__half2*)&Ol[(size_t)m * ldo + n] = ll;
                    } else {
                        *(__half2*)&Oh[(size_t)m * ldo + n] =
                            __floats2half2_rn(v0, v1);
                    }
                }
            }
        }
    }
}

// ------- fused keyv-build + attention: online softmax, fp16-hi ctx only -----
__global__ __launch_bounds__(128, 4) void fused_attn(
    const int* __restrict__ neigh,
    const int* __restrict__ eidx,
    const float* __restrict__ etime,
    const float* __restrict__ ts, int ts_div,
    const float* __restrict__ nf, const float* __restrict__ mem,
    const float* __restrict__ ef,
    const float* __restrict__ dense_neigh,
    const float* __restrict__ tw, const float* __restrict__ tb,
    const __half* __restrict__ QW,
    const __half* __restrict__ bufh, const __half* __restrict__ bufl,
    const float* __restrict__ wqb, const float* __restrict__ cqb,
    __half* __restrict__ ctxh,
    int* __restrict__ inv, int M)
{
    __shared__ float s_tw[128], s_tb[128];
    int tid = threadIdx.x;
    s_tw[tid] = tw[tid];
    s_tb[tid] = tb[tid];
    __syncthreads();

    int wl = tid >> 5, lane = tid & 31;
    int m = blockIdx.x * 4 + wl;
    if (m >= M) return;
    const float SC = 0.08838834764831843f;   // 1/sqrt(128)
    int l4 = lane * 4;

    // qb_h = src . wqb_h + cqb_h
    float qb0, qb1;
    {
        size_t sbse = (size_t)m * 896 + 768 + l4;
        float2 fh0 = __half22float2(*(const __half2*)&bufh[sbse]);
        float2 fh1 = __half22float2(*(const __half2*)&bufh[sbse + 2]);
        float2 fl0 = __half22float2(*(const __half2*)&bufl[sbse]);
        float2 fl1 = __half22float2(*(const __half2*)&bufl[sbse + 2]);
        float sx = fh0.x + fl0.x, sy = fh0.y + fl0.y;
        float sz = fh1.x + fl1.x, sw_ = fh1.y + fl1.y;
        float4 w0 = *(const float4*)&wqb[l4];
        float4 w1 = *(const float4*)&wqb[128 + l4];
        qb0 = sx*w0.x + sy*w0.y + sz*w0.z + sw_*w0.w;
        qb1 = sx*w1.x + sy*w1.y + sz*w1.z + sw_*w1.w;
        #pragma unroll
        for (int o = 16; o; o >>= 1) {
            qb0 += __shfl_xor_sync(0xffffffffu, qb0, o);
            qb1 += __shfl_xor_sync(0xffffffffu, qb1, o);
        }
        qb0 += cqb[0]; qb1 += cqb[1];
    }

    float4 qw0[3], qw1[3];
    {
        const __half* qwp = QW + (size_t)m * 768;
        #pragma unroll
        for (int s = 0; s < 3; s++) {
            float2 c0 = __half22float2(*(const __half2*)&qwp[s * 128 + l4]);
            float2 c1 = __half22float2(*(const __half2*)&qwp[s * 128 + l4 + 2]);
            qw0[s] = make_float4(c0.x, c0.y, c1.x, c1.y);
            c0 = __half22float2(*(const __half2*)&qwp[384 + s * 128 + l4]);
            c1 = __half22float2(*(const __half2*)&qwp[384 + s * 128 + l4 + 2]);
            qw1[s] = make_float4(c0.x, c0.y, c1.x, c1.y);
        }
    }

    float tsv = ts[m / ts_div];
    bool allm = true;
    #pragma unroll
    for (int k = 0; k < N_K; k++) allm = allm && (neigh[m * N_K + k] == 0);

    // ---- single pass: online softmax + ctx accumulation
    float mx0 = -3.0e38f, mx1 = -3.0e38f, sm0 = 0.f, sm1 = 0.f;
    float4 a0[3], a1[3];
    #pragma unroll
    for (int s = 0; s < 3; s++) {
        a0[s] = make_float4(0.f, 0.f, 0.f, 0.f);
        a1[s] = make_float4(0.f, 0.f, 0.f, 0.f);
    }

    #pragma unroll
    for (int k = 0; k < N_K; k++) {
        int ndk = neigh[m * N_K + k];
        int edk = eidx [m * N_K + k];
        float4 vn, ve, vc;
        if (dense_neigh) {
            vn = *(const float4*)&dense_neigh[(size_t)(m * N_K + k) * N_D + l4];
        } else {
            float4 a = *(const float4*)&nf [(size_t)ndk * N_D + l4];
            float4 b = *(const float4*)&mem[(size_t)ndk * N_D + l4];
            vn = make_float4(a.x + b.x, a.y + b.y, a.z + b.z, a.w + b.w);
        }
        ve = *(const float4*)&ef[(size_t)edk * N_D + l4];
        float dd = tsv - etime[m * N_K + k];
        vc.x = cosf(__fadd_rn(__fmul_rn(dd, s_tw[l4 + 0]), s_tb[l4 + 0]));
        vc.y = cosf(__fadd_rn(__fmul_rn(dd, s_tw[l4 + 1]), s_tb[l4 + 1]));
        vc.z = cosf(__fadd_rn(__fmul_rn(dd, s_tw[l4 + 2]), s_tb[l4 + 2]));
        vc.w = cosf(__fadd_rn(__fmul_rn(dd, s_tw[l4 + 3]), s_tb[l4 + 3]));

        float p0 = qw0[0].x*vn.x + qw0[0].y*vn.y + qw0[0].z*vn.z + qw0[0].w*vn.w
                 + qw0[1].x*ve.x + qw0[1].y*ve.y + qw0[1].z*ve.z + qw0[1].w*ve.w
                 + qw0[2].x*vc.x + qw0[2].y*vc.y + qw0[2].z*vc.z + qw0[2].w*vc.w;
        float p1 = qw1[0].x*vn.x + qw1[0].y*vn.y + qw1[0].z*vn.z + qw1[0].w*vn.w
                 + qw1[1].x*ve.x + qw1[1].y*ve.y + qw1[1].z*ve.z + qw1[1].w*ve.w
                 + qw1[2].x*vc.x + qw1[2].y*vc.y + qw1[2].z*vc.z + qw1[2].w*vc.w;
        #pragma unroll
        for (int o = 16; o; o >>= 1) {
            p0 += __shfl_xor_sync(0xffffffffu, p0, o);
            p1 += __shfl_xor_sync(0xffffffffu, p1, o);
        }
        bool mk = (ndk == 0) && !(allm && k == 0);
        float sc0 = mk ? -1e9f : (p0 + qb0) * SC;
        float sc1 = mk ? -1e9f : (p1 + qb1) * SC;

        float nm0 = fmaxf(mx0, sc0);
        float rs0 = __expf(mx0 - nm0);
        float e0  = __expf(sc0 - nm0);
        sm0 = sm0 * rs0 + e0;
        mx0 = nm0;
        float nm1 = fmaxf(mx1, sc1);
        float rs1 = __expf(mx1 - nm1);
        float e1  = __expf(sc1 - nm1);
        sm1 = sm1 * rs1 + e1;
        mx1 = nm1;
        a0[0].x = fmaf(e0, vn.x, a0[0].x * rs0); a0[0].y = fmaf(e0, vn.y, a0[0].y * rs0);
        a0[0].z = fmaf(e0, vn.z, a0[0].z * rs0); a0[0].w = fmaf(e0, vn.w, a0[0].w * rs0);
        a0[1].x = fmaf(e0, ve.x, a0[1].x * rs0); a0[1].y = fmaf(e0, ve.y, a0[1].y * rs0);
        a0[1].z = fmaf(e0, ve.z, a0[1].z * rs0); a0[1].w = fmaf(e0, ve.w, a0[1].w * rs0);
        a0[2].x = fmaf(e0, vc.x, a0[2].x * rs0); a0[2].y = fmaf(e0, vc.y, a0[2].y * rs0);
        a0[2].z = fmaf(e0, vc.z, a0[2].z * rs0); a0[2].w = fmaf(e0, vc.w, a0[2].w * rs0);
        a1[0].x = fmaf(e1, vn.x, a1[0].x * rs1); a1[0].y = fmaf(e1, vn.y, a1[0].y * rs1);
        a1[0].z = fmaf(e1, vn.z, a1[0].z * rs1); a1[0].w = fmaf(e1, vn.w, a1[0].w * rs1);
        a1[1].x = fmaf(e1, ve.x, a1[1].x * rs1); a1[1].y = fmaf(e1, ve.y, a1[1].y * rs1);
        a1[1].z = fmaf(e1, ve.z, a1[1].z * rs1); a1[1].w = fmaf(e1, ve.w, a1[1].w * rs1);
        a1[2].x = fmaf(e1, vc.x, a1[2].x * rs1); a1[2].y = fmaf(e1, vc.y, a1[2].y * rs1);
        a1[2].z = fmaf(e1, vc.z, a1[2].z * rs1); a1[2].w = fmaf(e1, vc.w, a1[2].w * rs1);
    }

    float zf = allm ? 0.f : 1.f;       // fold invalid-row zeroing into ctx
    float r0 = zf / sm0, r1 = zf / sm1;

    size_t ob = (size_t)m * 896;
    #pragma unroll
    for (int s = 0; s < 3; s++) {
        size_t o0 = ob + s * 128 + l4;
        *(__half2*)&ctxh[o0]     = __floats2half2_rn(a0[s].x * r0, a0[s].y * r0);
        *(__half2*)&ctxh[o0 + 2] = __floats2half2_rn(a0[s].z * r0, a0[s].w * r0);
        size_t o1 = ob + 384 + s * 128 + l4;
        *(__half2*)&ctxh[o1]     = __floats2half2_rn(a1[s].x * r1, a1[s].y * r1);
        *(__half2*)&ctxh[o1 + 2] = __floats2half2_rn(a1[s].z * r1, a1[s].w * r1);
    }
    if (lane == 0) inv[m] = allm ? 1 : 0;
}

// ---------------- one temporal attention layer ------------------------------
struct Ptrs {
    __half *bufh, *bufl, *hh, *QW;
    int* inv;
    __half *wcq, *wf, *w2;
    float *cq, *ckq, *cvec, *wqb, *cqb;
};

static void run_layer(const Ptrs& P, int p, int M,
                      const int* neigh, const float* dense_neigh,
                      const int* eidx, const float* etime,
                      const float* ts, int ts_div,
                      const float* nf, const float* mem, const float* ef,
                      const float* tw, const float* tb,
                      const float* b1, const float* b2,
                      float* outCf, __half* outOh, __half* outOl, int out_ldo)
{
    // QW = src(hi) @ Wcombq^T + ckq  -> fp16 (score path; 1-pass A)
    mma_gemm<<<dim3(6, M/128), 256, GSMEM>>>(
        P.bufh + 768, nullptr, 896,
        P.wcq + (size_t)p*768*128, 128, 128,
        P.ckq + p*768, nullptr, nullptr, 0, P.QW, nullptr, 768, nullptr, 0);
    // fused keyv-build + attention -> ctx (fp16 hi only) into buf cols 0..767
    fused_attn<<<(M + 3) / 4, 128>>>(neigh, eidx, etime, ts, ts_div,
                                     nf, mem, ef, dense_neigh, tw, tb,
                                     P.QW, P.bufh, P.bufl,
                                     P.wqb + p*256, P.cqb + p*2,
                                     P.bufh, P.inv, M);
    // h = relu(buf(hi) @ wf^T + b1 + (valid ? cvec : 0))  (1-pass, fp16 out)
    mma_gemm<<<dim3(1, M/128), 256, GSMEM>>>(
        P.bufh, nullptr, 896,
        P.wf + (size_t)p*128*896, 896, 896,
        b1 + p*128, P.cvec + p*128, nullptr, 0, P.hh, nullptr, 128, P.inv, GF_RELU);
    // out = h @ W2^T + b2  (1-pass)
    mma_gemm<<<dim3(1, M/128), 256, GSMEM>>>(
        P.hh, nullptr, 128,
        P.w2 + (size_t)p*16384, 128, 128,
        b2 + p*128, nullptr, outCf, 128, outOh, outOl, out_ldo, nullptr, 0);
}

// ---------------- entry -----------------------------------------------------
extern "C" void kernel_launch(void* const* d_in, const int* in_sizes, int n_in,
                              void* d_out, int out_size)
{
    const float* node_feat   = (const float*)d_in[0];
    const float* memory      = (const float*)d_in[1];
    const float* edge_feat   = (const float*)d_in[2];
    const float* time_w      = (const float*)d_in[3];
    const float* time_b      = (const float*)d_in[4];
    const float* Wq          = (const float*)d_in[5];
    const float* bq          = (const float*)d_in[6];
    const float* Wk          = (const float*)d_in[7];
    const float* bk          = (const float*)d_in[8];
    const float* Wv          = (const float*)d_in[9];
    const float* bv          = (const float*)d_in[10];
    const float* Wo          = (const float*)d_in[11];
    const float* bo          = (const float*)d_in[12];
    const float* W1          = (const float*)d_in[13];
    const float* b1          = (const float*)d_in[14];
    const float* W2          = (const float*)d_in[15];
    const float* b2          = (const float*)d_in[16];
    const float* timestamps  = (const float*)d_in[17];
    const int*   src_nodes   = (const int*)d_in[18];
    const int*   neighbors1  = (const int*)d_in[19];
    const int*   edge_idx1   = (const int*)d_in[20];
    const float* edge_times1 = (const float*)d_in[21];
    const int*   neighbors2  = (const int*)d_in[22];
    const int*   edge_idx2   = (const int*)d_in[23];
    const float* edge_times2 = (const float*)d_in[24];

    cudaFuncSetAttribute(mma_gemm, cudaFuncAttributeMaxDynamicSharedMemorySize, GSMEM);

    Ptrs P; float *NL1, *tmpvo, *bvo;
    cudaGetSymbolAddress((void**)&P.QW,   g_QW);
    cudaGetSymbolAddress((void**)&P.bufh, g_buf_h);
    cudaGetSymbolAddress((void**)&P.bufl, g_buf_l);
    cudaGetSymbolAddress((void**)&P.hh,   g_h_h);
    cudaGetSymbolAddress((void**)&NL1,    g_NL1);
    cudaGetSymbolAddress((void**)&P.inv,  g_inv);
    cudaGetSymbolAddress((void**)&P.cq,   g_cq);
    cudaGetSymbolAddress((void**)&P.wcq,  g_wcq);
    cudaGetSymbolAddress((void**)&P.ckq,  g_ckq);
    cudaGetSymbolAddress((void**)&tmpvo,  g_tmpvo);
    cudaGetSymbolAddress((void**)&bvo,    g_bvo);
    cudaGetSymbolAddress((void**)&P.wf,   g_wf);
    cudaGetSymbolAddress((void**)&P.cvec, g_cvec);
    cudaGetSymbolAddress((void**)&P.w2,   g_w2);
    cudaGetSymbolAddress((void**)&P.wqb,  g_wqb);
    cudaGetSymbolAddress((void**)&P.cqb,  g_cqb);

    // launch 1: const_q | comb_vo | stage-1 gather
    prep1_kernel<<<2 + 1536 + M_HOP2/2, 256>>>(
        Wq, bq, time_b, Wo, Wv, bo, bv,
        node_feat, memory, neighbors1,
        P.cq, tmpvo, bvo, P.bufh, P.bufl);
    // launch 2: comb_q | comb_qb | comb_w1 | misc
    prep2_kernel<<<768 + 2 + 768 + 256, 256>>>(
        Wk, Wq, P.cq, bk, W1, W2, tmpvo, bvo,
        P.wcq, P.ckq, P.wqb, P.cqb, P.wf, P.cvec, P.w2);

    // stage 1: layer-1 embedding of flattened first-hop neighbors (p0)
    run_layer(P, 0, M_HOP2, neighbors2, nullptr, edge_idx2, edge_times2,
              timestamps, N_K, node_feat, memory, edge_feat, time_w, time_b,
              b1, b2, NL1, nullptr, nullptr, 0);

    // stage 2: layer-1 embedding of src nodes (p0); SL1 -> buf col 768 (hi/lo)
    gather_emb_kernel<<<N_B, 128>>>(node_feat, memory, src_nodes, P.bufh, P.bufl, N_B);
    run_layer(P, 0, N_B, neighbors1, nullptr, edge_idx1, edge_times1,
              timestamps, 1, node_feat, memory, edge_feat, time_w, time_b,
              b1, b2, nullptr, P.bufh + 768, P.bufl + 768, 896);

    // stage 3: layer-2 aggregation (p1), neighbor feats = NL1
    run_layer(P, 1, N_B, neighbors1, NL1, edge_idx1, edge_times1,
              timestamps, 1, node_feat, memory, edge_feat, time_w, time_b,
              b1, b2, (float*)d_out, nullptr, nullptr, 0);
}